// round 7
// baseline (speedup 1.0000x reference)
#include <cuda_runtime.h>
#include <cstdint>
#include <math.h>

#define B_  8
#define S_  1024
#define D_  768
#define H_  12
#define DH_ 64
#define FF_ 3072
#define E_  8
#define CAP_ 2048
#define T_  8192

// ---------------- scratch (device globals) ----------------------------------
__device__ float g_q[B_*H_*S_*DH_];
__device__ float g_k[B_*H_*S_*DH_];
__device__ float g_v[B_*H_*S_*DH_];
__device__ float g_ctx[T_*D_];
__device__ float g_tmp[T_*D_];
__device__ float g_att[T_*D_];
__device__ float g_h[50331648];            // E*CAP*FF
__device__ float g_ffn[T_*D_];
__device__ int   g_cnt[E_];
__device__ int   g_tokmap[E_*CAP_];
__device__ float g_gate[T_];

__device__ __forceinline__ float gelu_f(float x) {
    return 0.5f * x * (1.0f + erff(x * 0.70710678118654752f));
}

__device__ __forceinline__ void cpa16(uint32_t dst, const void* src) {
    asm volatile("cp.async.ca.shared.global [%0], [%1], 16;" :: "r"(dst), "l"(src));
}
__device__ __forceinline__ void cpa_commit() {
    asm volatile("cp.async.commit_group;" ::: "memory");
}
__device__ __forceinline__ void cpa_wait0() {
    asm volatile("cp.async.wait_group 0;" ::: "memory");
}
__device__ __forceinline__ void mma8(float* c, const uint32_t* a, const uint32_t* b) {
    asm volatile(
        "mma.sync.aligned.m16n8k8.row.col.f32.tf32.tf32.f32 "
        "{%0,%1,%2,%3}, {%4,%5,%6,%7}, {%8,%9}, {%0,%1,%2,%3};\n"
        : "+f"(c[0]), "+f"(c[1]), "+f"(c[2]), "+f"(c[3])
        : "r"(a[0]), "r"(a[1]), "r"(a[2]), "r"(a[3]), "r"(b[0]), "r"(b[1]));
}

// ================= fused flash attention =====================================
__global__ __launch_bounds__(256) void fattn(const float* __restrict__ mask)
{
    constexpr int LDK = 68, LDV = 72, LDP = 68;
    constexpr int KBYTES = 64 * LDK * 4;
    constexpr int VBYTES = 64 * LDV * 4;
    constexpr int MBYTES = 256;
    constexpr int STAGE  = KBYTES + VBYTES + MBYTES;
    extern __shared__ char smc[];
    float* pS_all = (float*)(smc + 2 * STAGE);

    const int tid = threadIdx.x, wid = tid >> 5, lane = tid & 31;
    const int g = lane >> 2, t = lane & 3;
    const int z = blockIdx.y, mBase = blockIdx.x * 128;
    const int bq = z / H_, hh = z % H_;
    const int m0 = mBase + wid * 16;

    const float* Qp = g_q + (size_t)z * S_ * DH_;
    const float* Kp = g_k + (size_t)z * S_ * DH_;
    const float* Vp = g_v + (size_t)z * S_ * DH_;

    uint32_t qf[8][4];
    #pragma unroll
    for (int kb = 0; kb < 8; kb++) {
        qf[kb][0] = __float_as_uint(Qp[(m0 + g)     * DH_ + kb*8 + t]);
        qf[kb][1] = __float_as_uint(Qp[(m0 + g + 8) * DH_ + kb*8 + t]);
        qf[kb][2] = __float_as_uint(Qp[(m0 + g)     * DH_ + kb*8 + t + 4]);
        qf[kb][3] = __float_as_uint(Qp[(m0 + g + 8) * DH_ + kb*8 + t + 4]);
    }

    float oacc[8][4];
    #pragma unroll
    for (int nt = 0; nt < 8; nt++)
        #pragma unroll
        for (int q = 0; q < 4; q++) oacc[nt][q] = 0.f;
    float mrow0 = -1e30f, mrow1 = -1e30f, lrow0 = 0.f, lrow1 = 0.f;

    uint32_t sU = (uint32_t)__cvta_generic_to_shared(smc);
    auto issue = [&](int kt) {
        const int stg = kt & 1;
        const uint32_t base = sU + stg * STAGE;
        #pragma unroll
        for (int i = 0; i < 4; i++) {
            int idx = tid + i * 256;
            int row = idx >> 4, c4 = idx & 15;
            cpa16(base + row * (LDK*4) + c4 * 16,
                  Kp + (size_t)(kt*64 + row) * DH_ + c4 * 4);
        }
        #pragma unroll
        for (int i = 0; i < 4; i++) {
            int idx = tid + i * 256;
            int row = idx >> 4, c4 = idx & 15;
            cpa16(base + KBYTES + row * (LDV*4) + c4 * 16,
                  Vp + (size_t)(kt*64 + row) * DH_ + c4 * 4);
        }
        if (tid < 16)
            cpa16(base + KBYTES + VBYTES + tid * 16, mask + bq * S_ + kt*64 + tid * 4);
        cpa_commit();
    };

    float* pS = pS_all + wid * 16 * LDP;

    issue(0);
    for (int kt = 0; kt < 16; kt++) {
        cpa_wait0();
        __syncthreads();
        if (kt + 1 < 16) issue(kt + 1);

        const int stg = kt & 1;
        const float* kS = (const float*)(smc + stg * STAGE);
        const float* vS = (const float*)(smc + stg * STAGE + KBYTES);
        const float* mS = (const float*)(smc + stg * STAGE + KBYTES + VBYTES);

        float sacc[8][4];
        #pragma unroll
        for (int nt = 0; nt < 8; nt++)
            #pragma unroll
            for (int q = 0; q < 4; q++) sacc[nt][q] = 0.f;
        #pragma unroll
        for (int ks = 0; ks < 8; ks++) {
            #pragma unroll
            for (int nt = 0; nt < 8; nt++) {
                uint32_t b[2];
                b[0] = __float_as_uint(kS[(nt*8 + g) * LDK + ks*8 + t]);
                b[1] = __float_as_uint(kS[(nt*8 + g) * LDK + ks*8 + t + 4]);
                mma8(sacc[nt], qf[ks], b);
            }
        }

        float mx0 = -1e30f, mx1 = -1e30f;
        #pragma unroll
        for (int nt = 0; nt < 8; nt++) {
            float mk0 = mS[nt*8 + 2*t], mk1 = mS[nt*8 + 2*t + 1];
            sacc[nt][0] = sacc[nt][0]*0.125f + mk0;
            sacc[nt][1] = sacc[nt][1]*0.125f + mk1;
            sacc[nt][2] = sacc[nt][2]*0.125f + mk0;
            sacc[nt][3] = sacc[nt][3]*0.125f + mk1;
            mx0 = fmaxf(mx0, fmaxf(sacc[nt][0], sacc[nt][1]));
            mx1 = fmaxf(mx1, fmaxf(sacc[nt][2], sacc[nt][3]));
        }
        mx0 = fmaxf(mx0, __shfl_xor_sync(0xffffffffu, mx0, 1));
        mx0 = fmaxf(mx0, __shfl_xor_sync(0xffffffffu, mx0, 2));
        mx1 = fmaxf(mx1, __shfl_xor_sync(0xffffffffu, mx1, 1));
        mx1 = fmaxf(mx1, __shfl_xor_sync(0xffffffffu, mx1, 2));

        float mn0 = fmaxf(mrow0, mx0), mn1 = fmaxf(mrow1, mx1);
        float a0 = __expf(mrow0 - mn0), a1 = __expf(mrow1 - mn1);
        mrow0 = mn0; mrow1 = mn1;

        float s0 = 0.f, s1 = 0.f;
        #pragma unroll
        for (int nt = 0; nt < 8; nt++) {
            float p0 = __expf(sacc[nt][0] - mn0);
            float p1 = __expf(sacc[nt][1] - mn0);
            float p2 = __expf(sacc[nt][2] - mn1);
            float p3 = __expf(sacc[nt][3] - mn1);
            s0 += p0 + p1; s1 += p2 + p3;
            *(float2*)(pS + g * LDP + nt*8 + 2*t)       = make_float2(p0, p1);
            *(float2*)(pS + (g + 8) * LDP + nt*8 + 2*t) = make_float2(p2, p3);
        }
        s0 += __shfl_xor_sync(0xffffffffu, s0, 1);
        s0 += __shfl_xor_sync(0xffffffffu, s0, 2);
        s1 += __shfl_xor_sync(0xffffffffu, s1, 1);
        s1 += __shfl_xor_sync(0xffffffffu, s1, 2);
        lrow0 = lrow0 * a0 + s0;
        lrow1 = lrow1 * a1 + s1;

        #pragma unroll
        for (int nt = 0; nt < 8; nt++) {
            oacc[nt][0] *= a0; oacc[nt][1] *= a0;
            oacc[nt][2] *= a1; oacc[nt][3] *= a1;
        }
        __syncwarp();

        #pragma unroll
        for (int kb = 0; kb < 8; kb++) {
            uint32_t a[4];
            a[0] = __float_as_uint(pS[g * LDP + kb*8 + t]);
            a[1] = __float_as_uint(pS[(g + 8) * LDP + kb*8 + t]);
            a[2] = __float_as_uint(pS[g * LDP + kb*8 + t + 4]);
            a[3] = __float_as_uint(pS[(g + 8) * LDP + kb*8 + t + 4]);
            #pragma unroll
            for (int nt = 0; nt < 8; nt++) {
                uint32_t b[2];
                b[0] = __float_as_uint(vS[(kb*8 + t)     * LDV + nt*8 + g]);
                b[1] = __float_as_uint(vS[(kb*8 + t + 4) * LDV + nt*8 + g]);
                mma8(oacc[nt], a, b);
            }
        }
    }

    float inv0 = 1.0f / lrow0, inv1 = 1.0f / lrow1;
    int mr0 = m0 + g, mr1 = m0 + g + 8;
    #pragma unroll
    for (int nt = 0; nt < 8; nt++) {
        int col = hh * DH_ + nt*8 + 2*t;
        *(float2*)(g_ctx + ((size_t)(bq * S_ + mr0)) * D_ + col) =
            make_float2(oacc[nt][0] * inv0, oacc[nt][1] * inv0);
        *(float2*)(g_ctx + ((size_t)(bq * S_ + mr1)) * D_ + col) =
            make_float2(oacc[nt][2] * inv1, oacc[nt][3] * inv1);
    }
}

// ---------------- tf32 mma.sync GEMM: 128x64 tile, 128 threads, 4 CTAs/SM ----
// A[M][KK] k-major (opt. gathered). B[k][n] n-major, row stride LDBG.
// MODE 0: QKV proj (z selects W/b), headed scatter
// MODE 3: ctx @ Wo -> g_tmp
// MODE 4: gather(att) @ W1[e] + b1 -> gelu -> g_h
// MODE 5: g_h @ W2[e] + b2, * gate, scatter -> g_ffn
template<int MODE, int KK, int LDBG>
__global__ __launch_bounds__(128, 4)
void tgemm(const float* __restrict__ Ag, const float* __restrict__ Bg,
           const float* __restrict__ Bg2, const float* __restrict__ Bg3,
           const float* __restrict__ bias, const float* __restrict__ bias2,
           const float* __restrict__ bias3)
{
    constexpr int BN     = 64;
    constexpr int NC     = KK / 32;
    constexpr int NT     = 4;                  // warp tile 64 x 32
    constexpr int LDA    = 36;
    constexpr int LDBN   = BN + 8;             // 72
    constexpr int ABYTES = 128 * LDA * 4;      // 18432
    constexpr int BBYTES = 32 * LDBN * 4;      // 9216
    constexpr int STAGE  = ABYTES + BBYTES;    // 27648
    constexpr int CS     = BN + 4;             // 68
    constexpr int BF4    = BN / 4;             // 16

    extern __shared__ char smc[];
    __shared__ int rIdx[128];
    __shared__ int s_cnt;

    const int tid = threadIdx.x, wid = tid >> 5, lane = tid & 31;
    const int wr = wid >> 1, wc = wid & 1;
    const int g = lane >> 2, t = lane & 3;
    const int mBase = blockIdx.y * 128, nBase = blockIdx.x * BN, z = blockIdx.z;
    const int e = (MODE >= 4) ? (mBase >> 11) : 0;

    if (MODE == 4 || MODE == 5) {
        if (tid == 0) s_cnt = g_cnt[e];
        __syncthreads();
        if ((mBase & (CAP_-1)) >= s_cnt) return;
    }

    const float* A; const float* Bp; const float* biasp = bias;
    if      (MODE == 0) { A = Ag; Bp = (z==0)?Bg:((z==1)?Bg2:Bg3);
                          biasp = (z==0)?bias:((z==1)?bias2:bias3); }
    else if (MODE == 3) { A = g_ctx;  Bp = Bg; }
    else if (MODE == 4) { A = g_att;  Bp = Bg + (size_t)e * D_ * FF_; }
    else                { A = g_h;    Bp = Bg + (size_t)e * FF_ * D_; }

    {
        int m = mBase + tid, r = m;
        if (MODE == 4) {
            int pos = m & (CAP_-1);
            r = (pos < s_cnt) ? g_tokmap[e*CAP_ + pos] : 0;
        }
        rIdx[tid] = r;
    }
    __syncthreads();

    uint32_t sU = (uint32_t)__cvta_generic_to_shared(smc);

    auto issue = [&](int cix) {
        const int stg = cix & 1;
        const int k0 = cix * 32;
        const uint32_t aB = sU + stg * STAGE;
        #pragma unroll
        for (int i = 0; i < 8; i++) {
            int idx = tid + i * 128;
            int row = idx >> 3, c4 = idx & 7;
            cpa16(aB + row * (LDA*4) + c4 * 16,
                  A + (size_t)rIdx[row] * KK + k0 + c4 * 4);
        }
        const uint32_t bB = aB + ABYTES;
        #pragma unroll
        for (int i = 0; i < 4; i++) {
            int idx = tid + i * 128;
            int row = idx / BF4, c4 = idx % BF4;
            cpa16(bB + row * (LDBN*4) + c4 * 16,
                  Bp + (size_t)(k0 + row) * LDBG + nBase + c4 * 4);
        }
        cpa_commit();
    };

    float acc[4][NT][4];
    #pragma unroll
    for (int i = 0; i < 4; i++)
        #pragma unroll
        for (int j = 0; j < NT; j++)
            #pragma unroll
            for (int q = 0; q < 4; q++) acc[i][j][q] = 0.f;

    issue(0);
    for (int c = 0; c < NC; c++) {
        cpa_wait0();
        __syncthreads();
        if (c + 1 < NC) issue(c + 1);

        const int stg = c & 1;
        const uint32_t* aS = (const uint32_t*)(smc + stg * STAGE);
        const uint32_t* bS = (const uint32_t*)(smc + stg * STAGE + ABYTES);
        #pragma unroll
        for (int ks = 0; ks < 4; ks++) {
            uint32_t a[4][4];
            #pragma unroll
            for (int mt = 0; mt < 4; mt++) {
                int r = wr*64 + mt*16 + g;
                int cc = ks*8 + t;
                a[mt][0] = aS[r*LDA + cc];
                a[mt][1] = aS[(r+8)*LDA + cc];
                a[mt][2] = aS[r*LDA + cc + 4];
                a[mt][3] = aS[(r+8)*LDA + cc + 4];
            }
            uint32_t b[NT][2];
            #pragma unroll
            for (int nt = 0; nt < NT; nt++) {
                int n = wc*32 + nt*8 + g;
                int k = ks*8 + t;
                b[nt][0] = bS[k*LDBN + n];
                b[nt][1] = bS[(k+4)*LDBN + n];
            }
            #pragma unroll
            for (int mt = 0; mt < 4; mt++)
                #pragma unroll
                for (int nt = 0; nt < NT; nt++)
                    mma8(acc[mt][nt], a[mt], b[nt]);
        }
    }
    __syncthreads();

    // ---------------- epilogue ----------------
    float* cSf = (float*)smc;
    #pragma unroll
    for (int mt = 0; mt < 4; mt++) {
        #pragma unroll
        for (int nt = 0; nt < NT; nt++) {
            int r = wr*64 + mt*16 + g;
            int n = wc*32 + nt*8 + 2*t;
            *(float2*)(cSf + r*CS + n)     = make_float2(acc[mt][nt][0], acc[mt][nt][1]);
            *(float2*)(cSf + (r+8)*CS + n) = make_float2(acc[mt][nt][2], acc[mt][nt][3]);
        }
    }
    __syncthreads();

    constexpr int IT = (128 * BF4) / 128;
    #pragma unroll
    for (int it = 0; it < IT; it++) {
        int idx = it * 128 + tid;
        int row = idx / BF4, q = idx % BF4;
        float4 v = *(const float4*)(cSf + row*CS + q*4);
        int m  = mBase + row;
        int n0 = nBase + q*4;

        if (MODE == 0) {
            v.x += biasp[n0]; v.y += biasp[n0+1]; v.z += biasp[n0+2]; v.w += biasp[n0+3];
            int b = m >> 10, srow = m & 1023, hh = n0 >> 6, dh = n0 & 63;
            float* dst = (z == 0) ? g_q : ((z == 1) ? g_k : g_v);
            *(float4*)(dst + (((size_t)(b*H_ + hh)) * S_ + srow) * DH_ + dh) = v;
        } else if (MODE == 3) {
            *(float4*)(g_tmp + (size_t)m * D_ + n0) = v;
        } else if (MODE == 4) {
            int pos = m & (CAP_-1);
            if (pos < s_cnt) {
                const float4 bb = *(const float4*)(bias + (size_t)e*FF_ + n0);
                *(float4*)(g_h + (size_t)m * FF_ + n0) =
                    make_float4(gelu_f(v.x+bb.x), gelu_f(v.y+bb.y),
                                gelu_f(v.z+bb.z), gelu_f(v.w+bb.w));
            }
        } else {
            int pos = m & (CAP_-1);
            if (pos < s_cnt) {
                int tok = g_tokmap[e*CAP_ + pos];
                float gsc = g_gate[tok];
                const float4 bb = *(const float4*)(bias + (size_t)e*D_ + n0);
                *(float4*)(g_ffn + (size_t)tok * D_ + n0) =
                    make_float4((v.x+bb.x)*gsc, (v.y+bb.y)*gsc,
                                (v.z+bb.z)*gsc, (v.w+bb.w)*gsc);
            }
        }
    }
}

// ---------------- layernorm --------------------------------------------------
__global__ __launch_bounds__(256) void ln_kernel(
        const float* __restrict__ a, const float* __restrict__ bsum,
        const float* __restrict__ bias,
        const float* __restrict__ g, const float* __restrict__ beta,
        float* __restrict__ out)
{
    __shared__ float red[256];
    const int t = blockIdx.x, tid = threadIdx.x;
    const float* ap = a    + (size_t)t * D_;
    const float* bp = bsum + (size_t)t * D_;
    float v[3]; float s = 0.f;
    #pragma unroll
    for (int j=0;j<3;j++) {
        int i = tid + j*256;
        float x = ap[i] + bp[i];
        if (bias) x += bias[i];
        v[j] = x; s += x;
    }
    red[tid]=s; __syncthreads();
    for (int st=128; st>0; st>>=1) { if (tid<st) red[tid]+=red[tid+st]; __syncthreads(); }
    float mu = red[0] * (1.0f/768.0f);
    __syncthreads();
    float q = 0.f;
    #pragma unroll
    for (int j=0;j<3;j++) { float d = v[j]-mu; q += d*d; }
    red[tid]=q; __syncthreads();
    for (int st=128; st>0; st>>=1) { if (tid<st) red[tid]+=red[tid+st]; __syncthreads(); }
    float inv = rsqrtf(red[0]*(1.0f/768.0f) + 1e-12f);
    #pragma unroll
    for (int j=0;j<3;j++) {
        int i = tid + j*256;
        out[(size_t)t*D_ + i] = (v[j]-mu)*inv*g[i] + beta[i];
    }
}

// ---------------- router ------------------------------------------------------
__global__ __launch_bounds__(256) void router_kernel(
        const float* __restrict__ Wr, const float* __restrict__ br)
{
    int warp = (blockIdx.x * blockDim.x + threadIdx.x) >> 5;
    int lane = threadIdx.x & 31;
    if (warp >= T_) return;
    const float* xrow = g_att + (size_t)warp * D_;
    float acc[E_];
    #pragma unroll
    for (int e=0;e<E_;e++) acc[e]=0.f;
    for (int i = lane; i < D_; i += 32) {
        float x = xrow[i];
        const float* w = Wr + i*E_;
        #pragma unroll
        for (int e=0;e<E_;e++) acc[e] += x * w[e];
    }
    #pragma unroll
    for (int e=0;e<E_;e++)
        #pragma unroll
        for (int o=16;o>0;o>>=1)
            acc[e] += __shfl_xor_sync(0xffffffffu, acc[e], o);
    if (lane == 0) {
        float best = -1e30f; int be = 0;
        #pragma unroll
        for (int e=0;e<E_;e++) {
            float l = acc[e] + br[e];
            acc[e] = l;
            if (l > best) { best = l; be = e; }
        }
        float sm = 0.f;
        #pragma unroll
        for (int e=0;e<E_;e++) sm += expf(acc[e] - best);
        float gate = 1.0f / sm;
        int pos = atomicAdd(&g_cnt[be], 1);
        if (pos < CAP_) {
            g_tokmap[be*CAP_ + pos] = warp;
            g_gate[warp] = gate;
        }
    }
}

__global__ void zero_small() {
    if (threadIdx.x < E_) g_cnt[threadIdx.x] = 0;
}

// ---------------- launch ------------------------------------------------------
extern "C" void kernel_launch(void* const* d_in, const int* in_sizes, int n_in,
                              void* d_out, int out_size) {
    const float* x    = (const float*)d_in[0];
    const float* mask = (const float*)d_in[1];
    const float* Wq   = (const float*)d_in[2];
    const float* bq   = (const float*)d_in[3];
    const float* Wk   = (const float*)d_in[4];
    const float* bk   = (const float*)d_in[5];
    const float* Wv   = (const float*)d_in[6];
    const float* bv   = (const float*)d_in[7];
    const float* Wo   = (const float*)d_in[8];
    const float* bo   = (const float*)d_in[9];
    const float* ln1g = (const float*)d_in[10];
    const float* ln1b = (const float*)d_in[11];
    const float* Wr   = (const float*)d_in[12];
    const float* br   = (const float*)d_in[13];
    const float* W1   = (const float*)d_in[14];
    const float* b1   = (const float*)d_in[15];
    const float* W2   = (const float*)d_in[16];
    const float* b2   = (const float*)d_in[17];
    const float* ln2g = (const float*)d_in[18];
    const float* ln2b = (const float*)d_in[19];
    float* out = (float*)d_out;

    float *p_tmp, *p_att, *p_ffn;
    cudaGetSymbolAddress((void**)&p_tmp, g_tmp);
    cudaGetSymbolAddress((void**)&p_att, g_att);
    cudaGetSymbolAddress((void**)&p_ffn, g_ffn);

    constexpr int SH_G  = 2 * (128*36*4 + 32*72*4);   // 55296
    constexpr int SH_FA = 2 * (64*68*4 + 64*72*4 + 256) + 8*16*68*4;  // 106880
    cudaFuncSetAttribute((const void*)tgemm<0,768,768>,   cudaFuncAttributeMaxDynamicSharedMemorySize, SH_G);
    cudaFuncSetAttribute((const void*)tgemm<3,768,768>,   cudaFuncAttributeMaxDynamicSharedMemorySize, SH_G);
    cudaFuncSetAttribute((const void*)tgemm<4,768,3072>,  cudaFuncAttributeMaxDynamicSharedMemorySize, SH_G);
    cudaFuncSetAttribute((const void*)tgemm<5,3072,768>,  cudaFuncAttributeMaxDynamicSharedMemorySize, SH_G);
    cudaFuncSetAttribute((const void*)fattn, cudaFuncAttributeMaxDynamicSharedMemorySize, SH_FA);

    zero_small<<<1, 32>>>();

    // fused QKV projections (z selects weight/bias)
    tgemm<0,768,768><<<dim3(12,64,3), 128, SH_G>>>(x, Wq, Wk, Wv, bq, bk, bv);

    // fused flash attention -> g_ctx
    fattn<<<dim3(8, 96), 256, SH_FA>>>(mask);

    // att = LN1(x + ctx@Wo + bo)
    tgemm<3,768,768><<<dim3(12,64,1), 128, SH_G>>>(nullptr, Wo, nullptr, nullptr, nullptr, nullptr, nullptr);
    ln_kernel<<<T_, 256>>>(x, p_tmp, bo, ln1g, ln1b, p_att);

    // router + MoE
    router_kernel<<<T_/8, 256>>>(Wr, br);
    tgemm<4,768,3072><<<dim3(FF_/64, (E_*CAP_)/128, 1), 128, SH_G>>>(nullptr, W1, nullptr, nullptr, b1, nullptr, nullptr);
    tgemm<5,3072,768><<<dim3(D_/64, (E_*CAP_)/128, 1), 128, SH_G>>>(nullptr, W2, nullptr, nullptr, b2, nullptr, nullptr);

    // out = LN2(att + ffn)
    ln_kernel<<<T_, 256>>>(p_att, p_ffn, nullptr, ln2g, ln2b, out);
}

// round 8
// speedup vs baseline: 1.1260x; 1.1260x over previous
#include <cuda_runtime.h>
#include <cstdint>
#include <math.h>

#define B_  8
#define S_  1024
#define D_  768
#define H_  12
#define DH_ 64
#define FF_ 3072
#define E_  8
#define CAP_ 2048
#define T_  8192

// ---------------- scratch (device globals) ----------------------------------
__device__ float g_q[B_*H_*S_*DH_];
__device__ float g_k[B_*H_*S_*DH_];
__device__ float g_v[B_*H_*S_*DH_];
__device__ float g_ctx[T_*D_];
__device__ float g_tmp[T_*D_];
__device__ float g_att[T_*D_];
__device__ float g_h[50331648];            // E*CAP*FF
__device__ float g_ffn[T_*D_];
__device__ int   g_cnt[E_];
__device__ int   g_tokmap[E_*CAP_];
__device__ float g_gate[T_];

__device__ __forceinline__ float gelu_f(float x) {
    return 0.5f * x * (1.0f + erff(x * 0.70710678118654752f));
}

__device__ __forceinline__ void cpa16(uint32_t dst, const void* src) {
    asm volatile("cp.async.ca.shared.global [%0], [%1], 16;" :: "r"(dst), "l"(src));
}
__device__ __forceinline__ void cpa_commit() {
    asm volatile("cp.async.commit_group;" ::: "memory");
}
__device__ __forceinline__ void cpa_wait0() {
    asm volatile("cp.async.wait_group 0;" ::: "memory");
}
__device__ __forceinline__ void mma8(float* c, const uint32_t* a, const uint32_t* b) {
    asm volatile(
        "mma.sync.aligned.m16n8k8.row.col.f32.tf32.tf32.f32 "
        "{%0,%1,%2,%3}, {%4,%5,%6,%7}, {%8,%9}, {%0,%1,%2,%3};\n"
        : "+f"(c[0]), "+f"(c[1]), "+f"(c[2]), "+f"(c[3])
        : "r"(a[0]), "r"(a[1]), "r"(a[2]), "r"(a[3]), "r"(b[0]), "r"(b[1]));
}

// ================= fused flash attention =====================================
__global__ __launch_bounds__(256) void fattn(const float* __restrict__ mask)
{
    constexpr int LDK = 68, LDV = 72, LDP = 68;
    constexpr int KBYTES = 64 * LDK * 4;
    constexpr int VBYTES = 64 * LDV * 4;
    constexpr int MBYTES = 256;
    constexpr int STAGE  = KBYTES + VBYTES + MBYTES;
    extern __shared__ char smc[];
    float* pS_all = (float*)(smc + 2 * STAGE);

    const int tid = threadIdx.x, wid = tid >> 5, lane = tid & 31;
    const int g = lane >> 2, t = lane & 3;
    const int z = blockIdx.y, mBase = blockIdx.x * 128;
    const int bq = z / H_, hh = z % H_;
    const int m0 = mBase + wid * 16;

    const float* Qp = g_q + (size_t)z * S_ * DH_;
    const float* Kp = g_k + (size_t)z * S_ * DH_;
    const float* Vp = g_v + (size_t)z * S_ * DH_;

    uint32_t qf[8][4];
    #pragma unroll
    for (int kb = 0; kb < 8; kb++) {
        qf[kb][0] = __float_as_uint(Qp[(m0 + g)     * DH_ + kb*8 + t]);
        qf[kb][1] = __float_as_uint(Qp[(m0 + g + 8) * DH_ + kb*8 + t]);
        qf[kb][2] = __float_as_uint(Qp[(m0 + g)     * DH_ + kb*8 + t + 4]);
        qf[kb][3] = __float_as_uint(Qp[(m0 + g + 8) * DH_ + kb*8 + t + 4]);
    }

    float oacc[8][4];
    #pragma unroll
    for (int nt = 0; nt < 8; nt++)
        #pragma unroll
        for (int q = 0; q < 4; q++) oacc[nt][q] = 0.f;
    float mrow0 = -1e30f, mrow1 = -1e30f, lrow0 = 0.f, lrow1 = 0.f;

    uint32_t sU = (uint32_t)__cvta_generic_to_shared(smc);
    auto issue = [&](int kt) {
        const int stg = kt & 1;
        const uint32_t base = sU + stg * STAGE;
        #pragma unroll
        for (int i = 0; i < 4; i++) {
            int idx = tid + i * 256;
            int row = idx >> 4, c4 = idx & 15;
            cpa16(base + row * (LDK*4) + c4 * 16,
                  Kp + (size_t)(kt*64 + row) * DH_ + c4 * 4);
        }
        #pragma unroll
        for (int i = 0; i < 4; i++) {
            int idx = tid + i * 256;
            int row = idx >> 4, c4 = idx & 15;
            cpa16(base + KBYTES + row * (LDV*4) + c4 * 16,
                  Vp + (size_t)(kt*64 + row) * DH_ + c4 * 4);
        }
        if (tid < 16)
            cpa16(base + KBYTES + VBYTES + tid * 16, mask + bq * S_ + kt*64 + tid * 4);
        cpa_commit();
    };

    float* pS = pS_all + wid * 16 * LDP;

    issue(0);
    for (int kt = 0; kt < 16; kt++) {
        cpa_wait0();
        __syncthreads();
        if (kt + 1 < 16) issue(kt + 1);

        const int stg = kt & 1;
        const float* kS = (const float*)(smc + stg * STAGE);
        const float* vS = (const float*)(smc + stg * STAGE + KBYTES);
        const float* mS = (const float*)(smc + stg * STAGE + KBYTES + VBYTES);

        float sacc[8][4];
        #pragma unroll
        for (int nt = 0; nt < 8; nt++)
            #pragma unroll
            for (int q = 0; q < 4; q++) sacc[nt][q] = 0.f;
        #pragma unroll
        for (int ks = 0; ks < 8; ks++) {
            #pragma unroll
            for (int nt = 0; nt < 8; nt++) {
                uint32_t b[2];
                b[0] = __float_as_uint(kS[(nt*8 + g) * LDK + ks*8 + t]);
                b[1] = __float_as_uint(kS[(nt*8 + g) * LDK + ks*8 + t + 4]);
                mma8(sacc[nt], qf[ks], b);
            }
        }

        float mx0 = -1e30f, mx1 = -1e30f;
        #pragma unroll
        for (int nt = 0; nt < 8; nt++) {
            float mk0 = mS[nt*8 + 2*t], mk1 = mS[nt*8 + 2*t + 1];
            sacc[nt][0] = sacc[nt][0]*0.125f + mk0;
            sacc[nt][1] = sacc[nt][1]*0.125f + mk1;
            sacc[nt][2] = sacc[nt][2]*0.125f + mk0;
            sacc[nt][3] = sacc[nt][3]*0.125f + mk1;
            mx0 = fmaxf(mx0, fmaxf(sacc[nt][0], sacc[nt][1]));
            mx1 = fmaxf(mx1, fmaxf(sacc[nt][2], sacc[nt][3]));
        }
        mx0 = fmaxf(mx0, __shfl_xor_sync(0xffffffffu, mx0, 1));
        mx0 = fmaxf(mx0, __shfl_xor_sync(0xffffffffu, mx0, 2));
        mx1 = fmaxf(mx1, __shfl_xor_sync(0xffffffffu, mx1, 1));
        mx1 = fmaxf(mx1, __shfl_xor_sync(0xffffffffu, mx1, 2));

        float mn0 = fmaxf(mrow0, mx0), mn1 = fmaxf(mrow1, mx1);
        float a0 = __expf(mrow0 - mn0), a1 = __expf(mrow1 - mn1);
        mrow0 = mn0; mrow1 = mn1;

        float s0 = 0.f, s1 = 0.f;
        #pragma unroll
        for (int nt = 0; nt < 8; nt++) {
            float p0 = __expf(sacc[nt][0] - mn0);
            float p1 = __expf(sacc[nt][1] - mn0);
            float p2 = __expf(sacc[nt][2] - mn1);
            float p3 = __expf(sacc[nt][3] - mn1);
            s0 += p0 + p1; s1 += p2 + p3;
            *(float2*)(pS + g * LDP + nt*8 + 2*t)       = make_float2(p0, p1);
            *(float2*)(pS + (g + 8) * LDP + nt*8 + 2*t) = make_float2(p2, p3);
        }
        s0 += __shfl_xor_sync(0xffffffffu, s0, 1);
        s0 += __shfl_xor_sync(0xffffffffu, s0, 2);
        s1 += __shfl_xor_sync(0xffffffffu, s1, 1);
        s1 += __shfl_xor_sync(0xffffffffu, s1, 2);
        lrow0 = lrow0 * a0 + s0;
        lrow1 = lrow1 * a1 + s1;

        #pragma unroll
        for (int nt = 0; nt < 8; nt++) {
            oacc[nt][0] *= a0; oacc[nt][1] *= a0;
            oacc[nt][2] *= a1; oacc[nt][3] *= a1;
        }
        __syncwarp();

        #pragma unroll
        for (int kb = 0; kb < 8; kb++) {
            uint32_t a[4];
            a[0] = __float_as_uint(pS[g * LDP + kb*8 + t]);
            a[1] = __float_as_uint(pS[(g + 8) * LDP + kb*8 + t]);
            a[2] = __float_as_uint(pS[g * LDP + kb*8 + t + 4]);
            a[3] = __float_as_uint(pS[(g + 8) * LDP + kb*8 + t + 4]);
            #pragma unroll
            for (int nt = 0; nt < 8; nt++) {
                uint32_t b[2];
                b[0] = __float_as_uint(vS[(kb*8 + t)     * LDV + nt*8 + g]);
                b[1] = __float_as_uint(vS[(kb*8 + t + 4) * LDV + nt*8 + g]);
                mma8(oacc[nt], a, b);
            }
        }
    }

    float inv0 = 1.0f / lrow0, inv1 = 1.0f / lrow1;
    int mr0 = m0 + g, mr1 = m0 + g + 8;
    #pragma unroll
    for (int nt = 0; nt < 8; nt++) {
        int col = hh * DH_ + nt*8 + 2*t;
        *(float2*)(g_ctx + ((size_t)(bq * S_ + mr0)) * D_ + col) =
            make_float2(oacc[nt][0] * inv0, oacc[nt][1] * inv0);
        *(float2*)(g_ctx + ((size_t)(bq * S_ + mr1)) * D_ + col) =
            make_float2(oacc[nt][2] * inv1, oacc[nt][3] * inv1);
    }
}

// ---------------- tf32 mma.sync GEMM: 128x128 tile, 128 threads --------------
// 4 warps in 2x2; warp tile 64x64 (NT=8) -> 1.0 LDS per MMA.
// A[M][KK] k-major (opt. gathered). B[k][n] n-major, row stride LDBG.
// MODE 0: QKV proj (z selects W/b), headed scatter
// MODE 3: ctx @ Wo -> g_tmp
// MODE 4: gather(att) @ W1[e] + b1 -> gelu -> g_h
// MODE 5: g_h @ W2[e] + b2, * gate, scatter -> g_ffn
template<int MODE, int KK, int LDBG>
__global__ __launch_bounds__(128, 2)
void tgemm(const float* __restrict__ Ag, const float* __restrict__ Bg,
           const float* __restrict__ Bg2, const float* __restrict__ Bg3,
           const float* __restrict__ bias, const float* __restrict__ bias2,
           const float* __restrict__ bias3)
{
    constexpr int BN     = 128;
    constexpr int NC     = KK / 32;
    constexpr int NT     = 8;                  // warp tile 64 x 64
    constexpr int LDA    = 36;
    constexpr int LDBN   = BN + 8;             // 136
    constexpr int ABYTES = 128 * LDA * 4;      // 18432
    constexpr int BBYTES = 32 * LDBN * 4;      // 17408
    constexpr int STAGE  = ABYTES + BBYTES;    // 35840
    constexpr int CS     = BN + 4;             // 132
    constexpr int BF4    = BN / 4;             // 32

    extern __shared__ char smc[];
    __shared__ int rIdx[128];
    __shared__ int s_cnt;

    const int tid = threadIdx.x, wid = tid >> 5, lane = tid & 31;
    const int wr = wid >> 1, wc = wid & 1;
    const int g = lane >> 2, t = lane & 3;
    const int mBase = blockIdx.y * 128, nBase = blockIdx.x * BN, z = blockIdx.z;
    const int e = (MODE >= 4) ? (mBase >> 11) : 0;

    if (MODE == 4 || MODE == 5) {
        if (tid == 0) s_cnt = g_cnt[e];
        __syncthreads();
        if ((mBase & (CAP_-1)) >= s_cnt) return;
    }

    const float* A; const float* Bp; const float* biasp = bias;
    if      (MODE == 0) { A = Ag; Bp = (z==0)?Bg:((z==1)?Bg2:Bg3);
                          biasp = (z==0)?bias:((z==1)?bias2:bias3); }
    else if (MODE == 3) { A = g_ctx;  Bp = Bg; }
    else if (MODE == 4) { A = g_att;  Bp = Bg + (size_t)e * D_ * FF_; }
    else                { A = g_h;    Bp = Bg + (size_t)e * FF_ * D_; }

    {
        int m = mBase + tid, r = m;
        if (MODE == 4) {
            int pos = m & (CAP_-1);
            r = (pos < s_cnt) ? g_tokmap[e*CAP_ + pos] : 0;
        }
        rIdx[tid] = r;
    }
    __syncthreads();

    uint32_t sU = (uint32_t)__cvta_generic_to_shared(smc);

    auto issue = [&](int cix) {
        const int stg = cix & 1;
        const int k0 = cix * 32;
        const uint32_t aB = sU + stg * STAGE;
        #pragma unroll
        for (int i = 0; i < 8; i++) {
            int idx = tid + i * 128;
            int row = idx >> 3, c4 = idx & 7;
            cpa16(aB + row * (LDA*4) + c4 * 16,
                  A + (size_t)rIdx[row] * KK + k0 + c4 * 4);
        }
        const uint32_t bB = aB + ABYTES;
        #pragma unroll
        for (int i = 0; i < 8; i++) {
            int idx = tid + i * 128;
            int row = idx >> 5, c4 = idx & 31;
            cpa16(bB + row * (LDBN*4) + c4 * 16,
                  Bp + (size_t)(k0 + row) * LDBG + nBase + c4 * 4);
        }
        cpa_commit();
    };

    float acc[4][NT][4];
    #pragma unroll
    for (int i = 0; i < 4; i++)
        #pragma unroll
        for (int j = 0; j < NT; j++)
            #pragma unroll
            for (int q = 0; q < 4; q++) acc[i][j][q] = 0.f;

    issue(0);
    for (int c = 0; c < NC; c++) {
        cpa_wait0();
        __syncthreads();
        if (c + 1 < NC) issue(c + 1);

        const int stg = c & 1;
        const uint32_t* aS = (const uint32_t*)(smc + stg * STAGE);
        const uint32_t* bS = (const uint32_t*)(smc + stg * STAGE + ABYTES);
        #pragma unroll
        for (int ks = 0; ks < 4; ks++) {
            uint32_t a[4][4];
            #pragma unroll
            for (int mt = 0; mt < 4; mt++) {
                int r = wr*64 + mt*16 + g;
                int cc = ks*8 + t;
                a[mt][0] = aS[r*LDA + cc];
                a[mt][1] = aS[(r+8)*LDA + cc];
                a[mt][2] = aS[r*LDA + cc + 4];
                a[mt][3] = aS[(r+8)*LDA + cc + 4];
            }
            uint32_t b[NT][2];
            #pragma unroll
            for (int nt = 0; nt < NT; nt++) {
                int n = wc*64 + nt*8 + g;
                int k = ks*8 + t;
                b[nt][0] = bS[k*LDBN + n];
                b[nt][1] = bS[(k+4)*LDBN + n];
            }
            #pragma unroll
            for (int mt = 0; mt < 4; mt++)
                #pragma unroll
                for (int nt = 0; nt < NT; nt++)
                    mma8(acc[mt][nt], a[mt], b[nt]);
        }
    }
    __syncthreads();

    // ---------------- epilogue ----------------
    float* cSf = (float*)smc;
    #pragma unroll
    for (int mt = 0; mt < 4; mt++) {
        #pragma unroll
        for (int nt = 0; nt < NT; nt++) {
            int r = wr*64 + mt*16 + g;
            int n = wc*64 + nt*8 + 2*t;
            *(float2*)(cSf + r*CS + n)     = make_float2(acc[mt][nt][0], acc[mt][nt][1]);
            *(float2*)(cSf + (r+8)*CS + n) = make_float2(acc[mt][nt][2], acc[mt][nt][3]);
        }
    }
    __syncthreads();

    constexpr int IT = (128 * BF4) / 128;
    #pragma unroll
    for (int it = 0; it < IT; it++) {
        int idx = it * 128 + tid;
        int row = idx / BF4, q = idx % BF4;
        float4 v = *(const float4*)(cSf + row*CS + q*4);
        int m  = mBase + row;
        int n0 = nBase + q*4;

        if (MODE == 0) {
            v.x += biasp[n0]; v.y += biasp[n0+1]; v.z += biasp[n0+2]; v.w += biasp[n0+3];
            int b = m >> 10, srow = m & 1023, hh = n0 >> 6, dh = n0 & 63;
            float* dst = (z == 0) ? g_q : ((z == 1) ? g_k : g_v);
            *(float4*)(dst + (((size_t)(b*H_ + hh)) * S_ + srow) * DH_ + dh) = v;
        } else if (MODE == 3) {
            *(float4*)(g_tmp + (size_t)m * D_ + n0) = v;
        } else if (MODE == 4) {
            int pos = m & (CAP_-1);
            if (pos < s_cnt) {
                const float4 bb = *(const float4*)(bias + (size_t)e*FF_ + n0);
                *(float4*)(g_h + (size_t)m * FF_ + n0) =
                    make_float4(gelu_f(v.x+bb.x), gelu_f(v.y+bb.y),
                                gelu_f(v.z+bb.z), gelu_f(v.w+bb.w));
            }
        } else {
            int pos = m & (CAP_-1);
            if (pos < s_cnt) {
                int tok = g_tokmap[e*CAP_ + pos];
                float gsc = g_gate[tok];
                const float4 bb = *(const float4*)(bias + (size_t)e*D_ + n0);
                *(float4*)(g_ffn + (size_t)tok * D_ + n0) =
                    make_float4((v.x+bb.x)*gsc, (v.y+bb.y)*gsc,
                                (v.z+bb.z)*gsc, (v.w+bb.w)*gsc);
            }
        }
    }
}

// ---------------- layernorm --------------------------------------------------
__global__ __launch_bounds__(256) void ln_kernel(
        const float* __restrict__ a, const float* __restrict__ bsum,
        const float* __restrict__ bias,
        const float* __restrict__ g, const float* __restrict__ beta,
        float* __restrict__ out)
{
    __shared__ float red[256];
    const int t = blockIdx.x, tid = threadIdx.x;
    const float* ap = a    + (size_t)t * D_;
    const float* bp = bsum + (size_t)t * D_;
    float v[3]; float s = 0.f;
    #pragma unroll
    for (int j=0;j<3;j++) {
        int i = tid + j*256;
        float x = ap[i] + bp[i];
        if (bias) x += bias[i];
        v[j] = x; s += x;
    }
    red[tid]=s; __syncthreads();
    for (int st=128; st>0; st>>=1) { if (tid<st) red[tid]+=red[tid+st]; __syncthreads(); }
    float mu = red[0] * (1.0f/768.0f);
    __syncthreads();
    float q = 0.f;
    #pragma unroll
    for (int j=0;j<3;j++) { float d = v[j]-mu; q += d*d; }
    red[tid]=q; __syncthreads();
    for (int st=128; st>0; st>>=1) { if (tid<st) red[tid]+=red[tid+st]; __syncthreads(); }
    float inv = rsqrtf(red[0]*(1.0f/768.0f) + 1e-12f);
    #pragma unroll
    for (int j=0;j<3;j++) {
        int i = tid + j*256;
        out[(size_t)t*D_ + i] = (v[j]-mu)*inv*g[i] + beta[i];
    }
}

// ---------------- router ------------------------------------------------------
__global__ __launch_bounds__(256) void router_kernel(
        const float* __restrict__ Wr, const float* __restrict__ br)
{
    int warp = (blockIdx.x * blockDim.x + threadIdx.x) >> 5;
    int lane = threadIdx.x & 31;
    if (warp >= T_) return;
    const float* xrow = g_att + (size_t)warp * D_;
    float acc[E_];
    #pragma unroll
    for (int e=0;e<E_;e++) acc[e]=0.f;
    for (int i = lane; i < D_; i += 32) {
        float x = xrow[i];
        const float* w = Wr + i*E_;
        #pragma unroll
        for (int e=0;e<E_;e++) acc[e] += x * w[e];
    }
    #pragma unroll
    for (int e=0;e<E_;e++)
        #pragma unroll
        for (int o=16;o>0;o>>=1)
            acc[e] += __shfl_xor_sync(0xffffffffu, acc[e], o);
    if (lane == 0) {
        float best = -1e30f; int be = 0;
        #pragma unroll
        for (int e=0;e<E_;e++) {
            float l = acc[e] + br[e];
            acc[e] = l;
            if (l > best) { best = l; be = e; }
        }
        float sm = 0.f;
        #pragma unroll
        for (int e=0;e<E_;e++) sm += expf(acc[e] - best);
        float gate = 1.0f / sm;
        int pos = atomicAdd(&g_cnt[be], 1);
        if (pos < CAP_) {
            g_tokmap[be*CAP_ + pos] = warp;
            g_gate[warp] = gate;
        }
    }
}

__global__ void zero_small() {
    if (threadIdx.x < E_) g_cnt[threadIdx.x] = 0;
}

// ---------------- launch ------------------------------------------------------
extern "C" void kernel_launch(void* const* d_in, const int* in_sizes, int n_in,
                              void* d_out, int out_size) {
    const float* x    = (const float*)d_in[0];
    const float* mask = (const float*)d_in[1];
    const float* Wq   = (const float*)d_in[2];
    const float* bq   = (const float*)d_in[3];
    const float* Wk   = (const float*)d_in[4];
    const float* bk   = (const float*)d_in[5];
    const float* Wv   = (const float*)d_in[6];
    const float* bv   = (const float*)d_in[7];
    const float* Wo   = (const float*)d_in[8];
    const float* bo   = (const float*)d_in[9];
    const float* ln1g = (const float*)d_in[10];
    const float* ln1b = (const float*)d_in[11];
    const float* Wr   = (const float*)d_in[12];
    const float* br   = (const float*)d_in[13];
    const float* W1   = (const float*)d_in[14];
    const float* b1   = (const float*)d_in[15];
    const float* W2   = (const float*)d_in[16];
    const float* b2   = (const float*)d_in[17];
    const float* ln2g = (const float*)d_in[18];
    const float* ln2b = (const float*)d_in[19];
    float* out = (float*)d_out;

    float *p_tmp, *p_att, *p_ffn;
    cudaGetSymbolAddress((void**)&p_tmp, g_tmp);
    cudaGetSymbolAddress((void**)&p_att, g_att);
    cudaGetSymbolAddress((void**)&p_ffn, g_ffn);

    constexpr int SH_G  = 2 * (128*36*4 + 32*136*4);   // 71680
    constexpr int SH_FA = 2 * (64*68*4 + 64*72*4 + 256) + 8*16*68*4;  // 106880
    cudaFuncSetAttribute((const void*)tgemm<0,768,768>,   cudaFuncAttributeMaxDynamicSharedMemorySize, SH_G);
    cudaFuncSetAttribute((const void*)tgemm<3,768,768>,   cudaFuncAttributeMaxDynamicSharedMemorySize, SH_G);
    cudaFuncSetAttribute((const void*)tgemm<4,768,3072>,  cudaFuncAttributeMaxDynamicSharedMemorySize, SH_G);
    cudaFuncSetAttribute((const void*)tgemm<5,3072,768>,  cudaFuncAttributeMaxDynamicSharedMemorySize, SH_G);
    cudaFuncSetAttribute((const void*)fattn, cudaFuncAttributeMaxDynamicSharedMemorySize, SH_FA);

    zero_small<<<1, 32>>>();

    // fused QKV projections (z selects weight/bias)
    tgemm<0,768,768><<<dim3(6,64,3), 128, SH_G>>>(x, Wq, Wk, Wv, bq, bk, bv);

    // fused flash attention -> g_ctx
    fattn<<<dim3(8, 96), 256, SH_FA>>>(mask);

    // att = LN1(x + ctx@Wo + bo)
    tgemm<3,768,768><<<dim3(6,64,1), 128, SH_G>>>(nullptr, Wo, nullptr, nullptr, nullptr, nullptr, nullptr);
    ln_kernel<<<T_, 256>>>(x, p_tmp, bo, ln1g, ln1b, p_att);

    // router + MoE
    router_kernel<<<T_/8, 256>>>(Wr, br);
    tgemm<4,768,3072><<<dim3(FF_/128, (E_*CAP_)/128, 1), 128, SH_G>>>(nullptr, W1, nullptr, nullptr, b1, nullptr, nullptr);
    tgemm<5,3072,768><<<dim3(D_/128, (E_*CAP_)/128, 1), 128, SH_G>>>(nullptr, W2, nullptr, nullptr, b2, nullptr, nullptr);

    // out = LN2(att + ffn)
    ln_kernel<<<T_, 256>>>(p_att, p_ffn, nullptr, ln2g, ln2b, out);
}

// round 9
// speedup vs baseline: 1.1520x; 1.0231x over previous
#include <cuda_runtime.h>
#include <cstdint>
#include <math.h>

#define B_  8
#define S_  1024
#define D_  768
#define H_  12
#define DH_ 64
#define FF_ 3072
#define E_  8
#define CAP_ 2048
#define T_  8192

// ---------------- scratch (device globals) ----------------------------------
__device__ float g_q[B_*H_*S_*DH_];
__device__ float g_k[B_*H_*S_*DH_];
__device__ float g_v[B_*H_*S_*DH_];
__device__ float g_ctx[T_*D_];
__device__ float g_tmp[T_*D_];
__device__ float g_att[T_*D_];
__device__ float g_h[50331648];            // E*CAP*FF
__device__ float g_ffn[T_*D_];
__device__ int   g_cnt[E_];
__device__ int   g_tokmap[E_*CAP_];
__device__ float g_gate[T_];

__device__ __forceinline__ float gelu_f(float x) {
    return 0.5f * x * (1.0f + erff(x * 0.70710678118654752f));
}

__device__ __forceinline__ void cpa16(uint32_t dst, const void* src) {
    asm volatile("cp.async.ca.shared.global [%0], [%1], 16;" :: "r"(dst), "l"(src));
}
__device__ __forceinline__ void cpa_commit() {
    asm volatile("cp.async.commit_group;" ::: "memory");
}
__device__ __forceinline__ void cpa_wait0() {
    asm volatile("cp.async.wait_group 0;" ::: "memory");
}
__device__ __forceinline__ void mma8(float* c, const uint32_t* a, const uint32_t* b) {
    asm volatile(
        "mma.sync.aligned.m16n8k8.row.col.f32.tf32.tf32.f32 "
        "{%0,%1,%2,%3}, {%4,%5,%6,%7}, {%8,%9}, {%0,%1,%2,%3};\n"
        : "+f"(c[0]), "+f"(c[1]), "+f"(c[2]), "+f"(c[3])
        : "r"(a[0]), "r"(a[1]), "r"(a[2]), "r"(a[3]), "r"(b[0]), "r"(b[1]));
}
// ldmatrix.x4 on 32-bit data: returns m16xk8 f32 fragment
// r0=(row g, col t) r1=(g+8,t) r2=(g,t+4) r3=(g+8,t+4) for per-lane addr
// addr = base + (lane&15)*rowStrideBytes + ((lane>>4)<<4)
__device__ __forceinline__ void ldsm4(uint32_t* r, uint32_t addr) {
    asm volatile("ldmatrix.sync.aligned.m8n8.x4.b16 {%0,%1,%2,%3}, [%4];"
                 : "=r"(r[0]), "=r"(r[1]), "=r"(r[2]), "=r"(r[3]) : "r"(addr));
}

// ================= fused flash attention =====================================
__global__ __launch_bounds__(256) void fattn(const float* __restrict__ mask)
{
    constexpr int LDK = 68, LDV = 72, LDP = 68;
    constexpr int KBYTES = 64 * LDK * 4;
    constexpr int VBYTES = 64 * LDV * 4;
    constexpr int MBYTES = 256;
    constexpr int STAGE  = KBYTES + VBYTES + MBYTES;
    extern __shared__ char smc[];
    float* pS_all = (float*)(smc + 2 * STAGE);

    const int tid = threadIdx.x, wid = tid >> 5, lane = tid & 31;
    const int g = lane >> 2, t = lane & 3;
    const int z = blockIdx.y, mBase = blockIdx.x * 128;
    const int bq = z / H_, hh = z % H_;
    const int m0 = mBase + wid * 16;

    const float* Qp = g_q + (size_t)z * S_ * DH_;
    const float* Kp = g_k + (size_t)z * S_ * DH_;
    const float* Vp = g_v + (size_t)z * S_ * DH_;

    uint32_t qf[8][4];
    #pragma unroll
    for (int kb = 0; kb < 8; kb++) {
        qf[kb][0] = __float_as_uint(Qp[(m0 + g)     * DH_ + kb*8 + t]);
        qf[kb][1] = __float_as_uint(Qp[(m0 + g + 8) * DH_ + kb*8 + t]);
        qf[kb][2] = __float_as_uint(Qp[(m0 + g)     * DH_ + kb*8 + t + 4]);
        qf[kb][3] = __float_as_uint(Qp[(m0 + g + 8) * DH_ + kb*8 + t + 4]);
    }

    float oacc[8][4];
    #pragma unroll
    for (int nt = 0; nt < 8; nt++)
        #pragma unroll
        for (int q = 0; q < 4; q++) oacc[nt][q] = 0.f;
    float mrow0 = -1e30f, mrow1 = -1e30f, lrow0 = 0.f, lrow1 = 0.f;

    uint32_t sU = (uint32_t)__cvta_generic_to_shared(smc);
    // per-lane ldmatrix offsets
    const uint32_t lmRow = (lane & 15);
    const uint32_t lmHalf = (lane >> 4) << 4;
    const uint32_t kOff = lmRow * (LDK*4) + lmHalf;
    const uint32_t pU   = sU + 2*STAGE + wid * 16 * (LDP*4);
    const uint32_t pOff = pU + lmRow * (LDP*4) + lmHalf;

    auto issue = [&](int kt) {
        const int stg = kt & 1;
        const uint32_t base = sU + stg * STAGE;
        #pragma unroll
        for (int i = 0; i < 4; i++) {
            int idx = tid + i * 256;
            int row = idx >> 4, c4 = idx & 15;
            cpa16(base + row * (LDK*4) + c4 * 16,
                  Kp + (size_t)(kt*64 + row) * DH_ + c4 * 4);
        }
        #pragma unroll
        for (int i = 0; i < 4; i++) {
            int idx = tid + i * 256;
            int row = idx >> 4, c4 = idx & 15;
            cpa16(base + KBYTES + row * (LDV*4) + c4 * 16,
                  Vp + (size_t)(kt*64 + row) * DH_ + c4 * 4);
        }
        if (tid < 16)
            cpa16(base + KBYTES + VBYTES + tid * 16, mask + bq * S_ + kt*64 + tid * 4);
        cpa_commit();
    };

    float* pS = pS_all + wid * 16 * LDP;

    issue(0);
    for (int kt = 0; kt < 16; kt++) {
        cpa_wait0();
        __syncthreads();
        if (kt + 1 < 16) issue(kt + 1);

        const int stg = kt & 1;
        const uint32_t kBase = sU + stg * STAGE;
        const float* vS = (const float*)(smc + stg * STAGE + KBYTES);
        const float* mS = (const float*)(smc + stg * STAGE + KBYTES + VBYTES);

        float sacc[8][4];
        #pragma unroll
        for (int nt = 0; nt < 8; nt++)
            #pragma unroll
            for (int q = 0; q < 4; q++) sacc[nt][q] = 0.f;
        #pragma unroll
        for (int ks = 0; ks < 8; ks++) {
            #pragma unroll
            for (int p = 0; p < 4; p++) {   // 16 key rows per ldmatrix.x4
                uint32_t r[4];
                ldsm4(r, kBase + kOff + p * 16 * (LDK*4) + ks * 32);
                uint32_t b0[2] = { r[0], r[2] };
                uint32_t b1[2] = { r[1], r[3] };
                mma8(sacc[2*p],   qf[ks], b0);
                mma8(sacc[2*p+1], qf[ks], b1);
            }
        }

        float mx0 = -1e30f, mx1 = -1e30f;
        #pragma unroll
        for (int nt = 0; nt < 8; nt++) {
            float mk0 = mS[nt*8 + 2*t], mk1 = mS[nt*8 + 2*t + 1];
            sacc[nt][0] = sacc[nt][0]*0.125f + mk0;
            sacc[nt][1] = sacc[nt][1]*0.125f + mk1;
            sacc[nt][2] = sacc[nt][2]*0.125f + mk0;
            sacc[nt][3] = sacc[nt][3]*0.125f + mk1;
            mx0 = fmaxf(mx0, fmaxf(sacc[nt][0], sacc[nt][1]));
            mx1 = fmaxf(mx1, fmaxf(sacc[nt][2], sacc[nt][3]));
        }
        mx0 = fmaxf(mx0, __shfl_xor_sync(0xffffffffu, mx0, 1));
        mx0 = fmaxf(mx0, __shfl_xor_sync(0xffffffffu, mx0, 2));
        mx1 = fmaxf(mx1, __shfl_xor_sync(0xffffffffu, mx1, 1));
        mx1 = fmaxf(mx1, __shfl_xor_sync(0xffffffffu, mx1, 2));

        float mn0 = fmaxf(mrow0, mx0), mn1 = fmaxf(mrow1, mx1);
        float a0 = __expf(mrow0 - mn0), a1 = __expf(mrow1 - mn1);
        mrow0 = mn0; mrow1 = mn1;

        float s0 = 0.f, s1 = 0.f;
        #pragma unroll
        for (int nt = 0; nt < 8; nt++) {
            float p0 = __expf(sacc[nt][0] - mn0);
            float p1 = __expf(sacc[nt][1] - mn0);
            float p2 = __expf(sacc[nt][2] - mn1);
            float p3 = __expf(sacc[nt][3] - mn1);
            s0 += p0 + p1; s1 += p2 + p3;
            *(float2*)(pS + g * LDP + nt*8 + 2*t)       = make_float2(p0, p1);
            *(float2*)(pS + (g + 8) * LDP + nt*8 + 2*t) = make_float2(p2, p3);
        }
        s0 += __shfl_xor_sync(0xffffffffu, s0, 1);
        s0 += __shfl_xor_sync(0xffffffffu, s0, 2);
        s1 += __shfl_xor_sync(0xffffffffu, s1, 1);
        s1 += __shfl_xor_sync(0xffffffffu, s1, 2);
        lrow0 = lrow0 * a0 + s0;
        lrow1 = lrow1 * a1 + s1;

        #pragma unroll
        for (int nt = 0; nt < 8; nt++) {
            oacc[nt][0] *= a0; oacc[nt][1] *= a0;
            oacc[nt][2] *= a1; oacc[nt][3] *= a1;
        }
        __syncwarp();

        #pragma unroll
        for (int kb = 0; kb < 8; kb++) {
            uint32_t a[4];
            ldsm4(a, pOff + kb * 32);
            #pragma unroll
            for (int nt = 0; nt < 8; nt++) {
                uint32_t b[2];
                b[0] = __float_as_uint(vS[(kb*8 + t)     * LDV + nt*8 + g]);
                b[1] = __float_as_uint(vS[(kb*8 + t + 4) * LDV + nt*8 + g]);
                mma8(oacc[nt], a, b);
            }
        }
    }

    float inv0 = 1.0f / lrow0, inv1 = 1.0f / lrow1;
    int mr0 = m0 + g, mr1 = m0 + g + 8;
    #pragma unroll
    for (int nt = 0; nt < 8; nt++) {
        int col = hh * DH_ + nt*8 + 2*t;
        *(float2*)(g_ctx + ((size_t)(bq * S_ + mr0)) * D_ + col) =
            make_float2(oacc[nt][0] * inv0, oacc[nt][1] * inv0);
        *(float2*)(g_ctx + ((size_t)(bq * S_ + mr1)) * D_ + col) =
            make_float2(oacc[nt][2] * inv1, oacc[nt][3] * inv1);
    }
}

// ---------------- tf32 mma.sync GEMM: 128x128 tile, 128 threads --------------
// 4 warps 2x2; warp tile 64x64; A-fragments via ldmatrix.x4.
template<int MODE, int KK, int LDBG>
__global__ __launch_bounds__(128, 2)
void tgemm(const float* __restrict__ Ag, const float* __restrict__ Bg,
           const float* __restrict__ Bg2, const float* __restrict__ Bg3,
           const float* __restrict__ bias, const float* __restrict__ bias2,
           const float* __restrict__ bias3)
{
    constexpr int BN     = 128;
    constexpr int NC     = KK / 32;
    constexpr int NT     = 8;
    constexpr int LDA    = 36;
    constexpr int LDBN   = BN + 8;             // 136
    constexpr int ABYTES = 128 * LDA * 4;      // 18432
    constexpr int BBYTES = 32 * LDBN * 4;      // 17408
    constexpr int STAGE  = ABYTES + BBYTES;    // 35840
    constexpr int CS     = BN + 4;             // 132
    constexpr int BF4    = BN / 4;             // 32

    extern __shared__ char smc[];
    __shared__ int rIdx[128];
    __shared__ int s_cnt;

    const int tid = threadIdx.x, wid = tid >> 5, lane = tid & 31;
    const int wr = wid >> 1, wc = wid & 1;
    const int g = lane >> 2, t = lane & 3;
    const int mBase = blockIdx.y * 128, nBase = blockIdx.x * BN, z = blockIdx.z;
    const int e = (MODE >= 4) ? (mBase >> 11) : 0;

    if (MODE == 4 || MODE == 5) {
        if (tid == 0) s_cnt = g_cnt[e];
        __syncthreads();
        if ((mBase & (CAP_-1)) >= s_cnt) return;
    }

    const float* A; const float* Bp; const float* biasp = bias;
    if      (MODE == 0) { A = Ag; Bp = (z==0)?Bg:((z==1)?Bg2:Bg3);
                          biasp = (z==0)?bias:((z==1)?bias2:bias3); }
    else if (MODE == 3) { A = g_ctx;  Bp = Bg; }
    else if (MODE == 4) { A = g_att;  Bp = Bg + (size_t)e * D_ * FF_; }
    else                { A = g_h;    Bp = Bg + (size_t)e * FF_ * D_; }

    {
        int m = mBase + tid, r = m;
        if (MODE == 4) {
            int pos = m & (CAP_-1);
            r = (pos < s_cnt) ? g_tokmap[e*CAP_ + pos] : 0;
        }
        rIdx[tid] = r;
    }
    __syncthreads();

    uint32_t sU = (uint32_t)__cvta_generic_to_shared(smc);
    // ldmatrix per-lane offset within A tile
    const uint32_t aOff = (uint32_t)((wr*64 + (lane & 15)) * (LDA*4)) + ((lane >> 4) << 4);

    auto issue = [&](int cix) {
        const int stg = cix & 1;
        const int k0 = cix * 32;
        const uint32_t aB = sU + stg * STAGE;
        #pragma unroll
        for (int i = 0; i < 8; i++) {
            int idx = tid + i * 128;
            int row = idx >> 3, c4 = idx & 7;
            cpa16(aB + row * (LDA*4) + c4 * 16,
                  A + (size_t)rIdx[row] * KK + k0 + c4 * 4);
        }
        const uint32_t bB = aB + ABYTES;
        #pragma unroll
        for (int i = 0; i < 8; i++) {
            int idx = tid + i * 128;
            int row = idx >> 5, c4 = idx & 31;
            cpa16(bB + row * (LDBN*4) + c4 * 16,
                  Bp + (size_t)(k0 + row) * LDBG + nBase + c4 * 4);
        }
        cpa_commit();
    };

    float acc[4][NT][4];
    #pragma unroll
    for (int i = 0; i < 4; i++)
        #pragma unroll
        for (int j = 0; j < NT; j++)
            #pragma unroll
            for (int q = 0; q < 4; q++) acc[i][j][q] = 0.f;

    issue(0);
    for (int c = 0; c < NC; c++) {
        cpa_wait0();
        __syncthreads();
        if (c + 1 < NC) issue(c + 1);

        const int stg = c & 1;
        const uint32_t aBase = sU + stg * STAGE + aOff;
        const uint32_t* bS = (const uint32_t*)(smc + stg * STAGE + ABYTES);
        #pragma unroll
        for (int ks = 0; ks < 4; ks++) {
            uint32_t a[4][4];
            #pragma unroll
            for (int mt = 0; mt < 4; mt++)
                ldsm4(a[mt], aBase + mt * 16 * (LDA*4) + ks * 32);
            uint32_t b[NT][2];
            #pragma unroll
            for (int nt = 0; nt < NT; nt++) {
                int n = wc*64 + nt*8 + g;
                int k = ks*8 + t;
                b[nt][0] = bS[k*LDBN + n];
                b[nt][1] = bS[(k+4)*LDBN + n];
            }
            #pragma unroll
            for (int mt = 0; mt < 4; mt++)
                #pragma unroll
                for (int nt = 0; nt < NT; nt++)
                    mma8(acc[mt][nt], a[mt], b[nt]);
        }
    }
    __syncthreads();

    // ---------------- epilogue ----------------
    float* cSf = (float*)smc;
    #pragma unroll
    for (int mt = 0; mt < 4; mt++) {
        #pragma unroll
        for (int nt = 0; nt < NT; nt++) {
            int r = wr*64 + mt*16 + g;
            int n = wc*64 + nt*8 + 2*t;
            *(float2*)(cSf + r*CS + n)     = make_float2(acc[mt][nt][0], acc[mt][nt][1]);
            *(float2*)(cSf + (r+8)*CS + n) = make_float2(acc[mt][nt][2], acc[mt][nt][3]);
        }
    }
    __syncthreads();

    constexpr int IT = (128 * BF4) / 128;
    #pragma unroll
    for (int it = 0; it < IT; it++) {
        int idx = it * 128 + tid;
        int row = idx / BF4, q = idx % BF4;
        float4 v = *(const float4*)(cSf + row*CS + q*4);
        int m  = mBase + row;
        int n0 = nBase + q*4;

        if (MODE == 0) {
            v.x += biasp[n0]; v.y += biasp[n0+1]; v.z += biasp[n0+2]; v.w += biasp[n0+3];
            int b = m >> 10, srow = m & 1023, hh = n0 >> 6, dh = n0 & 63;
            float* dst = (z == 0) ? g_q : ((z == 1) ? g_k : g_v);
            *(float4*)(dst + (((size_t)(b*H_ + hh)) * S_ + srow) * DH_ + dh) = v;
        } else if (MODE == 3) {
            *(float4*)(g_tmp + (size_t)m * D_ + n0) = v;
        } else if (MODE == 4) {
            int pos = m & (CAP_-1);
            if (pos < s_cnt) {
                const float4 bb = *(const float4*)(bias + (size_t)e*FF_ + n0);
                *(float4*)(g_h + (size_t)m * FF_ + n0) =
                    make_float4(gelu_f(v.x+bb.x), gelu_f(v.y+bb.y),
                                gelu_f(v.z+bb.z), gelu_f(v.w+bb.w));
            }
        } else {
            int pos = m & (CAP_-1);
            if (pos < s_cnt) {
                int tok = g_tokmap[e*CAP_ + pos];
                float gsc = g_gate[tok];
                const float4 bb = *(const float4*)(bias + (size_t)e*D_ + n0);
                *(float4*)(g_ffn + (size_t)tok * D_ + n0) =
                    make_float4((v.x+bb.x)*gsc, (v.y+bb.y)*gsc,
                                (v.z+bb.z)*gsc, (v.w+bb.w)*gsc);
            }
        }
    }
}

// ---------------- layernorm --------------------------------------------------
__global__ __launch_bounds__(256) void ln_kernel(
        const float* __restrict__ a, const float* __restrict__ bsum,
        const float* __restrict__ bias,
        const float* __restrict__ g, const float* __restrict__ beta,
        float* __restrict__ out)
{
    __shared__ float red[256];
    const int t = blockIdx.x, tid = threadIdx.x;
    const float* ap = a    + (size_t)t * D_;
    const float* bp = bsum + (size_t)t * D_;
    float v[3]; float s = 0.f;
    #pragma unroll
    for (int j=0;j<3;j++) {
        int i = tid + j*256;
        float x = ap[i] + bp[i];
        if (bias) x += bias[i];
        v[j] = x; s += x;
    }
    red[tid]=s; __syncthreads();
    for (int st=128; st>0; st>>=1) { if (tid<st) red[tid]+=red[tid+st]; __syncthreads(); }
    float mu = red[0] * (1.0f/768.0f);
    __syncthreads();
    float q = 0.f;
    #pragma unroll
    for (int j=0;j<3;j++) { float d = v[j]-mu; q += d*d; }
    red[tid]=q; __syncthreads();
    for (int st=128; st>0; st>>=1) { if (tid<st) red[tid]+=red[tid+st]; __syncthreads(); }
    float inv = rsqrtf(red[0]*(1.0f/768.0f) + 1e-12f);
    #pragma unroll
    for (int j=0;j<3;j++) {
        int i = tid + j*256;
        out[(size_t)t*D_ + i] = (v[j]-mu)*inv*g[i] + beta[i];
    }
}

// ---------------- router ------------------------------------------------------
__global__ __launch_bounds__(256) void router_kernel(
        const float* __restrict__ Wr, const float* __restrict__ br)
{
    int warp = (blockIdx.x * blockDim.x + threadIdx.x) >> 5;
    int lane = threadIdx.x & 31;
    if (warp >= T_) return;
    const float* xrow = g_att + (size_t)warp * D_;
    float acc[E_];
    #pragma unroll
    for (int e=0;e<E_;e++) acc[e]=0.f;
    for (int i = lane; i < D_; i += 32) {
        float x = xrow[i];
        const float* w = Wr + i*E_;
        #pragma unroll
        for (int e=0;e<E_;e++) acc[e] += x * w[e];
    }
    #pragma unroll
    for (int e=0;e<E_;e++)
        #pragma unroll
        for (int o=16;o>0;o>>=1)
            acc[e] += __shfl_xor_sync(0xffffffffu, acc[e], o);
    if (lane == 0) {
        float best = -1e30f; int be = 0;
        #pragma unroll
        for (int e=0;e<E_;e++) {
            float l = acc[e] + br[e];
            acc[e] = l;
            if (l > best) { best = l; be = e; }
        }
        float sm = 0.f;
        #pragma unroll
        for (int e=0;e<E_;e++) sm += expf(acc[e] - best);
        float gate = 1.0f / sm;
        int pos = atomicAdd(&g_cnt[be], 1);
        if (pos < CAP_) {
            g_tokmap[be*CAP_ + pos] = warp;
            g_gate[warp] = gate;
        }
    }
}

__global__ void zero_small() {
    if (threadIdx.x < E_) g_cnt[threadIdx.x] = 0;
}

// ---------------- launch ------------------------------------------------------
extern "C" void kernel_launch(void* const* d_in, const int* in_sizes, int n_in,
                              void* d_out, int out_size) {
    const float* x    = (const float*)d_in[0];
    const float* mask = (const float*)d_in[1];
    const float* Wq   = (const float*)d_in[2];
    const float* bq   = (const float*)d_in[3];
    const float* Wk   = (const float*)d_in[4];
    const float* bk   = (const float*)d_in[5];
    const float* Wv   = (const float*)d_in[6];
    const float* bv   = (const float*)d_in[7];
    const float* Wo   = (const float*)d_in[8];
    const float* bo   = (const float*)d_in[9];
    const float* ln1g = (const float*)d_in[10];
    const float* ln1b = (const float*)d_in[11];
    const float* Wr   = (const float*)d_in[12];
    const float* br   = (const float*)d_in[13];
    const float* W1   = (const float*)d_in[14];
    const float* b1   = (const float*)d_in[15];
    const float* W2   = (const float*)d_in[16];
    const float* b2   = (const float*)d_in[17];
    const float* ln2g = (const float*)d_in[18];
    const float* ln2b = (const float*)d_in[19];
    float* out = (float*)d_out;

    float *p_tmp, *p_att, *p_ffn;
    cudaGetSymbolAddress((void**)&p_tmp, g_tmp);
    cudaGetSymbolAddress((void**)&p_att, g_att);
    cudaGetSymbolAddress((void**)&p_ffn, g_ffn);

    constexpr int SH_G  = 2 * (128*36*4 + 32*136*4);   // 71680
    constexpr int SH_FA = 2 * (64*68*4 + 64*72*4 + 256) + 8*16*68*4;  // 106880
    cudaFuncSetAttribute((const void*)tgemm<0,768,768>,   cudaFuncAttributeMaxDynamicSharedMemorySize, SH_G);
    cudaFuncSetAttribute((const void*)tgemm<3,768,768>,   cudaFuncAttributeMaxDynamicSharedMemorySize, SH_G);
    cudaFuncSetAttribute((const void*)tgemm<4,768,3072>,  cudaFuncAttributeMaxDynamicSharedMemorySize, SH_G);
    cudaFuncSetAttribute((const void*)tgemm<5,3072,768>,  cudaFuncAttributeMaxDynamicSharedMemorySize, SH_G);
    cudaFuncSetAttribute((const void*)fattn, cudaFuncAttributeMaxDynamicSharedMemorySize, SH_FA);

    zero_small<<<1, 32>>>();

    // fused QKV projections (z selects weight/bias)
    tgemm<0,768,768><<<dim3(6,64,3), 128, SH_G>>>(x, Wq, Wk, Wv, bq, bk, bv);

    // fused flash attention -> g_ctx
    fattn<<<dim3(8, 96), 256, SH_FA>>>(mask);

    // att = LN1(x + ctx@Wo + bo)
    tgemm<3,768,768><<<dim3(6,64,1), 128, SH_G>>>(nullptr, Wo, nullptr, nullptr, nullptr, nullptr, nullptr);
    ln_kernel<<<T_, 256>>>(x, p_tmp, bo, ln1g, ln1b, p_att);

    // router + MoE
    router_kernel<<<T_/8, 256>>>(Wr, br);
    tgemm<4,768,3072><<<dim3(FF_/128, (E_*CAP_)/128, 1), 128, SH_G>>>(nullptr, W1, nullptr, nullptr, b1, nullptr, nullptr);
    tgemm<5,3072,768><<<dim3(D_/128, (E_*CAP_)/128, 1), 128, SH_G>>>(nullptr, W2, nullptr, nullptr, b2, nullptr, nullptr);

    // out = LN2(att + ffn)
    ln_kernel<<<T_, 256>>>(p_att, p_ffn, nullptr, ln2g, ln2b, out);
}

// round 10
// speedup vs baseline: 1.1523x; 1.0002x over previous
#include <cuda_runtime.h>
#include <cstdint>
#include <math.h>

#define B_  8
#define S_  1024
#define D_  768
#define H_  12
#define DH_ 64
#define FF_ 3072
#define E_  8
#define CAP_ 2048
#define T_  8192

// ---------------- scratch (device globals) ----------------------------------
__device__ float g_q[B_*H_*S_*DH_];
__device__ float g_k[B_*H_*S_*DH_];
__device__ float g_v[B_*H_*S_*DH_];
__device__ float g_ctx[T_*D_];
__device__ float g_tmp[T_*D_];
__device__ float g_att[T_*D_];
__device__ float g_h[50331648];            // E*CAP*FF
__device__ float g_ffn[T_*D_];
__device__ int   g_cnt[E_];
__device__ int   g_tokmap[E_*CAP_];
__device__ float g_gate[T_];

__device__ __forceinline__ float gelu_f(float x) {
    return 0.5f * x * (1.0f + erff(x * 0.70710678118654752f));
}

__device__ __forceinline__ void cpa16(uint32_t dst, const void* src) {
    asm volatile("cp.async.ca.shared.global [%0], [%1], 16;" :: "r"(dst), "l"(src));
}
__device__ __forceinline__ void cpa_commit() {
    asm volatile("cp.async.commit_group;" ::: "memory");
}
__device__ __forceinline__ void cpa_wait0() {
    asm volatile("cp.async.wait_group 0;" ::: "memory");
}
__device__ __forceinline__ void mma8(float* c, const uint32_t* a, const uint32_t* b) {
    asm volatile(
        "mma.sync.aligned.m16n8k8.row.col.f32.tf32.tf32.f32 "
        "{%0,%1,%2,%3}, {%4,%5,%6,%7}, {%8,%9}, {%0,%1,%2,%3};\n"
        : "+f"(c[0]), "+f"(c[1]), "+f"(c[2]), "+f"(c[3])
        : "r"(a[0]), "r"(a[1]), "r"(a[2]), "r"(a[3]), "r"(b[0]), "r"(b[1]));
}
// ldmatrix.x4 on 32-bit data: returns m16xk8 f32 fragment
__device__ __forceinline__ void ldsm4(uint32_t* r, uint32_t addr) {
    asm volatile("ldmatrix.sync.aligned.m8n8.x4.b16 {%0,%1,%2,%3}, [%4];"
                 : "=r"(r[0]), "=r"(r[1]), "=r"(r[2]), "=r"(r[3]) : "r"(addr));
}

// ================= fused flash attention =====================================
__global__ __launch_bounds__(256) void fattn(const float* __restrict__ mask)
{
    constexpr int LDK = 68, LDV = 72, LDP = 68;
    constexpr int KBYTES = 64 * LDK * 4;
    constexpr int VBYTES = 64 * LDV * 4;
    constexpr int MBYTES = 256;
    constexpr int STAGE  = KBYTES + VBYTES + MBYTES;
    extern __shared__ char smc[];
    float* pS_all = (float*)(smc + 2 * STAGE);

    const int tid = threadIdx.x, wid = tid >> 5, lane = tid & 31;
    const int g = lane >> 2, t = lane & 3;
    const int z = blockIdx.y, mBase = blockIdx.x * 128;
    const int bq = z / H_, hh = z % H_;
    const int m0 = mBase + wid * 16;

    const float* Qp = g_q + (size_t)z * S_ * DH_;
    const float* Kp = g_k + (size_t)z * S_ * DH_;
    const float* Vp = g_v + (size_t)z * S_ * DH_;

    // Q fragments pre-scaled by 1/8 (power of 2 -> bit-exact vs scaling scores)
    uint32_t qf[8][4];
    #pragma unroll
    for (int kb = 0; kb < 8; kb++) {
        qf[kb][0] = __float_as_uint(0.125f * Qp[(m0 + g)     * DH_ + kb*8 + t]);
        qf[kb][1] = __float_as_uint(0.125f * Qp[(m0 + g + 8) * DH_ + kb*8 + t]);
        qf[kb][2] = __float_as_uint(0.125f * Qp[(m0 + g)     * DH_ + kb*8 + t + 4]);
        qf[kb][3] = __float_as_uint(0.125f * Qp[(m0 + g + 8) * DH_ + kb*8 + t + 4]);
    }

    float oacc[8][4];
    #pragma unroll
    for (int nt = 0; nt < 8; nt++)
        #pragma unroll
        for (int q = 0; q < 4; q++) oacc[nt][q] = 0.f;
    float mrow0 = -1e30f, mrow1 = -1e30f, lrow0 = 0.f, lrow1 = 0.f;

    uint32_t sU = (uint32_t)__cvta_generic_to_shared(smc);
    const uint32_t lmRow = (lane & 15);
    const uint32_t lmHalf = (lane >> 4) << 4;
    const uint32_t kOff = lmRow * (LDK*4) + lmHalf;
    const uint32_t pU   = sU + 2*STAGE + wid * 16 * (LDP*4);
    const uint32_t pOff = pU + lmRow * (LDP*4) + lmHalf;

    auto issue = [&](int kt) {
        const int stg = kt & 1;
        const uint32_t base = sU + stg * STAGE;
        #pragma unroll
        for (int i = 0; i < 4; i++) {
            int idx = tid + i * 256;
            int row = idx >> 4, c4 = idx & 15;
            cpa16(base + row * (LDK*4) + c4 * 16,
                  Kp + (size_t)(kt*64 + row) * DH_ + c4 * 4);
        }
        #pragma unroll
        for (int i = 0; i < 4; i++) {
            int idx = tid + i * 256;
            int row = idx >> 4, c4 = idx & 15;
            cpa16(base + KBYTES + row * (LDV*4) + c4 * 16,
                  Vp + (size_t)(kt*64 + row) * DH_ + c4 * 4);
        }
        if (tid < 16)
            cpa16(base + KBYTES + VBYTES + tid * 16, mask + bq * S_ + kt*64 + tid * 4);
        cpa_commit();
    };

    float* pS = pS_all + wid * 16 * LDP;

    issue(0);
    for (int kt = 0; kt < 16; kt++) {
        cpa_wait0();
        __syncthreads();
        if (kt + 1 < 16) issue(kt + 1);

        const int stg = kt & 1;
        const uint32_t kBase = sU + stg * STAGE;
        const float* vS = (const float*)(smc + stg * STAGE + KBYTES);
        const float* mS = (const float*)(smc + stg * STAGE + KBYTES + VBYTES);

        float sacc[8][4];
        #pragma unroll
        for (int nt = 0; nt < 8; nt++)
            #pragma unroll
            for (int q = 0; q < 4; q++) sacc[nt][q] = 0.f;
        #pragma unroll
        for (int ks = 0; ks < 8; ks++) {
            #pragma unroll
            for (int p = 0; p < 4; p++) {
                uint32_t r[4];
                ldsm4(r, kBase + kOff + p * 16 * (LDK*4) + ks * 32);
                uint32_t b0[2] = { r[0], r[2] };
                uint32_t b1[2] = { r[1], r[3] };
                mma8(sacc[2*p],   qf[ks], b0);
                mma8(sacc[2*p+1], qf[ks], b1);
            }
        }

        float mx0 = -1e30f, mx1 = -1e30f;
        #pragma unroll
        for (int nt = 0; nt < 8; nt++) {
            float mk0 = mS[nt*8 + 2*t], mk1 = mS[nt*8 + 2*t + 1];
            sacc[nt][0] += mk0;
            sacc[nt][1] += mk1;
            sacc[nt][2] += mk0;
            sacc[nt][3] += mk1;
            mx0 = fmaxf(mx0, fmaxf(sacc[nt][0], sacc[nt][1]));
            mx1 = fmaxf(mx1, fmaxf(sacc[nt][2], sacc[nt][3]));
        }
        mx0 = fmaxf(mx0, __shfl_xor_sync(0xffffffffu, mx0, 1));
        mx0 = fmaxf(mx0, __shfl_xor_sync(0xffffffffu, mx0, 2));
        mx1 = fmaxf(mx1, __shfl_xor_sync(0xffffffffu, mx1, 1));
        mx1 = fmaxf(mx1, __shfl_xor_sync(0xffffffffu, mx1, 2));

        float mn0 = fmaxf(mrow0, mx0), mn1 = fmaxf(mrow1, mx1);
        float a0 = __expf(mrow0 - mn0), a1 = __expf(mrow1 - mn1);
        mrow0 = mn0; mrow1 = mn1;

        float s0 = 0.f, s1 = 0.f;
        #pragma unroll
        for (int nt = 0; nt < 8; nt++) {
            float p0 = __expf(sacc[nt][0] - mn0);
            float p1 = __expf(sacc[nt][1] - mn0);
            float p2 = __expf(sacc[nt][2] - mn1);
            float p3 = __expf(sacc[nt][3] - mn1);
            s0 += p0 + p1; s1 += p2 + p3;
            *(float2*)(pS + g * LDP + nt*8 + 2*t)       = make_float2(p0, p1);
            *(float2*)(pS + (g + 8) * LDP + nt*8 + 2*t) = make_float2(p2, p3);
        }
        s0 += __shfl_xor_sync(0xffffffffu, s0, 1);
        s0 += __shfl_xor_sync(0xffffffffu, s0, 2);
        s1 += __shfl_xor_sync(0xffffffffu, s1, 1);
        s1 += __shfl_xor_sync(0xffffffffu, s1, 2);
        lrow0 = lrow0 * a0 + s0;
        lrow1 = lrow1 * a1 + s1;

        #pragma unroll
        for (int nt = 0; nt < 8; nt++) {
            oacc[nt][0] *= a0; oacc[nt][1] *= a0;
            oacc[nt][2] *= a1; oacc[nt][3] *= a1;
        }
        __syncwarp();

        // ---- P @ V with B-fragment double buffering ----
        uint32_t bv[2][8][2];
        #pragma unroll
        for (int nt = 0; nt < 8; nt++) {
            bv[0][nt][0] = __float_as_uint(vS[t       * LDV + nt*8 + g]);
            bv[0][nt][1] = __float_as_uint(vS[(t + 4) * LDV + nt*8 + g]);
        }
        #pragma unroll
        for (int kb = 0; kb < 8; kb++) {
            const int cur = kb & 1;
            if (kb < 7) {
                #pragma unroll
                for (int nt = 0; nt < 8; nt++) {
                    bv[cur^1][nt][0] = __float_as_uint(vS[((kb+1)*8 + t)     * LDV + nt*8 + g]);
                    bv[cur^1][nt][1] = __float_as_uint(vS[((kb+1)*8 + t + 4) * LDV + nt*8 + g]);
                }
            }
            uint32_t a[4];
            ldsm4(a, pOff + kb * 32);
            #pragma unroll
            for (int nt = 0; nt < 8; nt++)
                mma8(oacc[nt], a, bv[cur][nt]);
        }
    }

    float inv0 = 1.0f / lrow0, inv1 = 1.0f / lrow1;
    int mr0 = m0 + g, mr1 = m0 + g + 8;
    #pragma unroll
    for (int nt = 0; nt < 8; nt++) {
        int col = hh * DH_ + nt*8 + 2*t;
        *(float2*)(g_ctx + ((size_t)(bq * S_ + mr0)) * D_ + col) =
            make_float2(oacc[nt][0] * inv0, oacc[nt][1] * inv0);
        *(float2*)(g_ctx + ((size_t)(bq * S_ + mr1)) * D_ + col) =
            make_float2(oacc[nt][2] * inv1, oacc[nt][3] * inv1);
    }
}

// ---------------- tf32 mma.sync GEMM: 128x128 tile, 128 threads --------------
// 4 warps 2x2; warp tile 64x64; A via ldmatrix.x4; B fragments double-buffered.
template<int MODE, int KK, int LDBG>
__global__ __launch_bounds__(128, 2)
void tgemm(const float* __restrict__ Ag, const float* __restrict__ Bg,
           const float* __restrict__ Bg2, const float* __restrict__ Bg3,
           const float* __restrict__ bias, const float* __restrict__ bias2,
           const float* __restrict__ bias3)
{
    constexpr int BN     = 128;
    constexpr int NC     = KK / 32;
    constexpr int NT     = 8;
    constexpr int LDA    = 36;
    constexpr int LDBN   = BN + 8;             // 136
    constexpr int ABYTES = 128 * LDA * 4;      // 18432
    constexpr int BBYTES = 32 * LDBN * 4;      // 17408
    constexpr int STAGE  = ABYTES + BBYTES;    // 35840
    constexpr int CS     = BN + 4;             // 132
    constexpr int BF4    = BN / 4;             // 32

    extern __shared__ char smc[];
    __shared__ int rIdx[128];
    __shared__ int s_cnt;

    const int tid = threadIdx.x, wid = tid >> 5, lane = tid & 31;
    const int wr = wid >> 1, wc = wid & 1;
    const int g = lane >> 2, t = lane & 3;
    const int mBase = blockIdx.y * 128, nBase = blockIdx.x * BN, z = blockIdx.z;
    const int e = (MODE >= 4) ? (mBase >> 11) : 0;

    if (MODE == 4 || MODE == 5) {
        if (tid == 0) s_cnt = g_cnt[e];
        __syncthreads();
        if ((mBase & (CAP_-1)) >= s_cnt) return;
    }

    const float* A; const float* Bp; const float* biasp = bias;
    if      (MODE == 0) { A = Ag; Bp = (z==0)?Bg:((z==1)?Bg2:Bg3);
                          biasp = (z==0)?bias:((z==1)?bias2:bias3); }
    else if (MODE == 3) { A = g_ctx;  Bp = Bg; }
    else if (MODE == 4) { A = g_att;  Bp = Bg + (size_t)e * D_ * FF_; }
    else                { A = g_h;    Bp = Bg + (size_t)e * FF_ * D_; }

    {
        int m = mBase + tid, r = m;
        if (MODE == 4) {
            int pos = m & (CAP_-1);
            r = (pos < s_cnt) ? g_tokmap[e*CAP_ + pos] : 0;
        }
        rIdx[tid] = r;
    }
    __syncthreads();

    uint32_t sU = (uint32_t)__cvta_generic_to_shared(smc);
    const uint32_t aOff = (uint32_t)((wr*64 + (lane & 15)) * (LDA*4)) + ((lane >> 4) << 4);

    auto issue = [&](int cix) {
        const int stg = cix & 1;
        const int k0 = cix * 32;
        const uint32_t aB = sU + stg * STAGE;
        #pragma unroll
        for (int i = 0; i < 8; i++) {
            int idx = tid + i * 128;
            int row = idx >> 3, c4 = idx & 7;
            cpa16(aB + row * (LDA*4) + c4 * 16,
                  A + (size_t)rIdx[row] * KK + k0 + c4 * 4);
        }
        const uint32_t bB = aB + ABYTES;
        #pragma unroll
        for (int i = 0; i < 8; i++) {
            int idx = tid + i * 128;
            int row = idx >> 5, c4 = idx & 31;
            cpa16(bB + row * (LDBN*4) + c4 * 16,
                  Bp + (size_t)(k0 + row) * LDBG + nBase + c4 * 4);
        }
        cpa_commit();
    };

    float acc[4][NT][4];
    #pragma unroll
    for (int i = 0; i < 4; i++)
        #pragma unroll
        for (int j = 0; j < NT; j++)
            #pragma unroll
            for (int q = 0; q < 4; q++) acc[i][j][q] = 0.f;

    issue(0);
    for (int c = 0; c < NC; c++) {
        cpa_wait0();
        __syncthreads();
        if (c + 1 < NC) issue(c + 1);

        const int stg = c & 1;
        const uint32_t aBase = sU + stg * STAGE + aOff;
        const uint32_t* bS = (const uint32_t*)(smc + stg * STAGE + ABYTES);

        // B fragments double-buffered one ks-step ahead
        uint32_t bfr[2][NT][2];
        #pragma unroll
        for (int nt = 0; nt < NT; nt++) {
            int n = wc*64 + nt*8 + g;
            bfr[0][nt][0] = bS[t*LDBN + n];
            bfr[0][nt][1] = bS[(t+4)*LDBN + n];
        }
        #pragma unroll
        for (int ks = 0; ks < 4; ks++) {
            const int cur = ks & 1;
            if (ks < 3) {
                #pragma unroll
                for (int nt = 0; nt < NT; nt++) {
                    int n = wc*64 + nt*8 + g;
                    int k = (ks+1)*8 + t;
                    bfr[cur^1][nt][0] = bS[k*LDBN + n];
                    bfr[cur^1][nt][1] = bS[(k+4)*LDBN + n];
                }
            }
            uint32_t a[4][4];
            #pragma unroll
            for (int mt = 0; mt < 4; mt++)
                ldsm4(a[mt], aBase + mt * 16 * (LDA*4) + ks * 32);
            #pragma unroll
            for (int mt = 0; mt < 4; mt++)
                #pragma unroll
                for (int nt = 0; nt < NT; nt++)
                    mma8(acc[mt][nt], a[mt], bfr[cur][nt]);
        }
    }
    __syncthreads();

    // ---------------- epilogue ----------------
    float* cSf = (float*)smc;
    #pragma unroll
    for (int mt = 0; mt < 4; mt++) {
        #pragma unroll
        for (int nt = 0; nt < NT; nt++) {
            int r = wr*64 + mt*16 + g;
            int n = wc*64 + nt*8 + 2*t;
            *(float2*)(cSf + r*CS + n)     = make_float2(acc[mt][nt][0], acc[mt][nt][1]);
            *(float2*)(cSf + (r+8)*CS + n) = make_float2(acc[mt][nt][2], acc[mt][nt][3]);
        }
    }
    __syncthreads();

    constexpr int IT = (128 * BF4) / 128;
    #pragma unroll
    for (int it = 0; it < IT; it++) {
        int idx = it * 128 + tid;
        int row = idx / BF4, q = idx % BF4;
        float4 v = *(const float4*)(cSf + row*CS + q*4);
        int m  = mBase + row;
        int n0 = nBase + q*4;

        if (MODE == 0) {
            v.x += biasp[n0]; v.y += biasp[n0+1]; v.z += biasp[n0+2]; v.w += biasp[n0+3];
            int b = m >> 10, srow = m & 1023, hh = n0 >> 6, dh = n0 & 63;
            float* dst = (z == 0) ? g_q : ((z == 1) ? g_k : g_v);
            *(float4*)(dst + (((size_t)(b*H_ + hh)) * S_ + srow) * DH_ + dh) = v;
        } else if (MODE == 3) {
            *(float4*)(g_tmp + (size_t)m * D_ + n0) = v;
        } else if (MODE == 4) {
            int pos = m & (CAP_-1);
            if (pos < s_cnt) {
                const float4 bb = *(const float4*)(bias + (size_t)e*FF_ + n0);
                *(float4*)(g_h + (size_t)m * FF_ + n0) =
                    make_float4(gelu_f(v.x+bb.x), gelu_f(v.y+bb.y),
                                gelu_f(v.z+bb.z), gelu_f(v.w+bb.w));
            }
        } else {
            int pos = m & (CAP_-1);
            if (pos < s_cnt) {
                int tok = g_tokmap[e*CAP_ + pos];
                float gsc = g_gate[tok];
                const float4 bb = *(const float4*)(bias + (size_t)e*D_ + n0);
                *(float4*)(g_ffn + (size_t)tok * D_ + n0) =
                    make_float4((v.x+bb.x)*gsc, (v.y+bb.y)*gsc,
                                (v.z+bb.z)*gsc, (v.w+bb.w)*gsc);
            }
        }
    }
}

// ---------------- layernorm --------------------------------------------------
__global__ __launch_bounds__(256) void ln_kernel(
        const float* __restrict__ a, const float* __restrict__ bsum,
        const float* __restrict__ bias,
        const float* __restrict__ g, const float* __restrict__ beta,
        float* __restrict__ out)
{
    __shared__ float red[256];
    const int t = blockIdx.x, tid = threadIdx.x;
    const float* ap = a    + (size_t)t * D_;
    const float* bp = bsum + (size_t)t * D_;
    float v[3]; float s = 0.f;
    #pragma unroll
    for (int j=0;j<3;j++) {
        int i = tid + j*256;
        float x = ap[i] + bp[i];
        if (bias) x += bias[i];
        v[j] = x; s += x;
    }
    red[tid]=s; __syncthreads();
    for (int st=128; st>0; st>>=1) { if (tid<st) red[tid]+=red[tid+st]; __syncthreads(); }
    float mu = red[0] * (1.0f/768.0f);
    __syncthreads();
    float q = 0.f;
    #pragma unroll
    for (int j=0;j<3;j++) { float d = v[j]-mu; q += d*d; }
    red[tid]=q; __syncthreads();
    for (int st=128; st>0; st>>=1) { if (tid<st) red[tid]+=red[tid+st]; __syncthreads(); }
    float inv = rsqrtf(red[0]*(1.0f/768.0f) + 1e-12f);
    #pragma unroll
    for (int j=0;j<3;j++) {
        int i = tid + j*256;
        out[(size_t)t*D_ + i] = (v[j]-mu)*inv*g[i] + beta[i];
    }
}

// ---------------- router ------------------------------------------------------
__global__ __launch_bounds__(256) void router_kernel(
        const float* __restrict__ Wr, const float* __restrict__ br)
{
    int warp = (blockIdx.x * blockDim.x + threadIdx.x) >> 5;
    int lane = threadIdx.x & 31;
    if (warp >= T_) return;
    const float* xrow = g_att + (size_t)warp * D_;
    float acc[E_];
    #pragma unroll
    for (int e=0;e<E_;e++) acc[e]=0.f;
    for (int i = lane; i < D_; i += 32) {
        float x = xrow[i];
        const float* w = Wr + i*E_;
        #pragma unroll
        for (int e=0;e<E_;e++) acc[e] += x * w[e];
    }
    #pragma unroll
    for (int e=0;e<E_;e++)
        #pragma unroll
        for (int o=16;o>0;o>>=1)
            acc[e] += __shfl_xor_sync(0xffffffffu, acc[e], o);
    if (lane == 0) {
        float best = -1e30f; int be = 0;
        #pragma unroll
        for (int e=0;e<E_;e++) {
            float l = acc[e] + br[e];
            acc[e] = l;
            if (l > best) { best = l; be = e; }
        }
        float sm = 0.f;
        #pragma unroll
        for (int e=0;e<E_;e++) sm += expf(acc[e] - best);
        float gate = 1.0f / sm;
        int pos = atomicAdd(&g_cnt[be], 1);
        if (pos < CAP_) {
            g_tokmap[be*CAP_ + pos] = warp;
            g_gate[warp] = gate;
        }
    }
}

__global__ void zero_small() {
    if (threadIdx.x < E_) g_cnt[threadIdx.x] = 0;
}

// ---------------- launch ------------------------------------------------------
extern "C" void kernel_launch(void* const* d_in, const int* in_sizes, int n_in,
                              void* d_out, int out_size) {
    const float* x    = (const float*)d_in[0];
    const float* mask = (const float*)d_in[1];
    const float* Wq   = (const float*)d_in[2];
    const float* bq   = (const float*)d_in[3];
    const float* Wk   = (const float*)d_in[4];
    const float* bk   = (const float*)d_in[5];
    const float* Wv   = (const float*)d_in[6];
    const float* bv   = (const float*)d_in[7];
    const float* Wo   = (const float*)d_in[8];
    const float* bo   = (const float*)d_in[9];
    const float* ln1g = (const float*)d_in[10];
    const float* ln1b = (const float*)d_in[11];
    const float* Wr   = (const float*)d_in[12];
    const float* br   = (const float*)d_in[13];
    const float* W1   = (const float*)d_in[14];
    const float* b1   = (const float*)d_in[15];
    const float* W2   = (const float*)d_in[16];
    const float* b2   = (const float*)d_in[17];
    const float* ln2g = (const float*)d_in[18];
    const float* ln2b = (const float*)d_in[19];
    float* out = (float*)d_out;

    float *p_tmp, *p_att, *p_ffn;
    cudaGetSymbolAddress((void**)&p_tmp, g_tmp);
    cudaGetSymbolAddress((void**)&p_att, g_att);
    cudaGetSymbolAddress((void**)&p_ffn, g_ffn);

    constexpr int SH_G  = 2 * (128*36*4 + 32*136*4);   // 71680
    constexpr int SH_FA = 2 * (64*68*4 + 64*72*4 + 256) + 8*16*68*4;  // 106880
    cudaFuncSetAttribute((const void*)tgemm<0,768,768>,   cudaFuncAttributeMaxDynamicSharedMemorySize, SH_G);
    cudaFuncSetAttribute((const void*)tgemm<3,768,768>,   cudaFuncAttributeMaxDynamicSharedMemorySize, SH_G);
    cudaFuncSetAttribute((const void*)tgemm<4,768,3072>,  cudaFuncAttributeMaxDynamicSharedMemorySize, SH_G);
    cudaFuncSetAttribute((const void*)tgemm<5,3072,768>,  cudaFuncAttributeMaxDynamicSharedMemorySize, SH_G);
    cudaFuncSetAttribute((const void*)fattn, cudaFuncAttributeMaxDynamicSharedMemorySize, SH_FA);

    zero_small<<<1, 32>>>();

    // fused QKV projections (z selects weight/bias)
    tgemm<0,768,768><<<dim3(6,64,3), 128, SH_G>>>(x, Wq, Wk, Wv, bq, bk, bv);

    // fused flash attention -> g_ctx
    fattn<<<dim3(8, 96), 256, SH_FA>>>(mask);

    // att = LN1(x + ctx@Wo + bo)
    tgemm<3,768,768><<<dim3(6,64,1), 128, SH_G>>>(nullptr, Wo, nullptr, nullptr, nullptr, nullptr, nullptr);
    ln_kernel<<<T_, 256>>>(x, p_tmp, bo, ln1g, ln1b, p_att);

    // router + MoE
    router_kernel<<<T_/8, 256>>>(Wr, br);
    tgemm<4,768,3072><<<dim3(FF_/128, (E_*CAP_)/128, 1), 128, SH_G>>>(nullptr, W1, nullptr, nullptr, b1, nullptr, nullptr);
    tgemm<5,3072,768><<<dim3(D_/128, (E_*CAP_)/128, 1), 128, SH_G>>>(nullptr, W2, nullptr, nullptr, b2, nullptr, nullptr);

    // out = LN2(att + ffn)
    ln_kernel<<<T_, 256>>>(p_att, p_ffn, nullptr, ln2g, ln2b, out);
}

// round 11
// speedup vs baseline: 1.4452x; 1.2542x over previous
#include <cuda_runtime.h>
#include <cuda_fp16.h>
#include <cstdint>
#include <math.h>

#define B_  8
#define S_  1024
#define D_  768
#define H_  12
#define DH_ 64
#define FF_ 3072
#define E_  8
#define CAP_ 2048
#define T_  8192

// ---------------- scratch (device globals) ----------------------------------
__device__ float  g_q[B_*H_*S_*DH_];
__device__ float  g_k[B_*H_*S_*DH_];
__device__ float  g_v[B_*H_*S_*DH_];
__device__ float  g_tmp[T_*D_];
__device__ float  g_att[T_*D_];
__device__ float  g_ffn[T_*D_];
__device__ int    g_cnt[E_];
__device__ int    g_tokmap[E_*CAP_];
__device__ float  g_gate[T_];
// fp16 operand copies
__device__ __half g_xh[T_*D_];
__device__ __half g_wqh[D_*D_];
__device__ __half g_wkh[D_*D_];
__device__ __half g_wvh[D_*D_];
__device__ __half g_woh[D_*D_];
__device__ __half g_w1h[E_*D_*FF_];
__device__ __half g_w2h[E_*FF_*D_];
__device__ __half g_atth[T_*D_];
__device__ __half g_ctxh[T_*D_];
__device__ __half g_hh[50331648];          // E*CAP*FF fp16

__device__ __forceinline__ float gelu_f(float x) {
    return 0.5f * x * (1.0f + erff(x * 0.70710678118654752f));
}

__device__ __forceinline__ void cpa16(uint32_t dst, const void* src) {
    asm volatile("cp.async.ca.shared.global [%0], [%1], 16;" :: "r"(dst), "l"(src));
}
__device__ __forceinline__ void cpa_commit() {
    asm volatile("cp.async.commit_group;" ::: "memory");
}
__device__ __forceinline__ void cpa_wait0() {
    asm volatile("cp.async.wait_group 0;" ::: "memory");
}
__device__ __forceinline__ void mma8(float* c, const uint32_t* a, const uint32_t* b) {
    asm volatile(
        "mma.sync.aligned.m16n8k8.row.col.f32.tf32.tf32.f32 "
        "{%0,%1,%2,%3}, {%4,%5,%6,%7}, {%8,%9}, {%0,%1,%2,%3};\n"
        : "+f"(c[0]), "+f"(c[1]), "+f"(c[2]), "+f"(c[3])
        : "r"(a[0]), "r"(a[1]), "r"(a[2]), "r"(a[3]), "r"(b[0]), "r"(b[1]));
}
// fp16 m16n8k16, fp32 accumulate
__device__ __forceinline__ void mma16(float* c, const uint32_t* a, const uint32_t* b) {
    asm volatile(
        "mma.sync.aligned.m16n8k16.row.col.f32.f16.f16.f32 "
        "{%0,%1,%2,%3}, {%4,%5,%6,%7}, {%8,%9}, {%0,%1,%2,%3};\n"
        : "+f"(c[0]), "+f"(c[1]), "+f"(c[2]), "+f"(c[3])
        : "r"(a[0]), "r"(a[1]), "r"(a[2]), "r"(a[3]), "r"(b[0]), "r"(b[1]));
}
__device__ __forceinline__ void ldsm4(uint32_t* r, uint32_t addr) {
    asm volatile("ldmatrix.sync.aligned.m8n8.x4.b16 {%0,%1,%2,%3}, [%4];"
                 : "=r"(r[0]), "=r"(r[1]), "=r"(r[2]), "=r"(r[3]) : "r"(addr));
}
__device__ __forceinline__ void ldsm4t(uint32_t* r, uint32_t addr) {
    asm volatile("ldmatrix.sync.aligned.m8n8.x4.trans.shared.b16 {%0,%1,%2,%3}, [%4];"
                 : "=r"(r[0]), "=r"(r[1]), "=r"(r[2]), "=r"(r[3]) : "r"(addr));
}

// ---------------- fp32 -> fp16 conversion ------------------------------------
__global__ void f2h(const float* __restrict__ s, __half* __restrict__ d, int n4) {
    int i = blockIdx.x * blockDim.x + threadIdx.x;
    if (i >= n4) return;
    float4 v = ((const float4*)s)[i];
    __half2 h0 = __floats2half2_rn(v.x, v.y);
    __half2 h1 = __floats2half2_rn(v.z, v.w);
    ((__half2*)d)[i*2]   = h0;
    ((__half2*)d)[i*2+1] = h1;
}

// ================= fused flash attention (tf32 core, unchanged) ==============
__global__ __launch_bounds__(256) void fattn(const float* __restrict__ mask)
{
    constexpr int LDK = 68, LDV = 72, LDP = 68;
    constexpr int KBYTES = 64 * LDK * 4;
    constexpr int VBYTES = 64 * LDV * 4;
    constexpr int MBYTES = 256;
    constexpr int STAGE  = KBYTES + VBYTES + MBYTES;
    extern __shared__ char smc[];
    float* pS_all = (float*)(smc + 2 * STAGE);

    const int tid = threadIdx.x, wid = tid >> 5, lane = tid & 31;
    const int g = lane >> 2, t = lane & 3;
    const int z = blockIdx.y, mBase = blockIdx.x * 128;
    const int bq = z / H_, hh = z % H_;
    const int m0 = mBase + wid * 16;

    const float* Qp = g_q + (size_t)z * S_ * DH_;
    const float* Kp = g_k + (size_t)z * S_ * DH_;
    const float* Vp = g_v + (size_t)z * S_ * DH_;

    uint32_t qf[8][4];
    #pragma unroll
    for (int kb = 0; kb < 8; kb++) {
        qf[kb][0] = __float_as_uint(0.125f * Qp[(m0 + g)     * DH_ + kb*8 + t]);
        qf[kb][1] = __float_as_uint(0.125f * Qp[(m0 + g + 8) * DH_ + kb*8 + t]);
        qf[kb][2] = __float_as_uint(0.125f * Qp[(m0 + g)     * DH_ + kb*8 + t + 4]);
        qf[kb][3] = __float_as_uint(0.125f * Qp[(m0 + g + 8) * DH_ + kb*8 + t + 4]);
    }

    float oacc[8][4];
    #pragma unroll
    for (int nt = 0; nt < 8; nt++)
        #pragma unroll
        for (int q = 0; q < 4; q++) oacc[nt][q] = 0.f;
    float mrow0 = -1e30f, mrow1 = -1e30f, lrow0 = 0.f, lrow1 = 0.f;

    uint32_t sU = (uint32_t)__cvta_generic_to_shared(smc);
    const uint32_t lmRow = (lane & 15);
    const uint32_t lmHalf = (lane >> 4) << 4;
    const uint32_t kOff = lmRow * (LDK*4) + lmHalf;
    const uint32_t pU   = sU + 2*STAGE + wid * 16 * (LDP*4);
    const uint32_t pOff = pU + lmRow * (LDP*4) + lmHalf;

    auto issue = [&](int kt) {
        const int stg = kt & 1;
        const uint32_t base = sU + stg * STAGE;
        #pragma unroll
        for (int i = 0; i < 4; i++) {
            int idx = tid + i * 256;
            int row = idx >> 4, c4 = idx & 15;
            cpa16(base + row * (LDK*4) + c4 * 16,
                  Kp + (size_t)(kt*64 + row) * DH_ + c4 * 4);
        }
        #pragma unroll
        for (int i = 0; i < 4; i++) {
            int idx = tid + i * 256;
            int row = idx >> 4, c4 = idx & 15;
            cpa16(base + KBYTES + row * (LDV*4) + c4 * 16,
                  Vp + (size_t)(kt*64 + row) * DH_ + c4 * 4);
        }
        if (tid < 16)
            cpa16(base + KBYTES + VBYTES + tid * 16, mask + bq * S_ + kt*64 + tid * 4);
        cpa_commit();
    };

    float* pS = pS_all + wid * 16 * LDP;

    issue(0);
    for (int kt = 0; kt < 16; kt++) {
        cpa_wait0();
        __syncthreads();
        if (kt + 1 < 16) issue(kt + 1);

        const int stg = kt & 1;
        const uint32_t kBase = sU + stg * STAGE;
        const float* vS = (const float*)(smc + stg * STAGE + KBYTES);
        const float* mS = (const float*)(smc + stg * STAGE + KBYTES + VBYTES);

        float sacc[8][4];
        #pragma unroll
        for (int nt = 0; nt < 8; nt++)
            #pragma unroll
            for (int q = 0; q < 4; q++) sacc[nt][q] = 0.f;
        #pragma unroll
        for (int ks = 0; ks < 8; ks++) {
            #pragma unroll
            for (int p = 0; p < 4; p++) {
                uint32_t r[4];
                ldsm4(r, kBase + kOff + p * 16 * (LDK*4) + ks * 32);
                uint32_t b0[2] = { r[0], r[2] };
                uint32_t b1[2] = { r[1], r[3] };
                mma8(sacc[2*p],   qf[ks], b0);
                mma8(sacc[2*p+1], qf[ks], b1);
            }
        }

        float mx0 = -1e30f, mx1 = -1e30f;
        #pragma unroll
        for (int nt = 0; nt < 8; nt++) {
            float mk0 = mS[nt*8 + 2*t], mk1 = mS[nt*8 + 2*t + 1];
            sacc[nt][0] += mk0;
            sacc[nt][1] += mk1;
            sacc[nt][2] += mk0;
            sacc[nt][3] += mk1;
            mx0 = fmaxf(mx0, fmaxf(sacc[nt][0], sacc[nt][1]));
            mx1 = fmaxf(mx1, fmaxf(sacc[nt][2], sacc[nt][3]));
        }
        mx0 = fmaxf(mx0, __shfl_xor_sync(0xffffffffu, mx0, 1));
        mx0 = fmaxf(mx0, __shfl_xor_sync(0xffffffffu, mx0, 2));
        mx1 = fmaxf(mx1, __shfl_xor_sync(0xffffffffu, mx1, 1));
        mx1 = fmaxf(mx1, __shfl_xor_sync(0xffffffffu, mx1, 2));

        float mn0 = fmaxf(mrow0, mx0), mn1 = fmaxf(mrow1, mx1);
        float a0 = __expf(mrow0 - mn0), a1 = __expf(mrow1 - mn1);
        mrow0 = mn0; mrow1 = mn1;

        float s0 = 0.f, s1 = 0.f;
        #pragma unroll
        for (int nt = 0; nt < 8; nt++) {
            float p0 = __expf(sacc[nt][0] - mn0);
            float p1 = __expf(sacc[nt][1] - mn0);
            float p2 = __expf(sacc[nt][2] - mn1);
            float p3 = __expf(sacc[nt][3] - mn1);
            s0 += p0 + p1; s1 += p2 + p3;
            *(float2*)(pS + g * LDP + nt*8 + 2*t)       = make_float2(p0, p1);
            *(float2*)(pS + (g + 8) * LDP + nt*8 + 2*t) = make_float2(p2, p3);
        }
        s0 += __shfl_xor_sync(0xffffffffu, s0, 1);
        s0 += __shfl_xor_sync(0xffffffffu, s0, 2);
        s1 += __shfl_xor_sync(0xffffffffu, s1, 1);
        s1 += __shfl_xor_sync(0xffffffffu, s1, 2);
        lrow0 = lrow0 * a0 + s0;
        lrow1 = lrow1 * a1 + s1;

        #pragma unroll
        for (int nt = 0; nt < 8; nt++) {
            oacc[nt][0] *= a0; oacc[nt][1] *= a0;
            oacc[nt][2] *= a1; oacc[nt][3] *= a1;
        }
        __syncwarp();

        #pragma unroll
        for (int kb = 0; kb < 8; kb++) {
            uint32_t a[4];
            ldsm4(a, pOff + kb * 32);
            #pragma unroll
            for (int nt = 0; nt < 8; nt++) {
                uint32_t b[2];
                b[0] = __float_as_uint(vS[(kb*8 + t)     * LDV + nt*8 + g]);
                b[1] = __float_as_uint(vS[(kb*8 + t + 4) * LDV + nt*8 + g]);
                mma8(oacc[nt], a, b);
            }
        }
    }

    float inv0 = 1.0f / lrow0, inv1 = 1.0f / lrow1;
    int mr0 = m0 + g, mr1 = m0 + g + 8;
    #pragma unroll
    for (int nt = 0; nt < 8; nt++) {
        int col = hh * DH_ + nt*8 + 2*t;
        *(__half2*)(g_ctxh + ((size_t)(bq * S_ + mr0)) * D_ + col) =
            __floats2half2_rn(oacc[nt][0] * inv0, oacc[nt][1] * inv0);
        *(__half2*)(g_ctxh + ((size_t)(bq * S_ + mr1)) * D_ + col) =
            __floats2half2_rn(oacc[nt][2] * inv1, oacc[nt][3] * inv1);
    }
}

// ---------------- fp16 mma.sync GEMM: 128x128 tile, 128 threads --------------
// 4 warps 2x2; warp tile 64x64; m16n8k16; A via ldmatrix, B via ldmatrix.trans.
// A[M][KK] k-major fp16 (opt. gathered). B[k][n] n-major fp16, row stride LDBG (halves).
// MODE 0: QKV proj (z selects W/b), headed fp32 scatter to q/k/v
// MODE 3: ctxh @ Wo -> g_tmp (fp32)
// MODE 4: gather(atth) @ W1[e] + b1 -> gelu -> g_hh (fp16)
// MODE 5: g_hh @ W2[e] + b2, * gate, scatter -> g_ffn (fp32)
template<int MODE, int KK, int LDBG>
__global__ __launch_bounds__(128, 2)
void tgemm(const __half* __restrict__ Ag, const __half* __restrict__ Bg,
           const __half* __restrict__ Bg2, const __half* __restrict__ Bg3,
           const float* __restrict__ bias, const float* __restrict__ bias2,
           const float* __restrict__ bias3)
{
    constexpr int BN     = 128;
    constexpr int NC     = KK / 32;            // 32-halves chunks
    constexpr int NT     = 8;
    constexpr int LDA_H  = 40;                 // halves; row = 80B
    constexpr int LDB_H  = 136;                // halves; row = 272B
    constexpr int ABYTES = 128 * LDA_H * 2;    // 10240
    constexpr int BBYTES = 32 * LDB_H * 2;     // 8704
    constexpr int STAGE  = ABYTES + BBYTES;    // 18944
    constexpr int CS     = BN + 4;             // 132 (fp32 epilogue stride)
    constexpr int BF4    = BN / 4;             // 32

    extern __shared__ char smc[];
    __shared__ int rIdx[128];
    __shared__ int s_cnt;

    const int tid = threadIdx.x, wid = tid >> 5, lane = tid & 31;
    const int wr = wid >> 1, wc = wid & 1;
    const int g = lane >> 2, t = lane & 3;
    const int mBase = blockIdx.y * 128, nBase = blockIdx.x * BN, z = blockIdx.z;
    const int e = (MODE >= 4) ? (mBase >> 11) : 0;

    if (MODE == 4 || MODE == 5) {
        if (tid == 0) s_cnt = g_cnt[e];
        __syncthreads();
        if ((mBase & (CAP_-1)) >= s_cnt) return;
    }

    const __half* A; const __half* Bp; const float* biasp = bias;
    if      (MODE == 0) { A = Ag; Bp = (z==0)?Bg:((z==1)?Bg2:Bg3);
                          biasp = (z==0)?bias:((z==1)?bias2:bias3); }
    else if (MODE == 3) { A = g_ctxh;  Bp = Bg; }
    else if (MODE == 4) { A = g_atth;  Bp = Bg + (size_t)e * D_ * FF_; }
    else                { A = g_hh;    Bp = Bg + (size_t)e * FF_ * D_; }

    {
        int m = mBase + tid, r = m;
        if (MODE == 4) {
            int pos = m & (CAP_-1);
            r = (pos < s_cnt) ? g_tokmap[e*CAP_ + pos] : 0;
        }
        rIdx[tid] = r;
    }
    __syncthreads();

    uint32_t sU = (uint32_t)__cvta_generic_to_shared(smc);
    const uint32_t aOff = (uint32_t)((wr*64 + (lane & 15)) * (LDA_H*2)) + ((lane >> 4) << 4);
    const uint32_t bOff = (uint32_t)((lane & 15) * (LDB_H*2)) + ((lane >> 4) << 4);

    auto issue = [&](int cix) {
        const int stg = cix & 1;
        const int k0 = cix * 32;
        const uint32_t aB = sU + stg * STAGE;
        #pragma unroll
        for (int i = 0; i < 4; i++) {
            int idx = tid + i * 128;
            int row = idx >> 2, c4 = idx & 3;
            cpa16(aB + row * (LDA_H*2) + c4 * 16,
                  A + (size_t)rIdx[row] * KK + k0 + c4 * 8);
        }
        const uint32_t bB = aB + ABYTES;
        #pragma unroll
        for (int i = 0; i < 4; i++) {
            int idx = tid + i * 128;
            int row = idx >> 4, c4 = idx & 15;
            cpa16(bB + row * (LDB_H*2) + c4 * 16,
                  Bp + (size_t)(k0 + row) * LDBG + nBase + c4 * 8);
        }
        cpa_commit();
    };

    float acc[4][NT][4];
    #pragma unroll
    for (int i = 0; i < 4; i++)
        #pragma unroll
        for (int j = 0; j < NT; j++)
            #pragma unroll
            for (int q = 0; q < 4; q++) acc[i][j][q] = 0.f;

    issue(0);
    for (int c = 0; c < NC; c++) {
        cpa_wait0();
        __syncthreads();
        if (c + 1 < NC) issue(c + 1);

        const int stg = c & 1;
        const uint32_t aBase = sU + stg * STAGE + aOff;
        const uint32_t bBase = sU + stg * STAGE + ABYTES + bOff + wc * 128; // wc*64 halves
        #pragma unroll
        for (int ks = 0; ks < 2; ks++) {       // two k16 steps per 32-half chunk
            uint32_t a[4][4];
            #pragma unroll
            for (int mt = 0; mt < 4; mt++)
                ldsm4(a[mt], aBase + mt * 16 * (LDA_H*2) + ks * 32);
            uint32_t b[NT][2];
            #pragma unroll
            for (int p = 0; p < 4; p++) {      // 16-n-wide pairs
                uint32_t r[4];
                ldsm4t(r, bBase + ks * 16 * (LDB_H*2) + p * 32);
                b[2*p][0]   = r[0]; b[2*p][1]   = r[1];
                b[2*p+1][0] = r[2]; b[2*p+1][1] = r[3];
            }
            #pragma unroll
            for (int mt = 0; mt < 4; mt++)
                #pragma unroll
                for (int nt = 0; nt < NT; nt++)
                    mma16(acc[mt][nt], a[mt], b[nt]);
        }
    }
    __syncthreads();

    // ---------------- epilogue (fp32 accums through smem) --------------------
    float* cSf = (float*)smc;
    #pragma unroll
    for (int mt = 0; mt < 4; mt++) {
        #pragma unroll
        for (int nt = 0; nt < NT; nt++) {
            int r = wr*64 + mt*16 + g;
            int n = wc*64 + nt*8 + 2*t;
            *(float2*)(cSf + r*CS + n)     = make_float2(acc[mt][nt][0], acc[mt][nt][1]);
            *(float2*)(cSf + (r+8)*CS + n) = make_float2(acc[mt][nt][2], acc[mt][nt][3]);
        }
    }
    __syncthreads();

    constexpr int IT = (128 * BF4) / 128;
    #pragma unroll
    for (int it = 0; it < IT; it++) {
        int idx = it * 128 + tid;
        int row = idx / BF4, q = idx % BF4;
        float4 v = *(const float4*)(cSf + row*CS + q*4);
        int m  = mBase + row;
        int n0 = nBase + q*4;

        if (MODE == 0) {
            v.x += biasp[n0]; v.y += biasp[n0+1]; v.z += biasp[n0+2]; v.w += biasp[n0+3];
            int b = m >> 10, srow = m & 1023, hh = n0 >> 6, dh = n0 & 63;
            float* dst = (z == 0) ? g_q : ((z == 1) ? g_k : g_v);
            *(float4*)(dst + (((size_t)(b*H_ + hh)) * S_ + srow) * DH_ + dh) = v;
        } else if (MODE == 3) {
            *(float4*)(g_tmp + (size_t)m * D_ + n0) = v;
        } else if (MODE == 4) {
            int pos = m & (CAP_-1);
            if (pos < s_cnt) {
                const float4 bb = *(const float4*)(bias + (size_t)e*FF_ + n0);
                __half* dst = g_hh + (size_t)m * FF_ + n0;
                *(__half2*)(dst)     = __floats2half2_rn(gelu_f(v.x+bb.x), gelu_f(v.y+bb.y));
                *(__half2*)(dst + 2) = __floats2half2_rn(gelu_f(v.z+bb.z), gelu_f(v.w+bb.w));
            }
        } else {
            int pos = m & (CAP_-1);
            if (pos < s_cnt) {
                int tok = g_tokmap[e*CAP_ + pos];
                float gsc = g_gate[tok];
                const float4 bb = *(const float4*)(bias + (size_t)e*D_ + n0);
                *(float4*)(g_ffn + (size_t)tok * D_ + n0) =
                    make_float4((v.x+bb.x)*gsc, (v.y+bb.y)*gsc,
                                (v.z+bb.z)*gsc, (v.w+bb.w)*gsc);
            }
        }
    }
}

// ---------------- layernorm (optional fp16 mirror output) --------------------
__global__ __launch_bounds__(256) void ln_kernel(
        const float* __restrict__ a, const float* __restrict__ bsum,
        const float* __restrict__ bias,
        const float* __restrict__ g, const float* __restrict__ beta,
        float* __restrict__ out, __half* __restrict__ outh)
{
    __shared__ float red[256];
    const int t = blockIdx.x, tid = threadIdx.x;
    const float* ap = a    + (size_t)t * D_;
    const float* bp = bsum + (size_t)t * D_;
    float v[3]; float s = 0.f;
    #pragma unroll
    for (int j=0;j<3;j++) {
        int i = tid + j*256;
        float x = ap[i] + bp[i];
        if (bias) x += bias[i];
        v[j] = x; s += x;
    }
    red[tid]=s; __syncthreads();
    for (int st=128; st>0; st>>=1) { if (tid<st) red[tid]+=red[tid+st]; __syncthreads(); }
    float mu = red[0] * (1.0f/768.0f);
    __syncthreads();
    float q = 0.f;
    #pragma unroll
    for (int j=0;j<3;j++) { float d = v[j]-mu; q += d*d; }
    red[tid]=q; __syncthreads();
    for (int st=128; st>0; st>>=1) { if (tid<st) red[tid]+=red[tid+st]; __syncthreads(); }
    float inv = rsqrtf(red[0]*(1.0f/768.0f) + 1e-12f);
    #pragma unroll
    for (int j=0;j<3;j++) {
        int i = tid + j*256;
        float y = (v[j]-mu)*inv*g[i] + beta[i];
        out[(size_t)t*D_ + i] = y;
        if (outh) outh[(size_t)t*D_ + i] = __float2half_rn(y);
    }
}

// ---------------- router ------------------------------------------------------
__global__ __launch_bounds__(256) void router_kernel(
        const float* __restrict__ Wr, const float* __restrict__ br)
{
    int warp = (blockIdx.x * blockDim.x + threadIdx.x) >> 5;
    int lane = threadIdx.x & 31;
    if (warp >= T_) return;
    const float* xrow = g_att + (size_t)warp * D_;
    float acc[E_];
    #pragma unroll
    for (int e=0;e<E_;e++) acc[e]=0.f;
    for (int i = lane; i < D_; i += 32) {
        float x = xrow[i];
        const float* w = Wr + i*E_;
        #pragma unroll
        for (int e=0;e<E_;e++) acc[e] += x * w[e];
    }
    #pragma unroll
    for (int e=0;e<E_;e++)
        #pragma unroll
        for (int o=16;o>0;o>>=1)
            acc[e] += __shfl_xor_sync(0xffffffffu, acc[e], o);
    if (lane == 0) {
        float best = -1e30f; int be = 0;
        #pragma unroll
        for (int e=0;e<E_;e++) {
            float l = acc[e] + br[e];
            acc[e] = l;
            if (l > best) { best = l; be = e; }
        }
        float sm = 0.f;
        #pragma unroll
        for (int e=0;e<E_;e++) sm += expf(acc[e] - best);
        float gate = 1.0f / sm;
        int pos = atomicAdd(&g_cnt[be], 1);
        if (pos < CAP_) {
            g_tokmap[be*CAP_ + pos] = warp;
            g_gate[warp] = gate;
        }
    }
}

__global__ void zero_small() {
    if (threadIdx.x < E_) g_cnt[threadIdx.x] = 0;
}

// ---------------- launch ------------------------------------------------------
extern "C" void kernel_launch(void* const* d_in, const int* in_sizes, int n_in,
                              void* d_out, int out_size) {
    const float* x    = (const float*)d_in[0];
    const float* mask = (const float*)d_in[1];
    const float* Wq   = (const float*)d_in[2];
    const float* bq   = (const float*)d_in[3];
    const float* Wk   = (const float*)d_in[4];
    const float* bk   = (const float*)d_in[5];
    const float* Wv   = (const float*)d_in[6];
    const float* bv   = (const float*)d_in[7];
    const float* Wo   = (const float*)d_in[8];
    const float* bo   = (const float*)d_in[9];
    const float* ln1g = (const float*)d_in[10];
    const float* ln1b = (const float*)d_in[11];
    const float* Wr   = (const float*)d_in[12];
    const float* br   = (const float*)d_in[13];
    const float* W1   = (const float*)d_in[14];
    const float* b1   = (const float*)d_in[15];
    const float* W2   = (const float*)d_in[16];
    const float* b2   = (const float*)d_in[17];
    const float* ln2g = (const float*)d_in[18];
    const float* ln2b = (const float*)d_in[19];
    float* out = (float*)d_out;

    float *p_tmp, *p_att, *p_ffn;
    __half *p_xh, *p_wqh, *p_wkh, *p_wvh, *p_woh, *p_w1h, *p_w2h, *p_atth;
    cudaGetSymbolAddress((void**)&p_tmp, g_tmp);
    cudaGetSymbolAddress((void**)&p_att, g_att);
    cudaGetSymbolAddress((void**)&p_ffn, g_ffn);
    cudaGetSymbolAddress((void**)&p_xh,  g_xh);
    cudaGetSymbolAddress((void**)&p_wqh, g_wqh);
    cudaGetSymbolAddress((void**)&p_wkh, g_wkh);
    cudaGetSymbolAddress((void**)&p_wvh, g_wvh);
    cudaGetSymbolAddress((void**)&p_woh, g_woh);
    cudaGetSymbolAddress((void**)&p_w1h, g_w1h);
    cudaGetSymbolAddress((void**)&p_w2h, g_w2h);
    cudaGetSymbolAddress((void**)&p_atth, g_atth);

    constexpr int SH_G  = 128 * 132 * 4;               // epilogue dominates: 67584
    constexpr int SH_FA = 2 * (64*68*4 + 64*72*4 + 256) + 8*16*68*4;  // 106880
    cudaFuncSetAttribute((const void*)tgemm<0,768,768>,   cudaFuncAttributeMaxDynamicSharedMemorySize, SH_G);
    cudaFuncSetAttribute((const void*)tgemm<3,768,768>,   cudaFuncAttributeMaxDynamicSharedMemorySize, SH_G);
    cudaFuncSetAttribute((const void*)tgemm<4,768,3072>,  cudaFuncAttributeMaxDynamicSharedMemorySize, SH_G);
    cudaFuncSetAttribute((const void*)tgemm<5,3072,768>,  cudaFuncAttributeMaxDynamicSharedMemorySize, SH_G);
    cudaFuncSetAttribute((const void*)fattn, cudaFuncAttributeMaxDynamicSharedMemorySize, SH_FA);

    zero_small<<<1, 32>>>();

    // fp32 -> fp16 operand conversions
    f2h<<<(T_*D_/4 + 255)/256, 256>>>(x,  p_xh,  T_*D_/4);
    f2h<<<(D_*D_/4 + 255)/256, 256>>>(Wq, p_wqh, D_*D_/4);
    f2h<<<(D_*D_/4 + 255)/256, 256>>>(Wk, p_wkh, D_*D_/4);
    f2h<<<(D_*D_/4 + 255)/256, 256>>>(Wv, p_wvh, D_*D_/4);
    f2h<<<(D_*D_/4 + 255)/256, 256>>>(Wo, p_woh, D_*D_/4);
    f2h<<<(E_*D_*FF_/4 + 255)/256, 256>>>(W1, p_w1h, E_*D_*FF_/4);
    f2h<<<(E_*FF_*D_/4 + 255)/256, 256>>>(W2, p_w2h, E_*FF_*D_/4);

    // fused QKV projections (fp16 in, fp32 q/k/v out)
    tgemm<0,768,768><<<dim3(6,64,3), 128, SH_G>>>(p_xh, p_wqh, p_wkh, p_wvh, bq, bk, bv);

    // fused flash attention -> g_ctxh (fp16)
    fattn<<<dim3(8, 96), 256, SH_FA>>>(mask);

    // att = LN1(x + ctxh@Wo + bo) ; fp16 mirror for MoE
    tgemm<3,768,768><<<dim3(6,64,1), 128, SH_G>>>(nullptr, p_woh, nullptr, nullptr, nullptr, nullptr, nullptr);
    ln_kernel<<<T_, 256>>>(x, p_tmp, bo, ln1g, ln1b, p_att, p_atth);

    // router + MoE (fp16 operands, fp32 accum)
    router_kernel<<<T_/8, 256>>>(Wr, br);
    tgemm<4,768,3072><<<dim3(FF_/128, (E_*CAP_)/128, 1), 128, SH_G>>>(nullptr, p_w1h, nullptr, nullptr, b1, nullptr, nullptr);
    tgemm<5,3072,768><<<dim3(D_/128, (E_*CAP_)/128, 1), 128, SH_G>>>(nullptr, p_w2h, nullptr, nullptr, b2, nullptr, nullptr);

    // out = LN2(att + ffn)
    ln_kernel<<<T_, 256>>>(p_att, p_ffn, nullptr, ln2g, ln2b, out, nullptr);
}

// round 12
// speedup vs baseline: 1.6723x; 1.1571x over previous
#include <cuda_runtime.h>
#include <cuda_fp16.h>
#include <cstdint>
#include <math.h>

#define B_  8
#define S_  1024
#define D_  768
#define H_  12
#define DH_ 64
#define FF_ 3072
#define E_  8
#define CAP_ 2048
#define T_  8192

// ---------------- scratch (device globals) ----------------------------------
__device__ float  g_tmp[T_*D_];
__device__ float  g_att[T_*D_];
__device__ float  g_ffn[T_*D_];
__device__ int    g_cnt[E_];
__device__ int    g_tokmap[E_*CAP_];
__device__ float  g_gate[T_];
// fp16 tensors
__device__ __half g_qh[B_*H_*S_*DH_];
__device__ __half g_kh[B_*H_*S_*DH_];
__device__ __half g_vh[B_*H_*S_*DH_];
__device__ __half g_xh[T_*D_];
__device__ __half g_wqh[D_*D_];
__device__ __half g_wkh[D_*D_];
__device__ __half g_wvh[D_*D_];
__device__ __half g_woh[D_*D_];
__device__ __half g_w1h[E_*D_*FF_];
__device__ __half g_w2h[E_*FF_*D_];
__device__ __half g_atth[T_*D_];
__device__ __half g_ctxh[T_*D_];
__device__ __half g_hh[50331648];          // E*CAP*FF fp16

__device__ __forceinline__ float gelu_f(float x) {
    return 0.5f * x * (1.0f + erff(x * 0.70710678118654752f));
}

__device__ __forceinline__ void cpa16(uint32_t dst, const void* src) {
    asm volatile("cp.async.ca.shared.global [%0], [%1], 16;" :: "r"(dst), "l"(src));
}
__device__ __forceinline__ void cpa_commit() {
    asm volatile("cp.async.commit_group;" ::: "memory");
}
__device__ __forceinline__ void cpa_wait0() {
    asm volatile("cp.async.wait_group 0;" ::: "memory");
}
// fp16 m16n8k16, fp32 accumulate
__device__ __forceinline__ void mma16(float* c, const uint32_t* a, const uint32_t* b) {
    asm volatile(
        "mma.sync.aligned.m16n8k16.row.col.f32.f16.f16.f32 "
        "{%0,%1,%2,%3}, {%4,%5,%6,%7}, {%8,%9}, {%0,%1,%2,%3};\n"
        : "+f"(c[0]), "+f"(c[1]), "+f"(c[2]), "+f"(c[3])
        : "r"(a[0]), "r"(a[1]), "r"(a[2]), "r"(a[3]), "r"(b[0]), "r"(b[1]));
}
__device__ __forceinline__ void ldsm4(uint32_t* r, uint32_t addr) {
    asm volatile("ldmatrix.sync.aligned.m8n8.x4.b16 {%0,%1,%2,%3}, [%4];"
                 : "=r"(r[0]), "=r"(r[1]), "=r"(r[2]), "=r"(r[3]) : "r"(addr));
}
__device__ __forceinline__ void ldsm4t(uint32_t* r, uint32_t addr) {
    asm volatile("ldmatrix.sync.aligned.m8n8.x4.trans.shared.b16 {%0,%1,%2,%3}, [%4];"
                 : "=r"(r[0]), "=r"(r[1]), "=r"(r[2]), "=r"(r[3]) : "r"(addr));
}

// ---------------- fp32 -> fp16 conversion ------------------------------------
__global__ void f2h(const float* __restrict__ s, __half* __restrict__ d, int n4) {
    int i = blockIdx.x * blockDim.x + threadIdx.x;
    if (i >= n4) return;
    float4 v = ((const float4*)s)[i];
    ((__half2*)d)[i*2]   = __floats2half2_rn(v.x, v.y);
    ((__half2*)d)[i*2+1] = __floats2half2_rn(v.z, v.w);
}

// ================= fused flash attention (fp16 MMA) ==========================
// grid (8, 96), 256 threads; warp owns 16 Q rows; K/V tiles 64 keys fp16.
__global__ __launch_bounds__(256) void fattn(const float* __restrict__ mask)
{
    constexpr int LDK_H = 72, LDV_H = 72, LDP_H = 72;   // halves
    constexpr int KBYTES = 64 * LDK_H * 2;   // 9216
    constexpr int VBYTES = 64 * LDV_H * 2;   // 9216
    constexpr int MBYTES = 256;
    constexpr int STAGE  = KBYTES + VBYTES + MBYTES;  // 18688
    extern __shared__ char smc[];

    const int tid = threadIdx.x, wid = tid >> 5, lane = tid & 31;
    const int g = lane >> 2, t = lane & 3;
    const int z = blockIdx.y, mBase = blockIdx.x * 128;
    const int bq = z / H_, hh = z % H_;
    const int m0 = mBase + wid * 16;

    const __half* Qp = g_qh + (size_t)z * S_ * DH_;
    const __half* Kp = g_kh + (size_t)z * S_ * DH_;
    const __half* Vp = g_vh + (size_t)z * S_ * DH_;

    // Q fragments (fp16, pre-scaled by 1/8 — exact)
    const __half2 sc8 = __half2half2(__float2half(0.125f));
    uint32_t qf[4][4];
    #pragma unroll
    for (int ks = 0; ks < 4; ks++) {
        __half2 h0 = __hmul2(*(const __half2*)&Qp[(m0 + g)     * DH_ + ks*16 + 2*t],     sc8);
        __half2 h1 = __hmul2(*(const __half2*)&Qp[(m0 + g + 8) * DH_ + ks*16 + 2*t],     sc8);
        __half2 h2 = __hmul2(*(const __half2*)&Qp[(m0 + g)     * DH_ + ks*16 + 2*t + 8], sc8);
        __half2 h3 = __hmul2(*(const __half2*)&Qp[(m0 + g + 8) * DH_ + ks*16 + 2*t + 8], sc8);
        qf[ks][0] = *(uint32_t*)&h0; qf[ks][1] = *(uint32_t*)&h1;
        qf[ks][2] = *(uint32_t*)&h2; qf[ks][3] = *(uint32_t*)&h3;
    }

    float oacc[8][4];
    #pragma unroll
    for (int nt = 0; nt < 8; nt++)
        #pragma unroll
        for (int q = 0; q < 4; q++) oacc[nt][q] = 0.f;
    float mrow0 = -1e30f, mrow1 = -1e30f, lrow0 = 0.f, lrow1 = 0.f;

    uint32_t sU = (uint32_t)__cvta_generic_to_shared(smc);
    const uint32_t lmRow = (lane & 15);
    const uint32_t lmHalf = (lane >> 4) << 4;
    const uint32_t kOff = lmRow * (LDK_H*2) + lmHalf;            // K A-style frag addr
    const uint32_t vOff = lmRow * (LDV_H*2) + lmHalf;            // V trans frag addr
    const uint32_t pU   = sU + 2*STAGE + wid * 16 * (LDP_H*2);
    const uint32_t pOff = pU + lmRow * (LDP_H*2) + lmHalf;

    auto issue = [&](int kt) {
        const int stg = kt & 1;
        const uint32_t base = sU + stg * STAGE;
        #pragma unroll
        for (int i = 0; i < 2; i++) {
            int idx = tid + i * 256;
            int row = idx >> 3, c4 = idx & 7;
            cpa16(base + row * (LDK_H*2) + c4 * 16,
                  Kp + (size_t)(kt*64 + row) * DH_ + c4 * 8);
        }
        #pragma unroll
        for (int i = 0; i < 2; i++) {
            int idx = tid + i * 256;
            int row = idx >> 3, c4 = idx & 7;
            cpa16(base + KBYTES + row * (LDV_H*2) + c4 * 16,
                  Vp + (size_t)(kt*64 + row) * DH_ + c4 * 8);
        }
        if (tid < 16)
            cpa16(base + KBYTES + VBYTES + tid * 16, mask + bq * S_ + kt*64 + tid * 4);
        cpa_commit();
    };

    __half* pS = (__half*)(smc + 2*STAGE) + wid * 16 * LDP_H;

    issue(0);
    for (int kt = 0; kt < 16; kt++) {
        cpa_wait0();
        __syncthreads();
        if (kt + 1 < 16) issue(kt + 1);

        const int stg = kt & 1;
        const uint32_t kBase = sU + stg * STAGE;
        const uint32_t vBase = kBase + KBYTES;
        const float* mS = (const float*)(smc + stg * STAGE + KBYTES + VBYTES);

        // ---- scores strip 16 x 64 (fp16 mma, k=64 in 4 k16 steps) ----
        float sacc[8][4];
        #pragma unroll
        for (int nt = 0; nt < 8; nt++)
            #pragma unroll
            for (int q = 0; q < 4; q++) sacc[nt][q] = 0.f;
        #pragma unroll
        for (int ks = 0; ks < 4; ks++) {
            #pragma unroll
            for (int p = 0; p < 4; p++) {   // 16 keys per ldsm4
                uint32_t r[4];
                ldsm4(r, kBase + kOff + p * 16 * (LDK_H*2) + ks * 32);
                uint32_t b0[2] = { r[0], r[2] };
                uint32_t b1[2] = { r[1], r[3] };
                mma16(sacc[2*p],   qf[ks], b0);
                mma16(sacc[2*p+1], qf[ks], b1);
            }
        }

        // ---- mask + row max ----
        float mx0 = -1e30f, mx1 = -1e30f;
        #pragma unroll
        for (int nt = 0; nt < 8; nt++) {
            float mk0 = mS[nt*8 + 2*t], mk1 = mS[nt*8 + 2*t + 1];
            sacc[nt][0] += mk0;
            sacc[nt][1] += mk1;
            sacc[nt][2] += mk0;
            sacc[nt][3] += mk1;
            mx0 = fmaxf(mx0, fmaxf(sacc[nt][0], sacc[nt][1]));
            mx1 = fmaxf(mx1, fmaxf(sacc[nt][2], sacc[nt][3]));
        }
        mx0 = fmaxf(mx0, __shfl_xor_sync(0xffffffffu, mx0, 1));
        mx0 = fmaxf(mx0, __shfl_xor_sync(0xffffffffu, mx0, 2));
        mx1 = fmaxf(mx1, __shfl_xor_sync(0xffffffffu, mx1, 1));
        mx1 = fmaxf(mx1, __shfl_xor_sync(0xffffffffu, mx1, 2));

        float mn0 = fmaxf(mrow0, mx0), mn1 = fmaxf(mrow1, mx1);
        float a0 = __expf(mrow0 - mn0), a1 = __expf(mrow1 - mn1);
        mrow0 = mn0; mrow1 = mn1;

        // ---- exp, stage P as fp16, partial sums ----
        float s0 = 0.f, s1 = 0.f;
        #pragma unroll
        for (int nt = 0; nt < 8; nt++) {
            float p0 = __expf(sacc[nt][0] - mn0);
            float p1 = __expf(sacc[nt][1] - mn0);
            float p2 = __expf(sacc[nt][2] - mn1);
            float p3 = __expf(sacc[nt][3] - mn1);
            s0 += p0 + p1; s1 += p2 + p3;
            *(__half2*)(pS + g * LDP_H + nt*8 + 2*t)       = __floats2half2_rn(p0, p1);
            *(__half2*)(pS + (g + 8) * LDP_H + nt*8 + 2*t) = __floats2half2_rn(p2, p3);
        }
        s0 += __shfl_xor_sync(0xffffffffu, s0, 1);
        s0 += __shfl_xor_sync(0xffffffffu, s0, 2);
        s1 += __shfl_xor_sync(0xffffffffu, s1, 1);
        s1 += __shfl_xor_sync(0xffffffffu, s1, 2);
        lrow0 = lrow0 * a0 + s0;
        lrow1 = lrow1 * a1 + s1;

        #pragma unroll
        for (int nt = 0; nt < 8; nt++) {
            oacc[nt][0] *= a0; oacc[nt][1] *= a0;
            oacc[nt][2] *= a1; oacc[nt][3] *= a1;
        }
        __syncwarp();

        // ---- P @ V (fp16, k=64 in 4 k16 steps; V via ldsm4t n-major) ----
        #pragma unroll
        for (int ks = 0; ks < 4; ks++) {
            uint32_t a[4];
            ldsm4(a, pOff + ks * 32);
            #pragma unroll
            for (int p = 0; p < 4; p++) {   // 16 dh-cols per ldsm4t
                uint32_t r[4];
                ldsm4t(r, vBase + vOff + ks * 16 * (LDV_H*2) + p * 32);
                uint32_t b0[2] = { r[0], r[1] };
                uint32_t b1[2] = { r[2], r[3] };
                mma16(oacc[2*p],   a, b0);
                mma16(oacc[2*p+1], a, b1);
            }
        }
    }

    float inv0 = 1.0f / lrow0, inv1 = 1.0f / lrow1;
    int mr0 = m0 + g, mr1 = m0 + g + 8;
    #pragma unroll
    for (int nt = 0; nt < 8; nt++) {
        int col = hh * DH_ + nt*8 + 2*t;
        *(__half2*)(g_ctxh + ((size_t)(bq * S_ + mr0)) * D_ + col) =
            __floats2half2_rn(oacc[nt][0] * inv0, oacc[nt][1] * inv0);
        *(__half2*)(g_ctxh + ((size_t)(bq * S_ + mr1)) * D_ + col) =
            __floats2half2_rn(oacc[nt][2] * inv1, oacc[nt][3] * inv1);
    }
}

// ---------------- fp16 mma.sync GEMM: 128x128 tile, 128 threads --------------
// MODE 0: QKV proj (z selects W/b), headed fp16 scatter to q/k/v
// MODE 3: ctxh @ Wo -> g_tmp (fp32)
// MODE 4: gather(atth) @ W1[e] + b1 -> gelu -> g_hh (fp16)
// MODE 5: g_hh @ W2[e] + b2, * gate, scatter -> g_ffn (fp32)
template<int MODE, int KK, int LDBG>
__global__ __launch_bounds__(128, 2)
void tgemm(const __half* __restrict__ Ag, const __half* __restrict__ Bg,
           const __half* __restrict__ Bg2, const __half* __restrict__ Bg3,
           const float* __restrict__ bias, const float* __restrict__ bias2,
           const float* __restrict__ bias3)
{
    constexpr int BN     = 128;
    constexpr int NC     = KK / 32;
    constexpr int NT     = 8;
    constexpr int LDA_H  = 40;
    constexpr int LDB_H  = 136;
    constexpr int ABYTES = 128 * LDA_H * 2;    // 10240
    constexpr int BBYTES = 32 * LDB_H * 2;     // 8704
    constexpr int STAGE  = ABYTES + BBYTES;    // 18944
    constexpr int CS     = BN + 4;
    constexpr int BF4    = BN / 4;

    extern __shared__ char smc[];
    __shared__ int rIdx[128];
    __shared__ int s_cnt;

    const int tid = threadIdx.x, wid = tid >> 5, lane = tid & 31;
    const int wr = wid >> 1, wc = wid & 1;
    const int g = lane >> 2, t = lane & 3;
    const int mBase = blockIdx.y * 128, nBase = blockIdx.x * BN, z = blockIdx.z;
    const int e = (MODE >= 4) ? (mBase >> 11) : 0;

    if (MODE == 4 || MODE == 5) {
        if (tid == 0) s_cnt = g_cnt[e];
        __syncthreads();
        if ((mBase & (CAP_-1)) >= s_cnt) return;
    }

    const __half* A; const __half* Bp; const float* biasp = bias;
    if      (MODE == 0) { A = Ag; Bp = (z==0)?Bg:((z==1)?Bg2:Bg3);
                          biasp = (z==0)?bias:((z==1)?bias2:bias3); }
    else if (MODE == 3) { A = g_ctxh;  Bp = Bg; }
    else if (MODE == 4) { A = g_atth;  Bp = Bg + (size_t)e * D_ * FF_; }
    else                { A = g_hh;    Bp = Bg + (size_t)e * FF_ * D_; }

    {
        int m = mBase + tid, r = m;
        if (MODE == 4) {
            int pos = m & (CAP_-1);
            r = (pos < s_cnt) ? g_tokmap[e*CAP_ + pos] : 0;
        }
        rIdx[tid] = r;
    }
    __syncthreads();

    uint32_t sU = (uint32_t)__cvta_generic_to_shared(smc);
    const uint32_t aOff = (uint32_t)((wr*64 + (lane & 15)) * (LDA_H*2)) + ((lane >> 4) << 4);
    const uint32_t bOff = (uint32_t)((lane & 15) * (LDB_H*2)) + ((lane >> 4) << 4);

    auto issue = [&](int cix) {
        const int stg = cix & 1;
        const int k0 = cix * 32;
        const uint32_t aB = sU + stg * STAGE;
        #pragma unroll
        for (int i = 0; i < 4; i++) {
            int idx = tid + i * 128;
            int row = idx >> 2, c4 = idx & 3;
            cpa16(aB + row * (LDA_H*2) + c4 * 16,
                  A + (size_t)rIdx[row] * KK + k0 + c4 * 8);
        }
        const uint32_t bB = aB + ABYTES;
        #pragma unroll
        for (int i = 0; i < 4; i++) {
            int idx = tid + i * 128;
            int row = idx >> 4, c4 = idx & 15;
            cpa16(bB + row * (LDB_H*2) + c4 * 16,
                  Bp + (size_t)(k0 + row) * LDBG + nBase + c4 * 8);
        }
        cpa_commit();
    };

    float acc[4][NT][4];
    #pragma unroll
    for (int i = 0; i < 4; i++)
        #pragma unroll
        for (int j = 0; j < NT; j++)
            #pragma unroll
            for (int q = 0; q < 4; q++) acc[i][j][q] = 0.f;

    issue(0);
    for (int c = 0; c < NC; c++) {
        cpa_wait0();
        __syncthreads();
        if (c + 1 < NC) issue(c + 1);

        const int stg = c & 1;
        const uint32_t aBase = sU + stg * STAGE + aOff;
        const uint32_t bBase = sU + stg * STAGE + ABYTES + bOff + wc * 128;
        #pragma unroll
        for (int ks = 0; ks < 2; ks++) {
            uint32_t a[4][4];
            #pragma unroll
            for (int mt = 0; mt < 4; mt++)
                ldsm4(a[mt], aBase + mt * 16 * (LDA_H*2) + ks * 32);
            uint32_t b[NT][2];
            #pragma unroll
            for (int p = 0; p < 4; p++) {
                uint32_t r[4];
                ldsm4t(r, bBase + ks * 16 * (LDB_H*2) + p * 32);
                b[2*p][0]   = r[0]; b[2*p][1]   = r[1];
                b[2*p+1][0] = r[2]; b[2*p+1][1] = r[3];
            }
            #pragma unroll
            for (int mt = 0; mt < 4; mt++)
                #pragma unroll
                for (int nt = 0; nt < NT; nt++)
                    mma16(acc[mt][nt], a[mt], b[nt]);
        }
    }
    __syncthreads();

    // ---------------- epilogue ----------------
    float* cSf = (float*)smc;
    #pragma unroll
    for (int mt = 0; mt < 4; mt++) {
        #pragma unroll
        for (int nt = 0; nt < NT; nt++) {
            int r = wr*64 + mt*16 + g;
            int n = wc*64 + nt*8 + 2*t;
            *(float2*)(cSf + r*CS + n)     = make_float2(acc[mt][nt][0], acc[mt][nt][1]);
            *(float2*)(cSf + (r+8)*CS + n) = make_float2(acc[mt][nt][2], acc[mt][nt][3]);
        }
    }
    __syncthreads();

    constexpr int IT = (128 * BF4) / 128;
    #pragma unroll
    for (int it = 0; it < IT; it++) {
        int idx = it * 128 + tid;
        int row = idx / BF4, q = idx % BF4;
        float4 v = *(const float4*)(cSf + row*CS + q*4);
        int m  = mBase + row;
        int n0 = nBase + q*4;

        if (MODE == 0) {
            v.x += biasp[n0]; v.y += biasp[n0+1]; v.z += biasp[n0+2]; v.w += biasp[n0+3];
            int b = m >> 10, srow = m & 1023, hh = n0 >> 6, dh = n0 & 63;
            __half* dst = (z == 0) ? g_qh : ((z == 1) ? g_kh : g_vh);
            __half* p = dst + (((size_t)(b*H_ + hh)) * S_ + srow) * DH_ + dh;
            *(__half2*)(p)     = __floats2half2_rn(v.x, v.y);
            *(__half2*)(p + 2) = __floats2half2_rn(v.z, v.w);
        } else if (MODE == 3) {
            *(float4*)(g_tmp + (size_t)m * D_ + n0) = v;
        } else if (MODE == 4) {
            int pos = m & (CAP_-1);
            if (pos < s_cnt) {
                const float4 bb = *(const float4*)(bias + (size_t)e*FF_ + n0);
                __half* dst = g_hh + (size_t)m * FF_ + n0;
                *(__half2*)(dst)     = __floats2half2_rn(gelu_f(v.x+bb.x), gelu_f(v.y+bb.y));
                *(__half2*)(dst + 2) = __floats2half2_rn(gelu_f(v.z+bb.z), gelu_f(v.w+bb.w));
            }
        } else {
            int pos = m & (CAP_-1);
            if (pos < s_cnt) {
                int tok = g_tokmap[e*CAP_ + pos];
                float gsc = g_gate[tok];
                const float4 bb = *(const float4*)(bias + (size_t)e*D_ + n0);
                *(float4*)(g_ffn + (size_t)tok * D_ + n0) =
                    make_float4((v.x+bb.x)*gsc, (v.y+bb.y)*gsc,
                                (v.z+bb.z)*gsc, (v.w+bb.w)*gsc);
            }
        }
    }
}

// ---------------- layernorm (optional fp16 mirror output) --------------------
__global__ __launch_bounds__(256) void ln_kernel(
        const float* __restrict__ a, const float* __restrict__ bsum,
        const float* __restrict__ bias,
        const float* __restrict__ g, const float* __restrict__ beta,
        float* __restrict__ out, __half* __restrict__ outh)
{
    __shared__ float red[256];
    const int t = blockIdx.x, tid = threadIdx.x;
    const float* ap = a    + (size_t)t * D_;
    const float* bp = bsum + (size_t)t * D_;
    float v[3]; float s = 0.f;
    #pragma unroll
    for (int j=0;j<3;j++) {
        int i = tid + j*256;
        float x = ap[i] + bp[i];
        if (bias) x += bias[i];
        v[j] = x; s += x;
    }
    red[tid]=s; __syncthreads();
    for (int st=128; st>0; st>>=1) { if (tid<st) red[tid]+=red[tid+st]; __syncthreads(); }
    float mu = red[0] * (1.0f/768.0f);
    __syncthreads();
    float q = 0.f;
    #pragma unroll
    for (int j=0;j<3;j++) { float d = v[j]-mu; q += d*d; }
    red[tid]=q; __syncthreads();
    for (int st=128; st>0; st>>=1) { if (tid<st) red[tid]+=red[tid+st]; __syncthreads(); }
    float inv = rsqrtf(red[0]*(1.0f/768.0f) + 1e-12f);
    #pragma unroll
    for (int j=0;j<3;j++) {
        int i = tid + j*256;
        float y = (v[j]-mu)*inv*g[i] + beta[i];
        out[(size_t)t*D_ + i] = y;
        if (outh) outh[(size_t)t*D_ + i] = __float2half_rn(y);
    }
}

// ---------------- router ------------------------------------------------------
__global__ __launch_bounds__(256) void router_kernel(
        const float* __restrict__ Wr, const float* __restrict__ br)
{
    int warp = (blockIdx.x * blockDim.x + threadIdx.x) >> 5;
    int lane = threadIdx.x & 31;
    if (warp >= T_) return;
    const float* xrow = g_att + (size_t)warp * D_;
    float acc[E_];
    #pragma unroll
    for (int e=0;e<E_;e++) acc[e]=0.f;
    for (int i = lane; i < D_; i += 32) {
        float x = xrow[i];
        const float* w = Wr + i*E_;
        #pragma unroll
        for (int e=0;e<E_;e++) acc[e] += x * w[e];
    }
    #pragma unroll
    for (int e=0;e<E_;e++)
        #pragma unroll
        for (int o=16;o>0;o>>=1)
            acc[e] += __shfl_xor_sync(0xffffffffu, acc[e], o);
    if (lane == 0) {
        float best = -1e30f; int be = 0;
        #pragma unroll
        for (int e=0;e<E_;e++) {
            float l = acc[e] + br[e];
            acc[e] = l;
            if (l > best) { best = l; be = e; }
        }
        float sm = 0.f;
        #pragma unroll
        for (int e=0;e<E_;e++) sm += expf(acc[e] - best);
        float gate = 1.0f / sm;
        int pos = atomicAdd(&g_cnt[be], 1);
        if (pos < CAP_) {
            g_tokmap[be*CAP_ + pos] = warp;
            g_gate[warp] = gate;
        }
    }
}

__global__ void zero_small() {
    if (threadIdx.x < E_) g_cnt[threadIdx.x] = 0;
}

// ---------------- launch ------------------------------------------------------
extern "C" void kernel_launch(void* const* d_in, const int* in_sizes, int n_in,
                              void* d_out, int out_size) {
    const float* x    = (const float*)d_in[0];
    const float* mask = (const float*)d_in[1];
    const float* Wq   = (const float*)d_in[2];
    const float* bq   = (const float*)d_in[3];
    const float* Wk   = (const float*)d_in[4];
    const float* bk   = (const float*)d_in[5];
    const float* Wv   = (const float*)d_in[6];
    const float* bv   = (const float*)d_in[7];
    const float* Wo   = (const float*)d_in[8];
    const float* bo   = (const float*)d_in[9];
    const float* ln1g = (const float*)d_in[10];
    const float* ln1b = (const float*)d_in[11];
    const float* Wr   = (const float*)d_in[12];
    const float* br   = (const float*)d_in[13];
    const float* W1   = (const float*)d_in[14];
    const float* b1   = (const float*)d_in[15];
    const float* W2   = (const float*)d_in[16];
    const float* b2   = (const float*)d_in[17];
    const float* ln2g = (const float*)d_in[18];
    const float* ln2b = (const float*)d_in[19];
    float* out = (float*)d_out;

    float *p_tmp, *p_att, *p_ffn;
    __half *p_xh, *p_wqh, *p_wkh, *p_wvh, *p_woh, *p_w1h, *p_w2h, *p_atth;
    cudaGetSymbolAddress((void**)&p_tmp, g_tmp);
    cudaGetSymbolAddress((void**)&p_att, g_att);
    cudaGetSymbolAddress((void**)&p_ffn, g_ffn);
    cudaGetSymbolAddress((void**)&p_xh,  g_xh);
    cudaGetSymbolAddress((void**)&p_wqh, g_wqh);
    cudaGetSymbolAddress((void**)&p_wkh, g_wkh);
    cudaGetSymbolAddress((void**)&p_wvh, g_wvh);
    cudaGetSymbolAddress((void**)&p_woh, g_woh);
    cudaGetSymbolAddress((void**)&p_w1h, g_w1h);
    cudaGetSymbolAddress((void**)&p_w2h, g_w2h);
    cudaGetSymbolAddress((void**)&p_atth, g_atth);

    constexpr int SH_G  = 128 * 132 * 4;                       // 67584
    constexpr int SH_FA = 2 * 18688 + 8*16*72*2;               // 55808
    cudaFuncSetAttribute((const void*)tgemm<0,768,768>,   cudaFuncAttributeMaxDynamicSharedMemorySize, SH_G);
    cudaFuncSetAttribute((const void*)tgemm<3,768,768>,   cudaFuncAttributeMaxDynamicSharedMemorySize, SH_G);
    cudaFuncSetAttribute((const void*)tgemm<4,768,3072>,  cudaFuncAttributeMaxDynamicSharedMemorySize, SH_G);
    cudaFuncSetAttribute((const void*)tgemm<5,3072,768>,  cudaFuncAttributeMaxDynamicSharedMemorySize, SH_G);
    cudaFuncSetAttribute((const void*)fattn, cudaFuncAttributeMaxDynamicSharedMemorySize, SH_FA);

    zero_small<<<1, 32>>>();

    // fp32 -> fp16 operand conversions
    f2h<<<(T_*D_/4 + 255)/256, 256>>>(x,  p_xh,  T_*D_/4);
    f2h<<<(D_*D_/4 + 255)/256, 256>>>(Wq, p_wqh, D_*D_/4);
    f2h<<<(D_*D_/4 + 255)/256, 256>>>(Wk, p_wkh, D_*D_/4);
    f2h<<<(D_*D_/4 + 255)/256, 256>>>(Wv, p_wvh, D_*D_/4);
    f2h<<<(D_*D_/4 + 255)/256, 256>>>(Wo, p_woh, D_*D_/4);
    f2h<<<(E_*D_*FF_/4 + 255)/256, 256>>>(W1, p_w1h, E_*D_*FF_/4);
    f2h<<<(E_*FF_*D_/4 + 255)/256, 256>>>(W2, p_w2h, E_*FF_*D_/4);

    // fused QKV projections (fp16 in, fp16 q/k/v out)
    tgemm<0,768,768><<<dim3(6,64,3), 128, SH_G>>>(p_xh, p_wqh, p_wkh, p_wvh, bq, bk, bv);

    // fused flash attention (fp16 MMA) -> g_ctxh
    fattn<<<dim3(8, 96), 256, SH_FA>>>(mask);

    // att = LN1(x + ctxh@Wo + bo) ; fp16 mirror for MoE
    tgemm<3,768,768><<<dim3(6,64,1), 128, SH_G>>>(nullptr, p_woh, nullptr, nullptr, nullptr, nullptr, nullptr);
    ln_kernel<<<T_, 256>>>(x, p_tmp, bo, ln1g, ln1b, p_att, p_atth);

    // router + MoE (fp16 operands, fp32 accum)
    router_kernel<<<T_/8, 256>>>(Wr, br);
    tgemm<4,768,3072><<<dim3(FF_/128, (E_*CAP_)/128, 1), 128, SH_G>>>(nullptr, p_w1h, nullptr, nullptr, b1, nullptr, nullptr);
    tgemm<5,3072,768><<<dim3(D_/128, (E_*CAP_)/128, 1), 128, SH_G>>>(nullptr, p_w2h, nullptr, nullptr, b2, nullptr, nullptr);

    // out = LN2(att + ffn)
    ln_kernel<<<T_, 256>>>(p_att, p_ffn, nullptr, ln2g, ln2b, out, nullptr);
}

// round 13
// speedup vs baseline: 1.8176x; 1.0869x over previous
#include <cuda_runtime.h>
#include <cuda_fp16.h>
#include <cstdint>
#include <math.h>

#define B_  8
#define S_  1024
#define D_  768
#define H_  12
#define DH_ 64
#define FF_ 3072
#define E_  8
#define CAP_ 2048
#define T_  8192

// ---------------- scratch (device globals) ----------------------------------
__device__ float  g_tmp[T_*D_];
__device__ float  g_att[T_*D_];
__device__ float  g_ffn[T_*D_];
__device__ int    g_cnt[E_];
__device__ int    g_tokmap[E_*CAP_];
__device__ float  g_gate[T_];
// fp16 tensors
__device__ __half g_qh[B_*H_*S_*DH_];
__device__ __half g_kh[B_*H_*S_*DH_];
__device__ __half g_vh[B_*H_*S_*DH_];
__device__ __half g_xh[T_*D_];
__device__ __half g_wqh[D_*D_];
__device__ __half g_wkh[D_*D_];
__device__ __half g_wvh[D_*D_];
__device__ __half g_woh[D_*D_];
__device__ __half g_w1h[E_*D_*FF_];
__device__ __half g_w2h[E_*FF_*D_];
__device__ __half g_atth[T_*D_];
__device__ __half g_ctxh[T_*D_];
__device__ __half g_hh[50331648];          // E*CAP*FF fp16

__device__ __forceinline__ float gelu_f(float x) {
    return 0.5f * x * (1.0f + erff(x * 0.70710678118654752f));
}

__device__ __forceinline__ void cpa16(uint32_t dst, const void* src) {
    asm volatile("cp.async.ca.shared.global [%0], [%1], 16;" :: "r"(dst), "l"(src));
}
__device__ __forceinline__ void cpa_commit() {
    asm volatile("cp.async.commit_group;" ::: "memory");
}
__device__ __forceinline__ void cpa_wait0() {
    asm volatile("cp.async.wait_group 0;" ::: "memory");
}
// fp16 m16n8k16, fp32 accumulate
__device__ __forceinline__ void mma16(float* c, const uint32_t* a, const uint32_t* b) {
    asm volatile(
        "mma.sync.aligned.m16n8k16.row.col.f32.f16.f16.f32 "
        "{%0,%1,%2,%3}, {%4,%5,%6,%7}, {%8,%9}, {%0,%1,%2,%3};\n"
        : "+f"(c[0]), "+f"(c[1]), "+f"(c[2]), "+f"(c[3])
        : "r"(a[0]), "r"(a[1]), "r"(a[2]), "r"(a[3]), "r"(b[0]), "r"(b[1]));
}
__device__ __forceinline__ void ldsm4(uint32_t* r, uint32_t addr) {
    asm volatile("ldmatrix.sync.aligned.m8n8.x4.b16 {%0,%1,%2,%3}, [%4];"
                 : "=r"(r[0]), "=r"(r[1]), "=r"(r[2]), "=r"(r[3]) : "r"(addr));
}
__device__ __forceinline__ void ldsm4t(uint32_t* r, uint32_t addr) {
    asm volatile("ldmatrix.sync.aligned.m8n8.x4.trans.shared.b16 {%0,%1,%2,%3}, [%4];"
                 : "=r"(r[0]), "=r"(r[1]), "=r"(r[2]), "=r"(r[3]) : "r"(addr));
}

// ---------------- fp32 -> fp16 conversion ------------------------------------
__global__ void f2h(const float* __restrict__ s, __half* __restrict__ d, int n4) {
    int i = blockIdx.x * blockDim.x + threadIdx.x;
    if (i >= n4) return;
    float4 v = ((const float4*)s)[i];
    ((__half2*)d)[i*2]   = __floats2half2_rn(v.x, v.y);
    ((__half2*)d)[i*2+1] = __floats2half2_rn(v.z, v.w);
}

// ================= fused flash attention (fp16 MMA) ==========================
__global__ __launch_bounds__(256) void fattn(const float* __restrict__ mask)
{
    constexpr int LDK_H = 72, LDV_H = 72, LDP_H = 72;
    constexpr int KBYTES = 64 * LDK_H * 2;
    constexpr int VBYTES = 64 * LDV_H * 2;
    constexpr int MBYTES = 256;
    constexpr int STAGE  = KBYTES + VBYTES + MBYTES;
    extern __shared__ char smc[];

    const int tid = threadIdx.x, wid = tid >> 5, lane = tid & 31;
    const int g = lane >> 2, t = lane & 3;
    const int z = blockIdx.y, mBase = blockIdx.x * 128;
    const int bq = z / H_, hh = z % H_;
    const int m0 = mBase + wid * 16;

    const __half* Qp = g_qh + (size_t)z * S_ * DH_;
    const __half* Kp = g_kh + (size_t)z * S_ * DH_;
    const __half* Vp = g_vh + (size_t)z * S_ * DH_;

    const __half2 sc8 = __half2half2(__float2half(0.125f));
    uint32_t qf[4][4];
    #pragma unroll
    for (int ks = 0; ks < 4; ks++) {
        __half2 h0 = __hmul2(*(const __half2*)&Qp[(m0 + g)     * DH_ + ks*16 + 2*t],     sc8);
        __half2 h1 = __hmul2(*(const __half2*)&Qp[(m0 + g + 8) * DH_ + ks*16 + 2*t],     sc8);
        __half2 h2 = __hmul2(*(const __half2*)&Qp[(m0 + g)     * DH_ + ks*16 + 2*t + 8], sc8);
        __half2 h3 = __hmul2(*(const __half2*)&Qp[(m0 + g + 8) * DH_ + ks*16 + 2*t + 8], sc8);
        qf[ks][0] = *(uint32_t*)&h0; qf[ks][1] = *(uint32_t*)&h1;
        qf[ks][2] = *(uint32_t*)&h2; qf[ks][3] = *(uint32_t*)&h3;
    }

    float oacc[8][4];
    #pragma unroll
    for (int nt = 0; nt < 8; nt++)
        #pragma unroll
        for (int q = 0; q < 4; q++) oacc[nt][q] = 0.f;
    float mrow0 = -1e30f, mrow1 = -1e30f, lrow0 = 0.f, lrow1 = 0.f;

    uint32_t sU = (uint32_t)__cvta_generic_to_shared(smc);
    const uint32_t lmRow = (lane & 15);
    const uint32_t lmHalf = (lane >> 4) << 4;
    const uint32_t kOff = lmRow * (LDK_H*2) + lmHalf;
    const uint32_t vOff = lmRow * (LDV_H*2) + lmHalf;
    const uint32_t pU   = sU + 2*STAGE + wid * 16 * (LDP_H*2);
    const uint32_t pOff = pU + lmRow * (LDP_H*2) + lmHalf;

    auto issue = [&](int kt) {
        const int stg = kt & 1;
        const uint32_t base = sU + stg * STAGE;
        #pragma unroll
        for (int i = 0; i < 2; i++) {
            int idx = tid + i * 256;
            int row = idx >> 3, c4 = idx & 7;
            cpa16(base + row * (LDK_H*2) + c4 * 16,
                  Kp + (size_t)(kt*64 + row) * DH_ + c4 * 8);
        }
        #pragma unroll
        for (int i = 0; i < 2; i++) {
            int idx = tid + i * 256;
            int row = idx >> 3, c4 = idx & 7;
            cpa16(base + KBYTES + row * (LDV_H*2) + c4 * 16,
                  Vp + (size_t)(kt*64 + row) * DH_ + c4 * 8);
        }
        if (tid < 16)
            cpa16(base + KBYTES + VBYTES + tid * 16, mask + bq * S_ + kt*64 + tid * 4);
        cpa_commit();
    };

    __half* pS = (__half*)(smc + 2*STAGE) + wid * 16 * LDP_H;

    issue(0);
    for (int kt = 0; kt < 16; kt++) {
        cpa_wait0();
        __syncthreads();
        if (kt + 1 < 16) issue(kt + 1);

        const int stg = kt & 1;
        const uint32_t kBase = sU + stg * STAGE;
        const uint32_t vBase = kBase + KBYTES;
        const float* mS = (const float*)(smc + stg * STAGE + KBYTES + VBYTES);

        float sacc[8][4];
        #pragma unroll
        for (int nt = 0; nt < 8; nt++)
            #pragma unroll
            for (int q = 0; q < 4; q++) sacc[nt][q] = 0.f;
        #pragma unroll
        for (int ks = 0; ks < 4; ks++) {
            #pragma unroll
            for (int p = 0; p < 4; p++) {
                uint32_t r[4];
                ldsm4(r, kBase + kOff + p * 16 * (LDK_H*2) + ks * 32);
                uint32_t b0[2] = { r[0], r[2] };
                uint32_t b1[2] = { r[1], r[3] };
                mma16(sacc[2*p],   qf[ks], b0);
                mma16(sacc[2*p+1], qf[ks], b1);
            }
        }

        float mx0 = -1e30f, mx1 = -1e30f;
        #pragma unroll
        for (int nt = 0; nt < 8; nt++) {
            float mk0 = mS[nt*8 + 2*t], mk1 = mS[nt*8 + 2*t + 1];
            sacc[nt][0] += mk0;
            sacc[nt][1] += mk1;
            sacc[nt][2] += mk0;
            sacc[nt][3] += mk1;
            mx0 = fmaxf(mx0, fmaxf(sacc[nt][0], sacc[nt][1]));
            mx1 = fmaxf(mx1, fmaxf(sacc[nt][2], sacc[nt][3]));
        }
        mx0 = fmaxf(mx0, __shfl_xor_sync(0xffffffffu, mx0, 1));
        mx0 = fmaxf(mx0, __shfl_xor_sync(0xffffffffu, mx0, 2));
        mx1 = fmaxf(mx1, __shfl_xor_sync(0xffffffffu, mx1, 1));
        mx1 = fmaxf(mx1, __shfl_xor_sync(0xffffffffu, mx1, 2));

        float mn0 = fmaxf(mrow0, mx0), mn1 = fmaxf(mrow1, mx1);
        float a0 = __expf(mrow0 - mn0), a1 = __expf(mrow1 - mn1);
        mrow0 = mn0; mrow1 = mn1;

        float s0 = 0.f, s1 = 0.f;
        #pragma unroll
        for (int nt = 0; nt < 8; nt++) {
            float p0 = __expf(sacc[nt][0] - mn0);
            float p1 = __expf(sacc[nt][1] - mn0);
            float p2 = __expf(sacc[nt][2] - mn1);
            float p3 = __expf(sacc[nt][3] - mn1);
            s0 += p0 + p1; s1 += p2 + p3;
            *(__half2*)(pS + g * LDP_H + nt*8 + 2*t)       = __floats2half2_rn(p0, p1);
            *(__half2*)(pS + (g + 8) * LDP_H + nt*8 + 2*t) = __floats2half2_rn(p2, p3);
        }
        s0 += __shfl_xor_sync(0xffffffffu, s0, 1);
        s0 += __shfl_xor_sync(0xffffffffu, s0, 2);
        s1 += __shfl_xor_sync(0xffffffffu, s1, 1);
        s1 += __shfl_xor_sync(0xffffffffu, s1, 2);
        lrow0 = lrow0 * a0 + s0;
        lrow1 = lrow1 * a1 + s1;

        #pragma unroll
        for (int nt = 0; nt < 8; nt++) {
            oacc[nt][0] *= a0; oacc[nt][1] *= a0;
            oacc[nt][2] *= a1; oacc[nt][3] *= a1;
        }
        __syncwarp();

        #pragma unroll
        for (int ks = 0; ks < 4; ks++) {
            uint32_t a[4];
            ldsm4(a, pOff + ks * 32);
            #pragma unroll
            for (int p = 0; p < 4; p++) {
                uint32_t r[4];
                ldsm4t(r, vBase + vOff + ks * 16 * (LDV_H*2) + p * 32);
                uint32_t b0[2] = { r[0], r[1] };
                uint32_t b1[2] = { r[2], r[3] };
                mma16(oacc[2*p],   a, b0);
                mma16(oacc[2*p+1], a, b1);
            }
        }
    }

    float inv0 = 1.0f / lrow0, inv1 = 1.0f / lrow1;
    int mr0 = m0 + g, mr1 = m0 + g + 8;
    #pragma unroll
    for (int nt = 0; nt < 8; nt++) {
        int col = hh * DH_ + nt*8 + 2*t;
        *(__half2*)(g_ctxh + ((size_t)(bq * S_ + mr0)) * D_ + col) =
            __floats2half2_rn(oacc[nt][0] * inv0, oacc[nt][1] * inv0);
        *(__half2*)(g_ctxh + ((size_t)(bq * S_ + mr1)) * D_ + col) =
            __floats2half2_rn(oacc[nt][2] * inv1, oacc[nt][3] * inv1);
    }
}

// ---------------- fp16 mma.sync GEMM: 128x128 tile, K-chunk 64 ---------------
template<int MODE, int KK, int LDBG>
__global__ __launch_bounds__(128, 2)
void tgemm(const __half* __restrict__ Ag, const __half* __restrict__ Bg,
           const __half* __restrict__ Bg2, const __half* __restrict__ Bg3,
           const float* __restrict__ bias, const float* __restrict__ bias2,
           const float* __restrict__ bias3)
{
    constexpr int BN     = 128;
    constexpr int NC     = KK / 64;            // 64-half chunks
    constexpr int NT     = 8;
    constexpr int LDA_H  = 72;                 // halves; row = 144B
    constexpr int LDB_H  = 136;                // halves; row = 272B
    constexpr int ABYTES = 128 * LDA_H * 2;    // 18432
    constexpr int BBYTES = 64 * LDB_H * 2;     // 17408
    constexpr int STAGE  = ABYTES + BBYTES;    // 35840
    constexpr int CS     = BN + 4;
    constexpr int BF4    = BN / 4;

    extern __shared__ char smc[];
    __shared__ int rIdx[128];
    __shared__ int s_cnt;

    const int tid = threadIdx.x, wid = tid >> 5, lane = tid & 31;
    const int wr = wid >> 1, wc = wid & 1;
    const int g = lane >> 2, t = lane & 3;
    const int mBase = blockIdx.y * 128, nBase = blockIdx.x * BN, z = blockIdx.z;
    const int e = (MODE >= 4) ? (mBase >> 11) : 0;

    if (MODE == 4 || MODE == 5) {
        if (tid == 0) s_cnt = g_cnt[e];
        __syncthreads();
        if ((mBase & (CAP_-1)) >= s_cnt) return;
    }

    const __half* A; const __half* Bp; const float* biasp = bias;
    if      (MODE == 0) { A = Ag; Bp = (z==0)?Bg:((z==1)?Bg2:Bg3);
                          biasp = (z==0)?bias:((z==1)?bias2:bias3); }
    else if (MODE == 3) { A = g_ctxh;  Bp = Bg; }
    else if (MODE == 4) { A = g_atth;  Bp = Bg + (size_t)e * D_ * FF_; }
    else                { A = g_hh;    Bp = Bg + (size_t)e * FF_ * D_; }

    {
        int m = mBase + tid, r = m;
        if (MODE == 4) {
            int pos = m & (CAP_-1);
            r = (pos < s_cnt) ? g_tokmap[e*CAP_ + pos] : 0;
        }
        rIdx[tid] = r;
    }
    __syncthreads();

    uint32_t sU = (uint32_t)__cvta_generic_to_shared(smc);
    const uint32_t aOff = (uint32_t)((wr*64 + (lane & 15)) * (LDA_H*2)) + ((lane >> 4) << 4);
    const uint32_t bOff = (uint32_t)((lane & 15) * (LDB_H*2)) + ((lane >> 4) << 4);

    auto issue = [&](int cix) {
        const int stg = cix & 1;
        const int k0 = cix * 64;
        const uint32_t aB = sU + stg * STAGE;
        #pragma unroll
        for (int i = 0; i < 8; i++) {
            int idx = tid + i * 128;
            int row = idx >> 3, c4 = idx & 7;
            cpa16(aB + row * (LDA_H*2) + c4 * 16,
                  A + (size_t)rIdx[row] * KK + k0 + c4 * 8);
        }
        const uint32_t bB = aB + ABYTES;
        #pragma unroll
        for (int i = 0; i < 8; i++) {
            int idx = tid + i * 128;
            int row = idx >> 4, c4 = idx & 15;
            cpa16(bB + row * (LDB_H*2) + c4 * 16,
                  Bp + (size_t)(k0 + row) * LDBG + nBase + c4 * 8);
        }
        cpa_commit();
    };

    float acc[4][NT][4];
    #pragma unroll
    for (int i = 0; i < 4; i++)
        #pragma unroll
        for (int j = 0; j < NT; j++)
            #pragma unroll
            for (int q = 0; q < 4; q++) acc[i][j][q] = 0.f;

    issue(0);
    for (int c = 0; c < NC; c++) {
        cpa_wait0();
        __syncthreads();
        if (c + 1 < NC) issue(c + 1);

        const int stg = c & 1;
        const uint32_t aBase = sU + stg * STAGE + aOff;
        const uint32_t bBase = sU + stg * STAGE + ABYTES + bOff + wc * 128;
        #pragma unroll
        for (int ks = 0; ks < 4; ks++) {       // four k16 steps per 64-half chunk
            uint32_t a[4][4];
            #pragma unroll
            for (int mt = 0; mt < 4; mt++)
                ldsm4(a[mt], aBase + mt * 16 * (LDA_H*2) + ks * 32);
            uint32_t b[NT][2];
            #pragma unroll
            for (int p = 0; p < 4; p++) {
                uint32_t r[4];
                ldsm4t(r, bBase + ks * 16 * (LDB_H*2) + p * 32);
                b[2*p][0]   = r[0]; b[2*p][1]   = r[1];
                b[2*p+1][0] = r[2]; b[2*p+1][1] = r[3];
            }
            #pragma unroll
            for (int mt = 0; mt < 4; mt++)
                #pragma unroll
                for (int nt = 0; nt < NT; nt++)
                    mma16(acc[mt][nt], a[mt], b[nt]);
        }
    }
    __syncthreads();

    // ---------------- epilogue ----------------
    float* cSf = (float*)smc;
    #pragma unroll
    for (int mt = 0; mt < 4; mt++) {
        #pragma unroll
        for (int nt = 0; nt < NT; nt++) {
            int r = wr*64 + mt*16 + g;
            int n = wc*64 + nt*8 + 2*t;
            *(float2*)(cSf + r*CS + n)     = make_float2(acc[mt][nt][0], acc[mt][nt][1]);
            *(float2*)(cSf + (r+8)*CS + n) = make_float2(acc[mt][nt][2], acc[mt][nt][3]);
        }
    }
    __syncthreads();

    constexpr int IT = (128 * BF4) / 128;
    #pragma unroll
    for (int it = 0; it < IT; it++) {
        int idx = it * 128 + tid;
        int row = idx / BF4, q = idx % BF4;
        float4 v = *(const float4*)(cSf + row*CS + q*4);
        int m  = mBase + row;
        int n0 = nBase + q*4;

        if (MODE == 0) {
            v.x += biasp[n0]; v.y += biasp[n0+1]; v.z += biasp[n0+2]; v.w += biasp[n0+3];
            int b = m >> 10, srow = m & 1023, hh = n0 >> 6, dh = n0 & 63;
            __half* dst = (z == 0) ? g_qh : ((z == 1) ? g_kh : g_vh);
            __half* p = dst + (((size_t)(b*H_ + hh)) * S_ + srow) * DH_ + dh;
            *(__half2*)(p)     = __floats2half2_rn(v.x, v.y);
            *(__half2*)(p + 2) = __floats2half2_rn(v.z, v.w);
        } else if (MODE == 3) {
            *(float4*)(g_tmp + (size_t)m * D_ + n0) = v;
        } else if (MODE == 4) {
            int pos = m & (CAP_-1);
            if (pos < s_cnt) {
                const float4 bb = *(const float4*)(bias + (size_t)e*FF_ + n0);
                __half* dst = g_hh + (size_t)m * FF_ + n0;
                *(__half2*)(dst)     = __floats2half2_rn(gelu_f(v.x+bb.x), gelu_f(v.y+bb.y));
                *(__half2*)(dst + 2) = __floats2half2_rn(gelu_f(v.z+bb.z), gelu_f(v.w+bb.w));
            }
        } else {
            int pos = m & (CAP_-1);
            if (pos < s_cnt) {
                int tok = g_tokmap[e*CAP_ + pos];
                float gsc = g_gate[tok];
                const float4 bb = *(const float4*)(bias + (size_t)e*D_ + n0);
                *(float4*)(g_ffn + (size_t)tok * D_ + n0) =
                    make_float4((v.x+bb.x)*gsc, (v.y+bb.y)*gsc,
                                (v.z+bb.z)*gsc, (v.w+bb.w)*gsc);
            }
        }
    }
}

// ---------------- layernorm (optional fp16 mirror output) --------------------
__global__ __launch_bounds__(256) void ln_kernel(
        const float* __restrict__ a, const float* __restrict__ bsum,
        const float* __restrict__ bias,
        const float* __restrict__ g, const float* __restrict__ beta,
        float* __restrict__ out, __half* __restrict__ outh)
{
    __shared__ float red[256];
    const int t = blockIdx.x, tid = threadIdx.x;
    const float* ap = a    + (size_t)t * D_;
    const float* bp = bsum + (size_t)t * D_;
    float v[3]; float s = 0.f;
    #pragma unroll
    for (int j=0;j<3;j++) {
        int i = tid + j*256;
        float x = ap[i] + bp[i];
        if (bias) x += bias[i];
        v[j] = x; s += x;
    }
    red[tid]=s; __syncthreads();
    for (int st=128; st>0; st>>=1) { if (tid<st) red[tid]+=red[tid+st]; __syncthreads(); }
    float mu = red[0] * (1.0f/768.0f);
    __syncthreads();
    float q = 0.f;
    #pragma unroll
    for (int j=0;j<3;j++) { float d = v[j]-mu; q += d*d; }
    red[tid]=q; __syncthreads();
    for (int st=128; st>0; st>>=1) { if (tid<st) red[tid]+=red[tid+st]; __syncthreads(); }
    float inv = rsqrtf(red[0]*(1.0f/768.0f) + 1e-12f);
    #pragma unroll
    for (int j=0;j<3;j++) {
        int i = tid + j*256;
        float y = (v[j]-mu)*inv*g[i] + beta[i];
        out[(size_t)t*D_ + i] = y;
        if (outh) outh[(size_t)t*D_ + i] = __float2half_rn(y);
    }
}

// ---------------- router ------------------------------------------------------
__global__ __launch_bounds__(256) void router_kernel(
        const float* __restrict__ Wr, const float* __restrict__ br)
{
    int warp = (blockIdx.x * blockDim.x + threadIdx.x) >> 5;
    int lane = threadIdx.x & 31;
    if (warp >= T_) return;
    const float* xrow = g_att + (size_t)warp * D_;
    float acc[E_];
    #pragma unroll
    for (int e=0;e<E_;e++) acc[e]=0.f;
    for (int i = lane; i < D_; i += 32) {
        float x = xrow[i];
        const float* w = Wr + i*E_;
        #pragma unroll
        for (int e=0;e<E_;e++) acc[e] += x * w[e];
    }
    #pragma unroll
    for (int e=0;e<E_;e++)
        #pragma unroll
        for (int o=16;o>0;o>>=1)
            acc[e] += __shfl_xor_sync(0xffffffffu, acc[e], o);
    if (lane == 0) {
        float best = -1e30f; int be = 0;
        #pragma unroll
        for (int e=0;e<E_;e++) {
            float l = acc[e] + br[e];
            acc[e] = l;
            if (l > best) { best = l; be = e; }
        }
        float sm = 0.f;
        #pragma unroll
        for (int e=0;e<E_;e++) sm += expf(acc[e] - best);
        float gate = 1.0f / sm;
        int pos = atomicAdd(&g_cnt[be], 1);
        if (pos < CAP_) {
            g_tokmap[be*CAP_ + pos] = warp;
            g_gate[warp] = gate;
        }
    }
}

__global__ void zero_small() {
    if (threadIdx.x < E_) g_cnt[threadIdx.x] = 0;
}

// ---------------- launch ------------------------------------------------------
extern "C" void kernel_launch(void* const* d_in, const int* in_sizes, int n_in,
                              void* d_out, int out_size) {
    const float* x    = (const float*)d_in[0];
    const float* mask = (const float*)d_in[1];
    const float* Wq   = (const float*)d_in[2];
    const float* bq   = (const float*)d_in[3];
    const float* Wk   = (const float*)d_in[4];
    const float* bk   = (const float*)d_in[5];
    const float* Wv   = (const float*)d_in[6];
    const float* bv   = (const float*)d_in[7];
    const float* Wo   = (const float*)d_in[8];
    const float* bo   = (const float*)d_in[9];
    const float* ln1g = (const float*)d_in[10];
    const float* ln1b = (const float*)d_in[11];
    const float* Wr   = (const float*)d_in[12];
    const float* br   = (const float*)d_in[13];
    const float* W1   = (const float*)d_in[14];
    const float* b1   = (const float*)d_in[15];
    const float* W2   = (const float*)d_in[16];
    const float* b2   = (const float*)d_in[17];
    const float* ln2g = (const float*)d_in[18];
    const float* ln2b = (const float*)d_in[19];
    float* out = (float*)d_out;

    float *p_tmp, *p_att, *p_ffn;
    __half *p_xh, *p_wqh, *p_wkh, *p_wvh, *p_woh, *p_w1h, *p_w2h, *p_atth;
    cudaGetSymbolAddress((void**)&p_tmp, g_tmp);
    cudaGetSymbolAddress((void**)&p_att, g_att);
    cudaGetSymbolAddress((void**)&p_ffn, g_ffn);
    cudaGetSymbolAddress((void**)&p_xh,  g_xh);
    cudaGetSymbolAddress((void**)&p_wqh, g_wqh);
    cudaGetSymbolAddress((void**)&p_wkh, g_wkh);
    cudaGetSymbolAddress((void**)&p_wvh, g_wvh);
    cudaGetSymbolAddress((void**)&p_woh, g_woh);
    cudaGetSymbolAddress((void**)&p_w1h, g_w1h);
    cudaGetSymbolAddress((void**)&p_w2h, g_w2h);
    cudaGetSymbolAddress((void**)&p_atth, g_atth);

    constexpr int SH_G  = 2 * 35840;                           // 71680
    constexpr int SH_FA = 2 * 18688 + 8*16*72*2;               // 55808
    cudaFuncSetAttribute((const void*)tgemm<0,768,768>,   cudaFuncAttributeMaxDynamicSharedMemorySize, SH_G);
    cudaFuncSetAttribute((const void*)tgemm<3,768,768>,   cudaFuncAttributeMaxDynamicSharedMemorySize, SH_G);
    cudaFuncSetAttribute((const void*)tgemm<4,768,3072>,  cudaFuncAttributeMaxDynamicSharedMemorySize, SH_G);
    cudaFuncSetAttribute((const void*)tgemm<5,3072,768>,  cudaFuncAttributeMaxDynamicSharedMemorySize, SH_G);
    cudaFuncSetAttribute((const void*)fattn, cudaFuncAttributeMaxDynamicSharedMemorySize, SH_FA);

    // launch order arranged so the 6th launch (ncu -s 5 -c 1) is tgemm<0>
    zero_small<<<1, 32>>>();                                           // 1
    f2h<<<(T_*D_/4 + 255)/256, 256>>>(x,  p_xh,  T_*D_/4);             // 2
    f2h<<<(D_*D_/4 + 255)/256, 256>>>(Wq, p_wqh, D_*D_/4);             // 3
    f2h<<<(D_*D_/4 + 255)/256, 256>>>(Wk, p_wkh, D_*D_/4);             // 4
    f2h<<<(D_*D_/4 + 255)/256, 256>>>(Wv, p_wvh, D_*D_/4);             // 5

    // fused QKV projections (fp16 in, fp16 q/k/v out)                 // 6 <- profiled
    tgemm<0,768,768><<<dim3(6,64,3), 128, SH_G>>>(p_xh, p_wqh, p_wkh, p_wvh, bq, bk, bv);

    // fused flash attention (fp16 MMA) -> g_ctxh
    fattn<<<dim3(8, 96), 256, SH_FA>>>(mask);

    // att = LN1(x + ctxh@Wo + bo) ; fp16 mirror for MoE
    f2h<<<(D_*D_/4 + 255)/256, 256>>>(Wo, p_woh, D_*D_/4);
    tgemm<3,768,768><<<dim3(6,64,1), 128, SH_G>>>(nullptr, p_woh, nullptr, nullptr, nullptr, nullptr, nullptr);
    ln_kernel<<<T_, 256>>>(x, p_tmp, bo, ln1g, ln1b, p_att, p_atth);

    // router + MoE (fp16 operands, fp32 accum)
    router_kernel<<<T_/8, 256>>>(Wr, br);
    f2h<<<(E_*D_*FF_/4 + 255)/256, 256>>>(W1, p_w1h, E_*D_*FF_/4);
    tgemm<4,768,3072><<<dim3(FF_/128, (E_*CAP_)/128, 1), 128, SH_G>>>(nullptr, p_w1h, nullptr, nullptr, b1, nullptr, nullptr);
    f2h<<<(E_*FF_*D_/4 + 255)/256, 256>>>(W2, p_w2h, E_*FF_*D_/4);
    tgemm<5,3072,768><<<dim3(D_/128, (E_*CAP_)/128, 1), 128, SH_G>>>(nullptr, p_w2h, nullptr, nullptr, b2, nullptr, nullptr);

    // out = LN2(att + ffn)
    ln_kernel<<<T_, 256>>>(p_att, p_ffn, nullptr, ln2g, ln2b, out, nullptr);
}

// round 14
// speedup vs baseline: 1.8706x; 1.0292x over previous
#include <cuda_runtime.h>
#include <cuda_fp16.h>
#include <cstdint>
#include <math.h>

#define B_  8
#define S_  1024
#define D_  768
#define H_  12
#define DH_ 64
#define FF_ 3072
#define E_  8
#define CAP_ 2048
#define T_  8192

// ---------------- scratch (device globals) ----------------------------------
__device__ float  g_tmp[T_*D_];
__device__ float  g_att[T_*D_];
__device__ float  g_ffn[T_*D_];
__device__ int    g_cnt[E_];
__device__ int    g_tokmap[E_*CAP_];
__device__ float  g_gate[T_];
// fp16 tensors
__device__ __half g_qh[B_*H_*S_*DH_];
__device__ __half g_kh[B_*H_*S_*DH_];
__device__ __half g_vh[B_*H_*S_*DH_];
__device__ __half g_xh[T_*D_];
__device__ __half g_wqh[D_*D_];
__device__ __half g_wkh[D_*D_];
__device__ __half g_wvh[D_*D_];
__device__ __half g_woh[D_*D_];
__device__ __half g_w1h[E_*D_*FF_];
__device__ __half g_w2h[E_*FF_*D_];
__device__ __half g_atth[T_*D_];
__device__ __half g_ctxh[T_*D_];
__device__ __half g_hh[50331648];          // E*CAP*FF fp16

__device__ __forceinline__ float gelu_f(float x) {
    return 0.5f * x * (1.0f + erff(x * 0.70710678118654752f));
}

__device__ __forceinline__ void cpa16(uint32_t dst, const void* src) {
    asm volatile("cp.async.ca.shared.global [%0], [%1], 16;" :: "r"(dst), "l"(src));
}
__device__ __forceinline__ void cpa_commit() {
    asm volatile("cp.async.commit_group;" ::: "memory");
}
__device__ __forceinline__ void cpa_wait0() {
    asm volatile("cp.async.wait_group 0;" ::: "memory");
}
__device__ __forceinline__ void mma16(float* c, const uint32_t* a, const uint32_t* b) {
    asm volatile(
        "mma.sync.aligned.m16n8k16.row.col.f32.f16.f16.f32 "
        "{%0,%1,%2,%3}, {%4,%5,%6,%7}, {%8,%9}, {%0,%1,%2,%3};\n"
        : "+f"(c[0]), "+f"(c[1]), "+f"(c[2]), "+f"(c[3])
        : "r"(a[0]), "r"(a[1]), "r"(a[2]), "r"(a[3]), "r"(b[0]), "r"(b[1]));
}
__device__ __forceinline__ void ldsm4(uint32_t* r, uint32_t addr) {
    asm volatile("ldmatrix.sync.aligned.m8n8.x4.b16 {%0,%1,%2,%3}, [%4];"
                 : "=r"(r[0]), "=r"(r[1]), "=r"(r[2]), "=r"(r[3]) : "r"(addr));
}
__device__ __forceinline__ void ldsm4t(uint32_t* r, uint32_t addr) {
    asm volatile("ldmatrix.sync.aligned.m8n8.x4.trans.shared.b16 {%0,%1,%2,%3}, [%4];"
                 : "=r"(r[0]), "=r"(r[1]), "=r"(r[2]), "=r"(r[3]) : "r"(addr));
}

// ---------------- fp32 -> fp16 conversions ------------------------------------
__global__ void f2h(const float* __restrict__ s, __half* __restrict__ d, int n4) {
    int i = blockIdx.x * blockDim.x + threadIdx.x;
    if (i >= n4) return;
    float4 v = ((const float4*)s)[i];
    ((__half2*)d)[i*2]   = __floats2half2_rn(v.x, v.y);
    ((__half2*)d)[i*2+1] = __floats2half2_rn(v.z, v.w);
}
// merged small conversions: x (N4X) + 4 weight matrices (N4W each)
__global__ void f2h5(const float* __restrict__ x,  __half* dx,
                     const float* __restrict__ w0, __half* d0,
                     const float* __restrict__ w1, __half* d1,
                     const float* __restrict__ w2, __half* d2,
                     const float* __restrict__ w3, __half* d3) {
    constexpr int N4X = T_*D_/4, N4W = D_*D_/4;
    int i = blockIdx.x * blockDim.x + threadIdx.x;
    const float* s; __half* d; int j;
    if (i < N4X)            { s = x;  d = dx; j = i; }
    else if (i < N4X+N4W)   { s = w0; d = d0; j = i - N4X; }
    else if (i < N4X+2*N4W) { s = w1; d = d1; j = i - N4X - N4W; }
    else if (i < N4X+3*N4W) { s = w2; d = d2; j = i - N4X - 2*N4W; }
    else if (i < N4X+4*N4W) { s = w3; d = d3; j = i - N4X - 3*N4W; }
    else return;
    float4 v = ((const float4*)s)[j];
    ((__half2*)d)[j*2]   = __floats2half2_rn(v.x, v.y);
    ((__half2*)d)[j*2+1] = __floats2half2_rn(v.z, v.w);
}

// ================= fused flash attention (fp16 MMA, register P) ==============
__global__ __launch_bounds__(256) void fattn(const float* __restrict__ mask)
{
    constexpr int LDK_H = 72, LDV_H = 72;
    constexpr int KBYTES = 64 * LDK_H * 2;
    constexpr int VBYTES = 64 * LDV_H * 2;
    constexpr int MBYTES = 256;
    constexpr int STAGE  = KBYTES + VBYTES + MBYTES;
    extern __shared__ char smc[];

    const int tid = threadIdx.x, wid = tid >> 5, lane = tid & 31;
    const int g = lane >> 2, t = lane & 3;
    const int z = blockIdx.y, mBase = blockIdx.x * 128;
    const int bq = z / H_, hh = z % H_;
    const int m0 = mBase + wid * 16;

    const __half* Qp = g_qh + (size_t)z * S_ * DH_;
    const __half* Kp = g_kh + (size_t)z * S_ * DH_;
    const __half* Vp = g_vh + (size_t)z * S_ * DH_;

    const __half2 sc8 = __half2half2(__float2half(0.125f));
    uint32_t qf[4][4];
    #pragma unroll
    for (int ks = 0; ks < 4; ks++) {
        __half2 h0 = __hmul2(*(const __half2*)&Qp[(m0 + g)     * DH_ + ks*16 + 2*t],     sc8);
        __half2 h1 = __hmul2(*(const __half2*)&Qp[(m0 + g + 8) * DH_ + ks*16 + 2*t],     sc8);
        __half2 h2 = __hmul2(*(const __half2*)&Qp[(m0 + g)     * DH_ + ks*16 + 2*t + 8], sc8);
        __half2 h3 = __hmul2(*(const __half2*)&Qp[(m0 + g + 8) * DH_ + ks*16 + 2*t + 8], sc8);
        qf[ks][0] = *(uint32_t*)&h0; qf[ks][1] = *(uint32_t*)&h1;
        qf[ks][2] = *(uint32_t*)&h2; qf[ks][3] = *(uint32_t*)&h3;
    }

    float oacc[8][4];
    #pragma unroll
    for (int nt = 0; nt < 8; nt++)
        #pragma unroll
        for (int q = 0; q < 4; q++) oacc[nt][q] = 0.f;
    float mrow0 = -1e30f, mrow1 = -1e30f, lrow0 = 0.f, lrow1 = 0.f;

    uint32_t sU = (uint32_t)__cvta_generic_to_shared(smc);
    const uint32_t lmRow = (lane & 15);
    const uint32_t lmHalf = (lane >> 4) << 4;
    const uint32_t kOff = lmRow * (LDK_H*2) + lmHalf;
    const uint32_t vOff = lmRow * (LDV_H*2) + lmHalf;

    auto issue = [&](int kt) {
        const int stg = kt & 1;
        const uint32_t base = sU + stg * STAGE;
        #pragma unroll
        for (int i = 0; i < 2; i++) {
            int idx = tid + i * 256;
            int row = idx >> 3, c4 = idx & 7;
            cpa16(base + row * (LDK_H*2) + c4 * 16,
                  Kp + (size_t)(kt*64 + row) * DH_ + c4 * 8);
        }
        #pragma unroll
        for (int i = 0; i < 2; i++) {
            int idx = tid + i * 256;
            int row = idx >> 3, c4 = idx & 7;
            cpa16(base + KBYTES + row * (LDV_H*2) + c4 * 16,
                  Vp + (size_t)(kt*64 + row) * DH_ + c4 * 8);
        }
        if (tid < 16)
            cpa16(base + KBYTES + VBYTES + tid * 16, mask + bq * S_ + kt*64 + tid * 4);
        cpa_commit();
    };

    issue(0);
    for (int kt = 0; kt < 16; kt++) {
        cpa_wait0();
        __syncthreads();
        if (kt + 1 < 16) issue(kt + 1);

        const int stg = kt & 1;
        const uint32_t kBase = sU + stg * STAGE;
        const uint32_t vBase = kBase + KBYTES;
        const float* mS = (const float*)(smc + stg * STAGE + KBYTES + VBYTES);

        float sacc[8][4];
        #pragma unroll
        for (int nt = 0; nt < 8; nt++)
            #pragma unroll
            for (int q = 0; q < 4; q++) sacc[nt][q] = 0.f;
        #pragma unroll
        for (int ks = 0; ks < 4; ks++) {
            #pragma unroll
            for (int p = 0; p < 4; p++) {
                uint32_t r[4];
                ldsm4(r, kBase + kOff + p * 16 * (LDK_H*2) + ks * 32);
                uint32_t b0[2] = { r[0], r[2] };
                uint32_t b1[2] = { r[1], r[3] };
                mma16(sacc[2*p],   qf[ks], b0);
                mma16(sacc[2*p+1], qf[ks], b1);
            }
        }

        float mx0 = -1e30f, mx1 = -1e30f;
        #pragma unroll
        for (int nt = 0; nt < 8; nt++) {
            float mk0 = mS[nt*8 + 2*t], mk1 = mS[nt*8 + 2*t + 1];
            sacc[nt][0] += mk0;
            sacc[nt][1] += mk1;
            sacc[nt][2] += mk0;
            sacc[nt][3] += mk1;
            mx0 = fmaxf(mx0, fmaxf(sacc[nt][0], sacc[nt][1]));
            mx1 = fmaxf(mx1, fmaxf(sacc[nt][2], sacc[nt][3]));
        }
        mx0 = fmaxf(mx0, __shfl_xor_sync(0xffffffffu, mx0, 1));
        mx0 = fmaxf(mx0, __shfl_xor_sync(0xffffffffu, mx0, 2));
        mx1 = fmaxf(mx1, __shfl_xor_sync(0xffffffffu, mx1, 1));
        mx1 = fmaxf(mx1, __shfl_xor_sync(0xffffffffu, mx1, 2));

        float mn0 = fmaxf(mrow0, mx0), mn1 = fmaxf(mrow1, mx1);
        float a0 = __expf(mrow0 - mn0), a1 = __expf(mrow1 - mn1);
        mrow0 = mn0; mrow1 = mn1;

        // exp -> P fragments held in registers (exact A-fragment layout for PV)
        uint32_t pf0[8], pf1[8];
        float s0 = 0.f, s1 = 0.f;
        #pragma unroll
        for (int nt = 0; nt < 8; nt++) {
            float p0 = __expf(sacc[nt][0] - mn0);
            float p1 = __expf(sacc[nt][1] - mn0);
            float p2 = __expf(sacc[nt][2] - mn1);
            float p3 = __expf(sacc[nt][3] - mn1);
            s0 += p0 + p1; s1 += p2 + p3;
            __half2 hA = __floats2half2_rn(p0, p1);
            __half2 hB = __floats2half2_rn(p2, p3);
            pf0[nt] = *(uint32_t*)&hA;
            pf1[nt] = *(uint32_t*)&hB;
        }
        s0 += __shfl_xor_sync(0xffffffffu, s0, 1);
        s0 += __shfl_xor_sync(0xffffffffu, s0, 2);
        s1 += __shfl_xor_sync(0xffffffffu, s1, 1);
        s1 += __shfl_xor_sync(0xffffffffu, s1, 2);
        lrow0 = lrow0 * a0 + s0;
        lrow1 = lrow1 * a1 + s1;

        #pragma unroll
        for (int nt = 0; nt < 8; nt++) {
            oacc[nt][0] *= a0; oacc[nt][1] *= a0;
            oacc[nt][2] *= a1; oacc[nt][3] *= a1;
        }

        // ---- P @ V (P fragments from registers; V via ldsm4t) ----
        #pragma unroll
        for (int ks = 0; ks < 4; ks++) {
            uint32_t a[4] = { pf0[2*ks], pf1[2*ks], pf0[2*ks+1], pf1[2*ks+1] };
            #pragma unroll
            for (int p = 0; p < 4; p++) {
                uint32_t r[4];
                ldsm4t(r, vBase + vOff + ks * 16 * (LDV_H*2) + p * 32);
                uint32_t b0[2] = { r[0], r[1] };
                uint32_t b1[2] = { r[2], r[3] };
                mma16(oacc[2*p],   a, b0);
                mma16(oacc[2*p+1], a, b1);
            }
        }
    }

    float inv0 = 1.0f / lrow0, inv1 = 1.0f / lrow1;
    int mr0 = m0 + g, mr1 = m0 + g + 8;
    #pragma unroll
    for (int nt = 0; nt < 8; nt++) {
        int col = hh * DH_ + nt*8 + 2*t;
        *(__half2*)(g_ctxh + ((size_t)(bq * S_ + mr0)) * D_ + col) =
            __floats2half2_rn(oacc[nt][0] * inv0, oacc[nt][1] * inv0);
        *(__half2*)(g_ctxh + ((size_t)(bq * S_ + mr1)) * D_ + col) =
            __floats2half2_rn(oacc[nt][2] * inv1, oacc[nt][3] * inv1);
    }
}

// ---------------- fp16 mma.sync GEMM: 128x128 tile, K-chunk 64 ---------------
template<int MODE, int KK, int LDBG>
__global__ __launch_bounds__(128, 2)
void tgemm(const __half* __restrict__ Ag, const __half* __restrict__ Bg,
           const __half* __restrict__ Bg2, const __half* __restrict__ Bg3,
           const float* __restrict__ bias, const float* __restrict__ bias2,
           const float* __restrict__ bias3)
{
    constexpr int BN     = 128;
    constexpr int NC     = KK / 64;
    constexpr int NT     = 8;
    constexpr int LDA_H  = 72;
    constexpr int LDB_H  = 136;
    constexpr int ABYTES = 128 * LDA_H * 2;
    constexpr int BBYTES = 64 * LDB_H * 2;
    constexpr int STAGE  = ABYTES + BBYTES;
    constexpr int CS     = BN + 4;
    constexpr int BF4    = BN / 4;

    extern __shared__ char smc[];
    __shared__ int rIdx[128];
    __shared__ int s_cnt;

    const int tid = threadIdx.x, wid = tid >> 5, lane = tid & 31;
    const int wr = wid >> 1, wc = wid & 1;
    const int g = lane >> 2, t = lane & 3;
    const int mBase = blockIdx.y * 128, nBase = blockIdx.x * BN, z = blockIdx.z;
    const int e = (MODE >= 4) ? (mBase >> 11) : 0;

    if (MODE == 4 || MODE == 5) {
        if (tid == 0) s_cnt = g_cnt[e];
        __syncthreads();
        if ((mBase & (CAP_-1)) >= s_cnt) return;
    }

    const __half* A; const __half* Bp; const float* biasp = bias;
    if      (MODE == 0) { A = Ag; Bp = (z==0)?Bg:((z==1)?Bg2:Bg3);
                          biasp = (z==0)?bias:((z==1)?bias2:bias3); }
    else if (MODE == 3) { A = g_ctxh;  Bp = Bg; }
    else if (MODE == 4) { A = g_atth;  Bp = Bg + (size_t)e * D_ * FF_; }
    else                { A = g_hh;    Bp = Bg + (size_t)e * FF_ * D_; }

    {
        int m = mBase + tid, r = m;
        if (MODE == 4) {
            int pos = m & (CAP_-1);
            r = (pos < s_cnt) ? g_tokmap[e*CAP_ + pos] : 0;
        }
        rIdx[tid] = r;
    }
    __syncthreads();

    uint32_t sU = (uint32_t)__cvta_generic_to_shared(smc);
    const uint32_t aOff = (uint32_t)((wr*64 + (lane & 15)) * (LDA_H*2)) + ((lane >> 4) << 4);
    const uint32_t bOff = (uint32_t)((lane & 15) * (LDB_H*2)) + ((lane >> 4) << 4);

    auto issue = [&](int cix) {
        const int stg = cix & 1;
        const int k0 = cix * 64;
        const uint32_t aB = sU + stg * STAGE;
        #pragma unroll
        for (int i = 0; i < 8; i++) {
            int idx = tid + i * 128;
            int row = idx >> 3, c4 = idx & 7;
            cpa16(aB + row * (LDA_H*2) + c4 * 16,
                  A + (size_t)rIdx[row] * KK + k0 + c4 * 8);
        }
        const uint32_t bB = aB + ABYTES;
        #pragma unroll
        for (int i = 0; i < 8; i++) {
            int idx = tid + i * 128;
            int row = idx >> 4, c4 = idx & 15;
            cpa16(bB + row * (LDB_H*2) + c4 * 16,
                  Bp + (size_t)(k0 + row) * LDBG + nBase + c4 * 8);
        }
        cpa_commit();
    };

    float acc[4][NT][4];
    #pragma unroll
    for (int i = 0; i < 4; i++)
        #pragma unroll
        for (int j = 0; j < NT; j++)
            #pragma unroll
            for (int q = 0; q < 4; q++) acc[i][j][q] = 0.f;

    issue(0);
    for (int c = 0; c < NC; c++) {
        cpa_wait0();
        __syncthreads();
        if (c + 1 < NC) issue(c + 1);

        const int stg = c & 1;
        const uint32_t aBase = sU + stg * STAGE + aOff;
        const uint32_t bBase = sU + stg * STAGE + ABYTES + bOff + wc * 128;
        #pragma unroll
        for (int ks = 0; ks < 4; ks++) {
            uint32_t a[4][4];
            #pragma unroll
            for (int mt = 0; mt < 4; mt++)
                ldsm4(a[mt], aBase + mt * 16 * (LDA_H*2) + ks * 32);
            uint32_t b[NT][2];
            #pragma unroll
            for (int p = 0; p < 4; p++) {
                uint32_t r[4];
                ldsm4t(r, bBase + ks * 16 * (LDB_H*2) + p * 32);
                b[2*p][0]   = r[0]; b[2*p][1]   = r[1];
                b[2*p+1][0] = r[2]; b[2*p+1][1] = r[3];
            }
            #pragma unroll
            for (int mt = 0; mt < 4; mt++)
                #pragma unroll
                for (int nt = 0; nt < NT; nt++)
                    mma16(acc[mt][nt], a[mt], b[nt]);
        }
    }
    __syncthreads();

    // ---------------- epilogue ----------------
    float* cSf = (float*)smc;
    #pragma unroll
    for (int mt = 0; mt < 4; mt++) {
        #pragma unroll
        for (int nt = 0; nt < NT; nt++) {
            int r = wr*64 + mt*16 + g;
            int n = wc*64 + nt*8 + 2*t;
            *(float2*)(cSf + r*CS + n)     = make_float2(acc[mt][nt][0], acc[mt][nt][1]);
            *(float2*)(cSf + (r+8)*CS + n) = make_float2(acc[mt][nt][2], acc[mt][nt][3]);
        }
    }
    __syncthreads();

    constexpr int IT = (128 * BF4) / 128;
    #pragma unroll
    for (int it = 0; it < IT; it++) {
        int idx = it * 128 + tid;
        int row = idx / BF4, q = idx % BF4;
        float4 v = *(const float4*)(cSf + row*CS + q*4);
        int m  = mBase + row;
        int n0 = nBase + q*4;

        if (MODE == 0) {
            v.x += biasp[n0]; v.y += biasp[n0+1]; v.z += biasp[n0+2]; v.w += biasp[n0+3];
            int b = m >> 10, srow = m & 1023, hh = n0 >> 6, dh = n0 & 63;
            __half* dst = (z == 0) ? g_qh : ((z == 1) ? g_kh : g_vh);
            __half* p = dst + (((size_t)(b*H_ + hh)) * S_ + srow) * DH_ + dh;
            *(__half2*)(p)     = __floats2half2_rn(v.x, v.y);
            *(__half2*)(p + 2) = __floats2half2_rn(v.z, v.w);
        } else if (MODE == 3) {
            *(float4*)(g_tmp + (size_t)m * D_ + n0) = v;
        } else if (MODE == 4) {
            int pos = m & (CAP_-1);
            if (pos < s_cnt) {
                const float4 bb = *(const float4*)(bias + (size_t)e*FF_ + n0);
                __half* dst = g_hh + (size_t)m * FF_ + n0;
                *(__half2*)(dst)     = __floats2half2_rn(gelu_f(v.x+bb.x), gelu_f(v.y+bb.y));
                *(__half2*)(dst + 2) = __floats2half2_rn(gelu_f(v.z+bb.z), gelu_f(v.w+bb.w));
            }
        } else {
            int pos = m & (CAP_-1);
            if (pos < s_cnt) {
                int tok = g_tokmap[e*CAP_ + pos];
                float gsc = g_gate[tok];
                const float4 bb = *(const float4*)(bias + (size_t)e*D_ + n0);
                *(float4*)(g_ffn + (size_t)tok * D_ + n0) =
                    make_float4((v.x+bb.x)*gsc, (v.y+bb.y)*gsc,
                                (v.z+bb.z)*gsc, (v.w+bb.w)*gsc);
            }
        }
    }
}

// ---------------- layernorm (optional fp16 mirror output) --------------------
__global__ __launch_bounds__(256) void ln_kernel(
        const float* __restrict__ a, const float* __restrict__ bsum,
        const float* __restrict__ bias,
        const float* __restrict__ g, const float* __restrict__ beta,
        float* __restrict__ out, __half* __restrict__ outh)
{
    __shared__ float red[256];
    const int t = blockIdx.x, tid = threadIdx.x;
    const float* ap = a    + (size_t)t * D_;
    const float* bp = bsum + (size_t)t * D_;
    float v[3]; float s = 0.f;
    #pragma unroll
    for (int j=0;j<3;j++) {
        int i = tid + j*256;
        float x = ap[i] + bp[i];
        if (bias) x += bias[i];
        v[j] = x; s += x;
    }
    red[tid]=s; __syncthreads();
    for (int st=128; st>0; st>>=1) { if (tid<st) red[tid]+=red[tid+st]; __syncthreads(); }
    float mu = red[0] * (1.0f/768.0f);
    __syncthreads();
    float q = 0.f;
    #pragma unroll
    for (int j=0;j<3;j++) { float d = v[j]-mu; q += d*d; }
    red[tid]=q; __syncthreads();
    for (int st=128; st>0; st>>=1) { if (tid<st) red[tid]+=red[tid+st]; __syncthreads(); }
    float inv = rsqrtf(red[0]*(1.0f/768.0f) + 1e-12f);
    #pragma unroll
    for (int j=0;j<3;j++) {
        int i = tid + j*256;
        float y = (v[j]-mu)*inv*g[i] + beta[i];
        out[(size_t)t*D_ + i] = y;
        if (outh) outh[(size_t)t*D_ + i] = __float2half_rn(y);
    }
}

// ---------------- router ------------------------------------------------------
__global__ __launch_bounds__(256) void router_kernel(
        const float* __restrict__ Wr, const float* __restrict__ br)
{
    int warp = (blockIdx.x * blockDim.x + threadIdx.x) >> 5;
    int lane = threadIdx.x & 31;
    if (warp >= T_) return;
    const float* xrow = g_att + (size_t)warp * D_;
    float acc[E_];
    #pragma unroll
    for (int e=0;e<E_;e++) acc[e]=0.f;
    for (int i = lane; i < D_; i += 32) {
        float x = xrow[i];
        const float* w = Wr + i*E_;
        #pragma unroll
        for (int e=0;e<E_;e++) acc[e] += x * w[e];
    }
    #pragma unroll
    for (int e=0;e<E_;e++)
        #pragma unroll
        for (int o=16;o>0;o>>=1)
            acc[e] += __shfl_xor_sync(0xffffffffu, acc[e], o);
    if (lane == 0) {
        float best = -1e30f; int be = 0;
        #pragma unroll
        for (int e=0;e<E_;e++) {
            float l = acc[e] + br[e];
            acc[e] = l;
            if (l > best) { best = l; be = e; }
        }
        float sm = 0.f;
        #pragma unroll
        for (int e=0;e<E_;e++) sm += expf(acc[e] - best);
        float gate = 1.0f / sm;
        int pos = atomicAdd(&g_cnt[be], 1);
        if (pos < CAP_) {
            g_tokmap[be*CAP_ + pos] = warp;
            g_gate[warp] = gate;
        }
    }
}

__global__ void zero_small() {
    if (threadIdx.x < E_) g_cnt[threadIdx.x] = 0;
}

// ---------------- launch ------------------------------------------------------
extern "C" void kernel_launch(void* const* d_in, const int* in_sizes, int n_in,
                              void* d_out, int out_size) {
    const float* x    = (const float*)d_in[0];
    const float* mask = (const float*)d_in[1];
    const float* Wq   = (const float*)d_in[2];
    const float* bq   = (const float*)d_in[3];
    const float* Wk   = (const float*)d_in[4];
    const float* bk   = (const float*)d_in[5];
    const float* Wv   = (const float*)d_in[6];
    const float* bv   = (const float*)d_in[7];
    const float* Wo   = (const float*)d_in[8];
    const float* bo   = (const float*)d_in[9];
    const float* ln1g = (const float*)d_in[10];
    const float* ln1b = (const float*)d_in[11];
    const float* Wr   = (const float*)d_in[12];
    const float* br   = (const float*)d_in[13];
    const float* W1   = (const float*)d_in[14];
    const float* b1   = (const float*)d_in[15];
    const float* W2   = (const float*)d_in[16];
    const float* b2   = (const float*)d_in[17];
    const float* ln2g = (const float*)d_in[18];
    const float* ln2b = (const float*)d_in[19];
    float* out = (float*)d_out;

    float *p_tmp, *p_att, *p_ffn;
    __half *p_xh, *p_wqh, *p_wkh, *p_wvh, *p_woh, *p_w1h, *p_w2h, *p_atth;
    cudaGetSymbolAddress((void**)&p_tmp, g_tmp);
    cudaGetSymbolAddress((void**)&p_att, g_att);
    cudaGetSymbolAddress((void**)&p_ffn, g_ffn);
    cudaGetSymbolAddress((void**)&p_xh,  g_xh);
    cudaGetSymbolAddress((void**)&p_wqh, g_wqh);
    cudaGetSymbolAddress((void**)&p_wkh, g_wkh);
    cudaGetSymbolAddress((void**)&p_wvh, g_wvh);
    cudaGetSymbolAddress((void**)&p_woh, g_woh);
    cudaGetSymbolAddress((void**)&p_w1h, g_w1h);
    cudaGetSymbolAddress((void**)&p_w2h, g_w2h);
    cudaGetSymbolAddress((void**)&p_atth, g_atth);

    constexpr int SH_G  = 2 * 35840;                 // 71680
    constexpr int SH_FA = 2 * 18688;                 // 37376
    cudaFuncSetAttribute((const void*)tgemm<0,768,768>,   cudaFuncAttributeMaxDynamicSharedMemorySize, SH_G);
    cudaFuncSetAttribute((const void*)tgemm<3,768,768>,   cudaFuncAttributeMaxDynamicSharedMemorySize, SH_G);
    cudaFuncSetAttribute((const void*)tgemm<4,768,3072>,  cudaFuncAttributeMaxDynamicSharedMemorySize, SH_G);
    cudaFuncSetAttribute((const void*)tgemm<5,3072,768>,  cudaFuncAttributeMaxDynamicSharedMemorySize, SH_G);
    cudaFuncSetAttribute((const void*)fattn, cudaFuncAttributeMaxDynamicSharedMemorySize, SH_FA);

    zero_small<<<1, 32>>>();

    // merged small fp32->fp16 conversions (x, Wq, Wk, Wv, Wo)
    constexpr int N4ALL = T_*D_/4 + 4*(D_*D_/4);
    f2h5<<<(N4ALL + 255)/256, 256>>>(x, p_xh, Wq, p_wqh, Wk, p_wkh, Wv, p_wvh, Wo, p_woh);

    // fused QKV projections (fp16 in, fp16 q/k/v out)
    tgemm<0,768,768><<<dim3(6,64,3), 128, SH_G>>>(p_xh, p_wqh, p_wkh, p_wvh, bq, bk, bv);

    // fused flash attention (fp16 MMA, register P) -> g_ctxh
    fattn<<<dim3(8, 96), 256, SH_FA>>>(mask);

    // att = LN1(x + ctxh@Wo + bo) ; fp16 mirror for MoE
    tgemm<3,768,768><<<dim3(6,64,1), 128, SH_G>>>(nullptr, p_woh, nullptr, nullptr, nullptr, nullptr, nullptr);
    ln_kernel<<<T_, 256>>>(x, p_tmp, bo, ln1g, ln1b, p_att, p_atth);

    // router + MoE (fp16 operands, fp32 accum)
    router_kernel<<<T_/8, 256>>>(Wr, br);
    f2h<<<(E_*D_*FF_/4 + 255)/256, 256>>>(W1, p_w1h, E_*D_*FF_/4);
    tgemm<4,768,3072><<<dim3(FF_/128, (E_*CAP_)/128, 1), 128, SH_G>>>(nullptr, p_w1h, nullptr, nullptr, b1, nullptr, nullptr);
    f2h<<<(E_*FF_*D_/4 + 255)/256, 256>>>(W2, p_w2h, E_*FF_*D_/4);
    tgemm<5,3072,768><<<dim3(D_/128, (E_*CAP_)/128, 1), 128, SH_G>>>(nullptr, p_w2h, nullptr, nullptr, b2, nullptr, nullptr);

    // out = LN2(att + ffn)
    ln_kernel<<<T_, 256>>>(p_att, p_ffn, nullptr, ln2g, ln2b, out, nullptr);
}

// round 15
// speedup vs baseline: 1.8778x; 1.0039x over previous
#include <cuda_runtime.h>
#include <cuda_fp16.h>
#include <cstdint>
#include <math.h>

#define B_  8
#define S_  1024
#define D_  768
#define H_  12
#define DH_ 64
#define FF_ 3072
#define E_  8
#define CAP_ 2048
#define T_  8192

// ---------------- scratch (device globals) ----------------------------------
__device__ float  g_tmp[T_*D_];
__device__ float  g_att[T_*D_];
__device__ float  g_ffn[T_*D_];
__device__ int    g_cnt[E_];
__device__ int    g_tokmap[E_*CAP_];
__device__ float  g_gate[T_];
// fp16 tensors
__device__ __half g_qh[B_*H_*S_*DH_];
__device__ __half g_kh[B_*H_*S_*DH_];
__device__ __half g_vh[B_*H_*S_*DH_];
__device__ __half g_xh[T_*D_];
__device__ __half g_wqh[D_*D_];
__device__ __half g_wkh[D_*D_];
__device__ __half g_wvh[D_*D_];
__device__ __half g_woh[D_*D_];
__device__ __half g_w1h[E_*D_*FF_];
__device__ __half g_w2h[E_*FF_*D_];
__device__ __half g_atth[T_*D_];
__device__ __half g_ctxh[T_*D_];
__device__ __half g_hh[50331648];          // E*CAP*FF fp16

__device__ __forceinline__ float gelu_f(float x) {
    return 0.5f * x * (1.0f + erff(x * 0.70710678118654752f));
}

__device__ __forceinline__ void cpa16(uint32_t dst, const void* src) {
    asm volatile("cp.async.ca.shared.global [%0], [%1], 16;" :: "r"(dst), "l"(src));
}
__device__ __forceinline__ void cpa_commit() {
    asm volatile("cp.async.commit_group;" ::: "memory");
}
__device__ __forceinline__ void cpa_wait0() {
    asm volatile("cp.async.wait_group 0;" ::: "memory");
}
__device__ __forceinline__ void mma16(float* c, const uint32_t* a, const uint32_t* b) {
    asm volatile(
        "mma.sync.aligned.m16n8k16.row.col.f32.f16.f16.f32 "
        "{%0,%1,%2,%3}, {%4,%5,%6,%7}, {%8,%9}, {%0,%1,%2,%3};\n"
        : "+f"(c[0]), "+f"(c[1]), "+f"(c[2]), "+f"(c[3])
        : "r"(a[0]), "r"(a[1]), "r"(a[2]), "r"(a[3]), "r"(b[0]), "r"(b[1]));
}
__device__ __forceinline__ void ldsm4(uint32_t* r, uint32_t addr) {
    asm volatile("ldmatrix.sync.aligned.m8n8.x4.b16 {%0,%1,%2,%3}, [%4];"
                 : "=r"(r[0]), "=r"(r[1]), "=r"(r[2]), "=r"(r[3]) : "r"(addr));
}
__device__ __forceinline__ void ldsm4t(uint32_t* r, uint32_t addr) {
    asm volatile("ldmatrix.sync.aligned.m8n8.x4.trans.shared.b16 {%0,%1,%2,%3}, [%4];"
                 : "=r"(r[0]), "=r"(r[1]), "=r"(r[2]), "=r"(r[3]) : "r"(addr));
}

// ---------------- fp32 -> fp16 conversions ------------------------------------
__global__ void f2h(const float* __restrict__ s, __half* __restrict__ d, int n4) {
    int i = blockIdx.x * blockDim.x + threadIdx.x;
    if (i >= n4) return;
    float4 v = ((const float4*)s)[i];
    ((__half2*)d)[i*2]   = __floats2half2_rn(v.x, v.y);
    ((__half2*)d)[i*2+1] = __floats2half2_rn(v.z, v.w);
}
__global__ void f2h5(const float* __restrict__ x,  __half* dx,
                     const float* __restrict__ w0, __half* d0,
                     const float* __restrict__ w1, __half* d1,
                     const float* __restrict__ w2, __half* d2,
                     const float* __restrict__ w3, __half* d3) {
    constexpr int N4X = T_*D_/4, N4W = D_*D_/4;
    int i = blockIdx.x * blockDim.x + threadIdx.x;
    const float* s; __half* d; int j;
    if (i < N4X)            { s = x;  d = dx; j = i; }
    else if (i < N4X+N4W)   { s = w0; d = d0; j = i - N4X; }
    else if (i < N4X+2*N4W) { s = w1; d = d1; j = i - N4X - N4W; }
    else if (i < N4X+3*N4W) { s = w2; d = d2; j = i - N4X - 2*N4W; }
    else if (i < N4X+4*N4W) { s = w3; d = d3; j = i - N4X - 3*N4W; }
    else return;
    float4 v = ((const float4*)s)[j];
    ((__half2*)d)[j*2]   = __floats2half2_rn(v.x, v.y);
    ((__half2*)d)[j*2+1] = __floats2half2_rn(v.z, v.w);
}

// ================= fused flash attention (fp16 MMA, log2-domain softmax) =====
__global__ __launch_bounds__(256) void fattn(const float* __restrict__ mask)
{
    constexpr int LDK_H = 72, LDV_H = 72;
    constexpr int KBYTES = 64 * LDK_H * 2;
    constexpr int VBYTES = 64 * LDV_H * 2;
    constexpr int MBYTES = 256;
    constexpr int STAGE  = KBYTES + VBYTES + MBYTES;
    constexpr float LOG2E = 1.44269504088896f;
    extern __shared__ char smc[];

    const int tid = threadIdx.x, wid = tid >> 5, lane = tid & 31;
    const int g = lane >> 2, t = lane & 3;
    const int z = blockIdx.y, mBase = blockIdx.x * 128;
    const int bq = z / H_, hh = z % H_;
    const int m0 = mBase + wid * 16;

    const __half* Qp = g_qh + (size_t)z * S_ * DH_;
    const __half* Kp = g_kh + (size_t)z * S_ * DH_;
    const __half* Vp = g_vh + (size_t)z * S_ * DH_;

    // Q pre-scaled by (1/8)*log2(e): softmax runs in the log2 domain
    const __half2 sc8 = __half2half2(__float2half(0.125f * LOG2E));
    uint32_t qf[4][4];
    #pragma unroll
    for (int ks = 0; ks < 4; ks++) {
        __half2 h0 = __hmul2(*(const __half2*)&Qp[(m0 + g)     * DH_ + ks*16 + 2*t],     sc8);
        __half2 h1 = __hmul2(*(const __half2*)&Qp[(m0 + g + 8) * DH_ + ks*16 + 2*t],     sc8);
        __half2 h2 = __hmul2(*(const __half2*)&Qp[(m0 + g)     * DH_ + ks*16 + 2*t + 8], sc8);
        __half2 h3 = __hmul2(*(const __half2*)&Qp[(m0 + g + 8) * DH_ + ks*16 + 2*t + 8], sc8);
        qf[ks][0] = *(uint32_t*)&h0; qf[ks][1] = *(uint32_t*)&h1;
        qf[ks][2] = *(uint32_t*)&h2; qf[ks][3] = *(uint32_t*)&h3;
    }

    float oacc[8][4];
    #pragma unroll
    for (int nt = 0; nt < 8; nt++)
        #pragma unroll
        for (int q = 0; q < 4; q++) oacc[nt][q] = 0.f;
    float lacc[4] = {0.f, 0.f, 0.f, 0.f};   // row-sum accumulator (ones-column MMA)
    float mrow0 = -1e30f, mrow1 = -1e30f;
    const uint32_t ONE2 = 0x3C003C00u;       // half2(1,1)

    uint32_t sU = (uint32_t)__cvta_generic_to_shared(smc);
    const uint32_t lmRow = (lane & 15);
    const uint32_t lmHalf = (lane >> 4) << 4;
    const uint32_t kOff = lmRow * (LDK_H*2) + lmHalf;
    const uint32_t vOff = lmRow * (LDV_H*2) + lmHalf;

    auto issue = [&](int kt) {
        const int stg = kt & 1;
        const uint32_t base = sU + stg * STAGE;
        #pragma unroll
        for (int i = 0; i < 2; i++) {
            int idx = tid + i * 256;
            int row = idx >> 3, c4 = idx & 7;
            cpa16(base + row * (LDK_H*2) + c4 * 16,
                  Kp + (size_t)(kt*64 + row) * DH_ + c4 * 8);
        }
        #pragma unroll
        for (int i = 0; i < 2; i++) {
            int idx = tid + i * 256;
            int row = idx >> 3, c4 = idx & 7;
            cpa16(base + KBYTES + row * (LDV_H*2) + c4 * 16,
                  Vp + (size_t)(kt*64 + row) * DH_ + c4 * 8);
        }
        if (tid < 16)
            cpa16(base + KBYTES + VBYTES + tid * 16, mask + bq * S_ + kt*64 + tid * 4);
        cpa_commit();
    };

    issue(0);
    for (int kt = 0; kt < 16; kt++) {
        cpa_wait0();
        __syncthreads();
        if (kt + 1 < 16) issue(kt + 1);

        const int stg = kt & 1;
        const uint32_t kBase = sU + stg * STAGE;
        const uint32_t vBase = kBase + KBYTES;
        const float* mS = (const float*)(smc + stg * STAGE + KBYTES + VBYTES);

        float sacc[8][4];
        #pragma unroll
        for (int nt = 0; nt < 8; nt++)
            #pragma unroll
            for (int q = 0; q < 4; q++) sacc[nt][q] = 0.f;
        #pragma unroll
        for (int ks = 0; ks < 4; ks++) {
            #pragma unroll
            for (int p = 0; p < 4; p++) {
                uint32_t r[4];
                ldsm4(r, kBase + kOff + p * 16 * (LDK_H*2) + ks * 32);
                uint32_t b0[2] = { r[0], r[2] };
                uint32_t b1[2] = { r[1], r[3] };
                mma16(sacc[2*p],   qf[ks], b0);
                mma16(sacc[2*p+1], qf[ks], b1);
            }
        }

        float mx0 = -1e30f, mx1 = -1e30f;
        #pragma unroll
        for (int nt = 0; nt < 8; nt++) {
            float mk0 = mS[nt*8 + 2*t], mk1 = mS[nt*8 + 2*t + 1];
            sacc[nt][0] = fmaf(mk0, LOG2E, sacc[nt][0]);
            sacc[nt][1] = fmaf(mk1, LOG2E, sacc[nt][1]);
            sacc[nt][2] = fmaf(mk0, LOG2E, sacc[nt][2]);
            sacc[nt][3] = fmaf(mk1, LOG2E, sacc[nt][3]);
            mx0 = fmaxf(mx0, fmaxf(sacc[nt][0], sacc[nt][1]));
            mx1 = fmaxf(mx1, fmaxf(sacc[nt][2], sacc[nt][3]));
        }
        mx0 = fmaxf(mx0, __shfl_xor_sync(0xffffffffu, mx0, 1));
        mx0 = fmaxf(mx0, __shfl_xor_sync(0xffffffffu, mx0, 2));
        mx1 = fmaxf(mx1, __shfl_xor_sync(0xffffffffu, mx1, 1));
        mx1 = fmaxf(mx1, __shfl_xor_sync(0xffffffffu, mx1, 2));

        float mn0 = fmaxf(mrow0, mx0), mn1 = fmaxf(mrow1, mx1);
        float a0 = exp2f(mrow0 - mn0), a1 = exp2f(mrow1 - mn1);
        mrow0 = mn0; mrow1 = mn1;

        // exp2 -> P fragments in registers (exact A-fragment layout for PV)
        uint32_t pf0[8], pf1[8];
        #pragma unroll
        for (int nt = 0; nt < 8; nt++) {
            float p0 = exp2f(sacc[nt][0] - mn0);
            float p1 = exp2f(sacc[nt][1] - mn0);
            float p2 = exp2f(sacc[nt][2] - mn1);
            float p3 = exp2f(sacc[nt][3] - mn1);
            __half2 hA = __floats2half2_rn(p0, p1);
            __half2 hB = __floats2half2_rn(p2, p3);
            pf0[nt] = *(uint32_t*)&hA;
            pf1[nt] = *(uint32_t*)&hB;
        }

        // rescale O and l accumulators
        #pragma unroll
        for (int nt = 0; nt < 8; nt++) {
            oacc[nt][0] *= a0; oacc[nt][1] *= a0;
            oacc[nt][2] *= a1; oacc[nt][3] *= a1;
        }
        lacc[0] *= a0; lacc[1] *= a0; lacc[2] *= a1; lacc[3] *= a1;

        // ---- P @ V + P @ ones (row sums) ----
        #pragma unroll
        for (int ks = 0; ks < 4; ks++) {
            uint32_t a[4] = { pf0[2*ks], pf1[2*ks], pf0[2*ks+1], pf1[2*ks+1] };
            uint32_t bones[2] = { ONE2, ONE2 };
            mma16(lacc, a, bones);
            #pragma unroll
            for (int p = 0; p < 4; p++) {
                uint32_t r[4];
                ldsm4t(r, vBase + vOff + ks * 16 * (LDV_H*2) + p * 32);
                uint32_t b0[2] = { r[0], r[1] };
                uint32_t b1[2] = { r[2], r[3] };
                mma16(oacc[2*p],   a, b0);
                mma16(oacc[2*p+1], a, b1);
            }
        }
    }

    float inv0 = 1.0f / lacc[0], inv1 = 1.0f / lacc[2];
    int mr0 = m0 + g, mr1 = m0 + g + 8;
    #pragma unroll
    for (int nt = 0; nt < 8; nt++) {
        int col = hh * DH_ + nt*8 + 2*t;
        *(__half2*)(g_ctxh + ((size_t)(bq * S_ + mr0)) * D_ + col) =
            __floats2half2_rn(oacc[nt][0] * inv0, oacc[nt][1] * inv0);
        *(__half2*)(g_ctxh + ((size_t)(bq * S_ + mr1)) * D_ + col) =
            __floats2half2_rn(oacc[nt][2] * inv1, oacc[nt][3] * inv1);
    }
}

// ---------------- fp16 mma.sync GEMM: 128x128 tile, K-chunk 64 ---------------
template<int MODE, int KK, int LDBG>
__global__ __launch_bounds__(128, 2)
void tgemm(const __half* __restrict__ Ag, const __half* __restrict__ Bg,
           const __half* __restrict__ Bg2, const __half* __restrict__ Bg3,
           const float* __restrict__ bias, const float* __restrict__ bias2,
           const float* __restrict__ bias3)
{
    constexpr int BN     = 128;
    constexpr int NC     = KK / 64;
    constexpr int NT     = 8;
    constexpr int LDA_H  = 72;
    constexpr int LDB_H  = 136;
    constexpr int ABYTES = 128 * LDA_H * 2;
    constexpr int BBYTES = 64 * LDB_H * 2;
    constexpr int STAGE  = ABYTES + BBYTES;
    constexpr int CS     = BN + 4;
    constexpr int BF4    = BN / 4;

    extern __shared__ char smc[];
    __shared__ int rIdx[128];
    __shared__ int s_cnt;

    const int tid = threadIdx.x, wid = tid >> 5, lane = tid & 31;
    const int wr = wid >> 1, wc = wid & 1;
    const int g = lane >> 2, t = lane & 3;
    const int mBase = blockIdx.y * 128, nBase = blockIdx.x * BN, z = blockIdx.z;
    const int e = (MODE >= 4) ? (mBase >> 11) : 0;

    if (MODE == 4 || MODE == 5) {
        if (tid == 0) s_cnt = g_cnt[e];
        __syncthreads();
        if ((mBase & (CAP_-1)) >= s_cnt) return;
    }

    const __half* A; const __half* Bp; const float* biasp = bias;
    if      (MODE == 0) { A = Ag; Bp = (z==0)?Bg:((z==1)?Bg2:Bg3);
                          biasp = (z==0)?bias:((z==1)?bias2:bias3); }
    else if (MODE == 3) { A = g_ctxh;  Bp = Bg; }
    else if (MODE == 4) { A = g_atth;  Bp = Bg + (size_t)e * D_ * FF_; }
    else                { A = g_hh;    Bp = Bg + (size_t)e * FF_ * D_; }

    {
        int m = mBase + tid, r = m;
        if (MODE == 4) {
            int pos = m & (CAP_-1);
            r = (pos < s_cnt) ? g_tokmap[e*CAP_ + pos] : 0;
        }
        rIdx[tid] = r;
    }
    __syncthreads();

    uint32_t sU = (uint32_t)__cvta_generic_to_shared(smc);
    const uint32_t aOff = (uint32_t)((wr*64 + (lane & 15)) * (LDA_H*2)) + ((lane >> 4) << 4);
    const uint32_t bOff = (uint32_t)((lane & 15) * (LDB_H*2)) + ((lane >> 4) << 4);

    auto issue = [&](int cix) {
        const int stg = cix & 1;
        const int k0 = cix * 64;
        const uint32_t aB = sU + stg * STAGE;
        #pragma unroll
        for (int i = 0; i < 8; i++) {
            int idx = tid + i * 128;
            int row = idx >> 3, c4 = idx & 7;
            cpa16(aB + row * (LDA_H*2) + c4 * 16,
                  A + (size_t)rIdx[row] * KK + k0 + c4 * 8);
        }
        const uint32_t bB = aB + ABYTES;
        #pragma unroll
        for (int i = 0; i < 8; i++) {
            int idx = tid + i * 128;
            int row = idx >> 4, c4 = idx & 15;
            cpa16(bB + row * (LDB_H*2) + c4 * 16,
                  Bp + (size_t)(k0 + row) * LDBG + nBase + c4 * 8);
        }
        cpa_commit();
    };

    float acc[4][NT][4];
    #pragma unroll
    for (int i = 0; i < 4; i++)
        #pragma unroll
        for (int j = 0; j < NT; j++)
            #pragma unroll
            for (int q = 0; q < 4; q++) acc[i][j][q] = 0.f;

    issue(0);
    for (int c = 0; c < NC; c++) {
        cpa_wait0();
        __syncthreads();
        if (c + 1 < NC) issue(c + 1);

        const int stg = c & 1;
        const uint32_t aBase = sU + stg * STAGE + aOff;
        const uint32_t bBase = sU + stg * STAGE + ABYTES + bOff + wc * 128;
        #pragma unroll
        for (int ks = 0; ks < 4; ks++) {
            uint32_t a[4][4];
            #pragma unroll
            for (int mt = 0; mt < 4; mt++)
                ldsm4(a[mt], aBase + mt * 16 * (LDA_H*2) + ks * 32);
            uint32_t b[NT][2];
            #pragma unroll
            for (int p = 0; p < 4; p++) {
                uint32_t r[4];
                ldsm4t(r, bBase + ks * 16 * (LDB_H*2) + p * 32);
                b[2*p][0]   = r[0]; b[2*p][1]   = r[1];
                b[2*p+1][0] = r[2]; b[2*p+1][1] = r[3];
            }
            #pragma unroll
            for (int mt = 0; mt < 4; mt++)
                #pragma unroll
                for (int nt = 0; nt < NT; nt++)
                    mma16(acc[mt][nt], a[mt], b[nt]);
        }
    }
    __syncthreads();

    // ---------------- epilogue ----------------
    float* cSf = (float*)smc;
    #pragma unroll
    for (int mt = 0; mt < 4; mt++) {
        #pragma unroll
        for (int nt = 0; nt < NT; nt++) {
            int r = wr*64 + mt*16 + g;
            int n = wc*64 + nt*8 + 2*t;
            *(float2*)(cSf + r*CS + n)     = make_float2(acc[mt][nt][0], acc[mt][nt][1]);
            *(float2*)(cSf + (r+8)*CS + n) = make_float2(acc[mt][nt][2], acc[mt][nt][3]);
        }
    }
    __syncthreads();

    constexpr int IT = (128 * BF4) / 128;
    #pragma unroll
    for (int it = 0; it < IT; it++) {
        int idx = it * 128 + tid;
        int row = idx / BF4, q = idx % BF4;
        float4 v = *(const float4*)(cSf + row*CS + q*4);
        int m  = mBase + row;
        int n0 = nBase + q*4;

        if (MODE == 0) {
            v.x += biasp[n0]; v.y += biasp[n0+1]; v.z += biasp[n0+2]; v.w += biasp[n0+3];
            int b = m >> 10, srow = m & 1023, hh = n0 >> 6, dh = n0 & 63;
            __half* dst = (z == 0) ? g_qh : ((z == 1) ? g_kh : g_vh);
            __half* p = dst + (((size_t)(b*H_ + hh)) * S_ + srow) * DH_ + dh;
            *(__half2*)(p)     = __floats2half2_rn(v.x, v.y);
            *(__half2*)(p + 2) = __floats2half2_rn(v.z, v.w);
        } else if (MODE == 3) {
            *(float4*)(g_tmp + (size_t)m * D_ + n0) = v;
        } else if (MODE == 4) {
            int pos = m & (CAP_-1);
            if (pos < s_cnt) {
                const float4 bb = *(const float4*)(bias + (size_t)e*FF_ + n0);
                __half* dst = g_hh + (size_t)m * FF_ + n0;
                *(__half2*)(dst)     = __floats2half2_rn(gelu_f(v.x+bb.x), gelu_f(v.y+bb.y));
                *(__half2*)(dst + 2) = __floats2half2_rn(gelu_f(v.z+bb.z), gelu_f(v.w+bb.w));
            }
        } else {
            int pos = m & (CAP_-1);
            if (pos < s_cnt) {
                int tok = g_tokmap[e*CAP_ + pos];
                float gsc = g_gate[tok];
                const float4 bb = *(const float4*)(bias + (size_t)e*D_ + n0);
                *(float4*)(g_ffn + (size_t)tok * D_ + n0) =
                    make_float4((v.x+bb.x)*gsc, (v.y+bb.y)*gsc,
                                (v.z+bb.z)*gsc, (v.w+bb.w)*gsc);
            }
        }
    }
}

// ---------------- layernorm (optional fp16 mirror output) --------------------
__global__ __launch_bounds__(256) void ln_kernel(
        const float* __restrict__ a, const float* __restrict__ bsum,
        const float* __restrict__ bias,
        const float* __restrict__ g, const float* __restrict__ beta,
        float* __restrict__ out, __half* __restrict__ outh)
{
    __shared__ float red[256];
    const int t = blockIdx.x, tid = threadIdx.x;
    const float* ap = a    + (size_t)t * D_;
    const float* bp = bsum + (size_t)t * D_;
    float v[3]; float s = 0.f;
    #pragma unroll
    for (int j=0;j<3;j++) {
        int i = tid + j*256;
        float x = ap[i] + bp[i];
        if (bias) x += bias[i];
        v[j] = x; s += x;
    }
    red[tid]=s; __syncthreads();
    for (int st=128; st>0; st>>=1) { if (tid<st) red[tid]+=red[tid+st]; __syncthreads(); }
    float mu = red[0] * (1.0f/768.0f);
    __syncthreads();
    float q = 0.f;
    #pragma unroll
    for (int j=0;j<3;j++) { float d = v[j]-mu; q += d*d; }
    red[tid]=q; __syncthreads();
    for (int st=128; st>0; st>>=1) { if (tid<st) red[tid]+=red[tid+st]; __syncthreads(); }
    float inv = rsqrtf(red[0]*(1.0f/768.0f) + 1e-12f);
    #pragma unroll
    for (int j=0;j<3;j++) {
        int i = tid + j*256;
        float y = (v[j]-mu)*inv*g[i] + beta[i];
        out[(size_t)t*D_ + i] = y;
        if (outh) outh[(size_t)t*D_ + i] = __float2half_rn(y);
    }
}

// ---------------- router ------------------------------------------------------
__global__ __launch_bounds__(256) void router_kernel(
        const float* __restrict__ Wr, const float* __restrict__ br)
{
    int warp = (blockIdx.x * blockDim.x + threadIdx.x) >> 5;
    int lane = threadIdx.x & 31;
    if (warp >= T_) return;
    const float* xrow = g_att + (size_t)warp * D_;
    float acc[E_];
    #pragma unroll
    for (int e=0;e<E_;e++) acc[e]=0.f;
    for (int i = lane; i < D_; i += 32) {
        float x = xrow[i];
        const float* w = Wr + i*E_;
        #pragma unroll
        for (int e=0;e<E_;e++) acc[e] += x * w[e];
    }
    #pragma unroll
    for (int e=0;e<E_;e++)
        #pragma unroll
        for (int o=16;o>0;o>>=1)
            acc[e] += __shfl_xor_sync(0xffffffffu, acc[e], o);
    if (lane == 0) {
        float best = -1e30f; int be = 0;
        #pragma unroll
        for (int e=0;e<E_;e++) {
            float l = acc[e] + br[e];
            acc[e] = l;
            if (l > best) { best = l; be = e; }
        }
        float sm = 0.f;
        #pragma unroll
        for (int e=0;e<E_;e++) sm += expf(acc[e] - best);
        float gate = 1.0f / sm;
        int pos = atomicAdd(&g_cnt[be], 1);
        if (pos < CAP_) {
            g_tokmap[be*CAP_ + pos] = warp;
            g_gate[warp] = gate;
        }
    }
}

__global__ void zero_small() {
    if (threadIdx.x < E_) g_cnt[threadIdx.x] = 0;
}

// ---------------- launch ------------------------------------------------------
extern "C" void kernel_launch(void* const* d_in, const int* in_sizes, int n_in,
                              void* d_out, int out_size) {
    const float* x    = (const float*)d_in[0];
    const float* mask = (const float*)d_in[1];
    const float* Wq   = (const float*)d_in[2];
    const float* bq   = (const float*)d_in[3];
    const float* Wk   = (const float*)d_in[4];
    const float* bk   = (const float*)d_in[5];
    const float* Wv   = (const float*)d_in[6];
    const float* bv   = (const float*)d_in[7];
    const float* Wo   = (const float*)d_in[8];
    const float* bo   = (const float*)d_in[9];
    const float* ln1g = (const float*)d_in[10];
    const float* ln1b = (const float*)d_in[11];
    const float* Wr   = (const float*)d_in[12];
    const float* br   = (const float*)d_in[13];
    const float* W1   = (const float*)d_in[14];
    const float* b1   = (const float*)d_in[15];
    const float* W2   = (const float*)d_in[16];
    const float* b2   = (const float*)d_in[17];
    const float* ln2g = (const float*)d_in[18];
    const float* ln2b = (const float*)d_in[19];
    float* out = (float*)d_out;

    float *p_tmp, *p_att, *p_ffn;
    __half *p_xh, *p_wqh, *p_wkh, *p_wvh, *p_woh, *p_w1h, *p_w2h, *p_atth;
    cudaGetSymbolAddress((void**)&p_tmp, g_tmp);
    cudaGetSymbolAddress((void**)&p_att, g_att);
    cudaGetSymbolAddress((void**)&p_ffn, g_ffn);
    cudaGetSymbolAddress((void**)&p_xh,  g_xh);
    cudaGetSymbolAddress((void**)&p_wqh, g_wqh);
    cudaGetSymbolAddress((void**)&p_wkh, g_wkh);
    cudaGetSymbolAddress((void**)&p_wvh, g_wvh);
    cudaGetSymbolAddress((void**)&p_woh, g_woh);
    cudaGetSymbolAddress((void**)&p_w1h, g_w1h);
    cudaGetSymbolAddress((void**)&p_w2h, g_w2h);
    cudaGetSymbolAddress((void**)&p_atth, g_atth);

    constexpr int SH_G  = 2 * 35840;                 // 71680
    constexpr int SH_FA = 2 * 18688;                 // 37376
    cudaFuncSetAttribute((const void*)tgemm<0,768,768>,   cudaFuncAttributeMaxDynamicSharedMemorySize, SH_G);
    cudaFuncSetAttribute((const void*)tgemm<3,768,768>,   cudaFuncAttributeMaxDynamicSharedMemorySize, SH_G);
    cudaFuncSetAttribute((const void*)tgemm<4,768,3072>,  cudaFuncAttributeMaxDynamicSharedMemorySize, SH_G);
    cudaFuncSetAttribute((const void*)tgemm<5,3072,768>,  cudaFuncAttributeMaxDynamicSharedMemorySize, SH_G);
    cudaFuncSetAttribute((const void*)fattn, cudaFuncAttributeMaxDynamicSharedMemorySize, SH_FA);

    zero_small<<<1, 32>>>();

    // merged small fp32->fp16 conversions (x, Wq, Wk, Wv, Wo)
    constexpr int N4ALL = T_*D_/4 + 4*(D_*D_/4);
    f2h5<<<(N4ALL + 255)/256, 256>>>(x, p_xh, Wq, p_wqh, Wk, p_wkh, Wv, p_wvh, Wo, p_woh);

    // fused QKV projections (fp16 in, fp16 q/k/v out)
    tgemm<0,768,768><<<dim3(6,64,3), 128, SH_G>>>(p_xh, p_wqh, p_wkh, p_wvh, bq, bk, bv);

    // fused flash attention (fp16 MMA, register P, log2-domain softmax)
    fattn<<<dim3(8, 96), 256, SH_FA>>>(mask);

    // att = LN1(x + ctxh@Wo + bo) ; fp16 mirror for MoE
    tgemm<3,768,768><<<dim3(6,64,1), 128, SH_G>>>(nullptr, p_woh, nullptr, nullptr, nullptr, nullptr, nullptr);
    ln_kernel<<<T_, 256>>>(x, p_tmp, bo, ln1g, ln1b, p_att, p_atth);

    // router + MoE (fp16 operands, fp32 accum)
    router_kernel<<<T_/8, 256>>>(Wr, br);
    f2h<<<(E_*D_*FF_/4 + 255)/256, 256>>>(W1, p_w1h, E_*D_*FF_/4);
    tgemm<4,768,3072><<<dim3(FF_/128, (E_*CAP_)/128, 1), 128, SH_G>>>(nullptr, p_w1h, nullptr, nullptr, b1, nullptr, nullptr);
    f2h<<<(E_*FF_*D_/4 + 255)/256, 256>>>(W2, p_w2h, E_*FF_*D_/4);
    tgemm<5,3072,768><<<dim3(D_/128, (E_*CAP_)/128, 1), 128, SH_G>>>(nullptr, p_w2h, nullptr, nullptr, b2, nullptr, nullptr);

    // out = LN2(att + ffn)
    ln_kernel<<<T_, 256>>>(p_att, p_ffn, nullptr, ln2g, ln2b, out, nullptr);
}